// round 1
// baseline (speedup 1.0000x reference)
#include <cuda_runtime.h>
#include <math.h>

// ---------------- problem dims ----------------
#define HDIM 256
#define GDIM 768           // 3*H
#define EDIM 200
#define NW 4096            // B*R*S word sequences
#define TWSTEPS 32
#define NS 256             // B*R
#define TSSTEPS 16
#define NR 16              // B
#define TRSTEPS 16

// ---------------- scratch (static device globals; no allocs allowed) --------
__device__ float g_GXw[(size_t)NW * TWSTEPS * GDIM];   // 402 MB: word input gates
__device__ float g_GXs[(size_t)NS * TSSTEPS * GDIM];   // 12.6 MB
__device__ float g_GXr[(size_t)NR * TRSTEPS * GDIM];   // 0.8 MB
__device__ float g_GH [(size_t)NW * GDIM];             // recurrent gates scratch (max level)
__device__ float g_HwA[NW * HDIM], g_HwB[NW * HDIM];
__device__ float g_HsA[NS * HDIM], g_HsB[NS * HDIM];
__device__ float g_HrA[NR * HDIM], g_HrB[NR * HDIM];

// ---------------- SGEMM: C[M,N] = A[M,K] @ W[N,K]^T + bias[N] ----------------
// If GATHER: A row m is emb[idx[m], :] (A argument = emb table).
// Tile 128x128x8, 256 threads, 8x8 accumulators per thread. K % 8 == 0 assumed.
#define BM 128
#define BN 128
#define BK 8

template <bool GATHER>
__global__ __launch_bounds__(256)
void sgemm_kernel(const float* __restrict__ A, const int* __restrict__ idx,
                  const float* __restrict__ W, const float* __restrict__ bias,
                  float* __restrict__ C, int M, int K, int N)
{
    __shared__ float As[BK][BM];
    __shared__ float Bs[BK][BN];

    const int tid = threadIdx.x;
    const int m0 = blockIdx.y * BM;
    const int n0 = blockIdx.x * BN;

    // A-tile load mapping: 128 rows x 2 float4-chunks of K
    const int a_m  = tid & 127;
    const int a_kq = tid >> 7;       // 0..1 -> k offset a_kq*4
    // B-tile load mapping: 128 cols x 2 float4-chunks of K
    const int b_n  = tid >> 1;       // 0..127
    const int b_kq = tid & 1;

    const bool a_valid = (m0 + a_m) < M;
    const float* Arow = nullptr;
    if (a_valid) {
        if (GATHER) Arow = A + (size_t)idx[m0 + a_m] * K;
        else        Arow = A + (size_t)(m0 + a_m) * K;
    }
    const float* Brow = W + (size_t)(n0 + b_n) * K;

    const int tx = tid & 15;   // n micro-tile
    const int ty = tid >> 4;   // m micro-tile

    float acc[8][8];
#pragma unroll
    for (int i = 0; i < 8; i++)
#pragma unroll
        for (int j = 0; j < 8; j++) acc[i][j] = 0.f;

    for (int kk = 0; kk < K; kk += BK) {
        float4 av = make_float4(0.f, 0.f, 0.f, 0.f);
        if (a_valid) av = *reinterpret_cast<const float4*>(Arow + kk + a_kq * 4);
        As[a_kq * 4 + 0][a_m] = av.x;
        As[a_kq * 4 + 1][a_m] = av.y;
        As[a_kq * 4 + 2][a_m] = av.z;
        As[a_kq * 4 + 3][a_m] = av.w;

        float4 bv = *reinterpret_cast<const float4*>(Brow + kk + b_kq * 4);
        Bs[b_kq * 4 + 0][b_n] = bv.x;
        Bs[b_kq * 4 + 1][b_n] = bv.y;
        Bs[b_kq * 4 + 2][b_n] = bv.z;
        Bs[b_kq * 4 + 3][b_n] = bv.w;

        __syncthreads();

#pragma unroll
        for (int k = 0; k < BK; k++) {
            float a[8], b[8];
#pragma unroll
            for (int i = 0; i < 8; i++) a[i] = As[k][ty * 8 + i];
#pragma unroll
            for (int j = 0; j < 8; j++) b[j] = Bs[k][tx * 8 + j];
#pragma unroll
            for (int i = 0; i < 8; i++)
#pragma unroll
                for (int j = 0; j < 8; j++) acc[i][j] = fmaf(a[i], b[j], acc[i][j]);
        }
        __syncthreads();
    }

#pragma unroll
    for (int i = 0; i < 8; i++) {
        int row = m0 + ty * 8 + i;
        if (row >= M) continue;
#pragma unroll
        for (int j = 0; j < 8; j++) {
            int col = n0 + tx * 8 + j;
            C[(size_t)row * N + col] = acc[i][j] + bias[col];
        }
    }
}

// ---------------- GRU elementwise update ----------------
// gx laid out [seq, T, 768]; gh laid out [seq, 768] (bias already added in both).
__device__ __forceinline__ float sigmoid_f(float x) { return 1.f / (1.f + expf(-x)); }

__global__ void gru_update_kernel(const float* __restrict__ gx, const float* __restrict__ gh,
                                  const float* __restrict__ hin, float* __restrict__ hout,
                                  int Mseq, int T, int t)
{
    int i = blockIdx.x * blockDim.x + threadIdx.x;
    if (i >= Mseq * HDIM) return;
    int seq = i >> 8;          // / 256
    int j   = i & 255;

    const float* gxp = gx + ((size_t)seq * T + t) * GDIM;
    const float* ghp = gh + (size_t)seq * GDIM;

    float r = sigmoid_f(gxp[j]           + ghp[j]);
    float z = sigmoid_f(gxp[j + HDIM]    + ghp[j + HDIM]);
    float n = tanhf   (gxp[j + 2*HDIM]   + r * ghp[j + 2*HDIM]);
    float h = hin[i];
    hout[i] = (1.f - z) * n + z * h;
}

// ---------------- zero init ----------------
__global__ void zero_kernel(float* __restrict__ p, int n)
{
    int i = blockIdx.x * blockDim.x + threadIdx.x;
    if (i < n) p[i] = 0.f;
}

// ---------------- MLP: out[row] = W2 @ selu(x @ W1^T + b1) + b2 --------------
// X: [rows, 256], W1: [128,256], W2: [1,128]. One block (128 threads) per row.
__global__ __launch_bounds__(128)
void mlp_kernel(const float* __restrict__ X,
                const float* __restrict__ W1, const float* __restrict__ b1,
                const float* __restrict__ W2, const float* __restrict__ b2,
                float* __restrict__ out)
{
    const int row = blockIdx.x;
    const int i = threadIdx.x;                // hidden unit 0..127
    __shared__ float xs[HDIM];
    __shared__ float red[4];

    xs[i]       = X[(size_t)row * HDIM + i];
    xs[i + 128] = X[(size_t)row * HDIM + i + 128];
    __syncthreads();

    const float* w = W1 + (size_t)i * HDIM;
    float acc = b1[i];
#pragma unroll 8
    for (int k = 0; k < HDIM; k += 4) {
        float4 wv = *reinterpret_cast<const float4*>(w + k);
        acc = fmaf(wv.x, xs[k], acc);
        acc = fmaf(wv.y, xs[k + 1], acc);
        acc = fmaf(wv.z, xs[k + 2], acc);
        acc = fmaf(wv.w, xs[k + 3], acc);
    }
    const float scale = 1.0507009873554805f;
    const float alpha = 1.6732632423543772f;
    float s = scale * (acc > 0.f ? acc : alpha * (expf(acc) - 1.f));
    float v = s * W2[i];

    // block reduce 128 -> 1
#pragma unroll
    for (int off = 16; off > 0; off >>= 1)
        v += __shfl_down_sync(0xffffffffu, v, off);
    if ((i & 31) == 0) red[i >> 5] = v;
    __syncthreads();
    if (i == 0) out[row] = red[0] + red[1] + red[2] + red[3] + b2[0];
}

// ---------------- host orchestration ----------------
extern "C" void kernel_launch(void* const* d_in, const int* in_sizes, int n_in,
                              void* d_out, int out_size)
{
    (void)in_sizes; (void)n_in; (void)out_size;

    const int*   idx    = (const int*)  d_in[0];
    const float* emb    = (const float*)d_in[1];
    const float* w_Wih  = (const float*)d_in[2];
    const float* w_Whh  = (const float*)d_in[3];
    const float* w_bih  = (const float*)d_in[4];
    const float* w_bhh  = (const float*)d_in[5];
    const float* s_Wih  = (const float*)d_in[6];
    const float* s_Whh  = (const float*)d_in[7];
    const float* s_bih  = (const float*)d_in[8];
    const float* s_bhh  = (const float*)d_in[9];
    const float* r_Wih  = (const float*)d_in[10];
    const float* r_Whh  = (const float*)d_in[11];
    const float* r_bih  = (const float*)d_in[12];
    const float* r_bhh  = (const float*)d_in[13];
    const float* rfc_W1 = (const float*)d_in[14];
    const float* rfc_b1 = (const float*)d_in[15];
    const float* rfc_W2 = (const float*)d_in[16];
    const float* rfc_b2 = (const float*)d_in[17];
    const float* pfc_W1 = (const float*)d_in[18];
    const float* pfc_b1 = (const float*)d_in[19];
    const float* pfc_W2 = (const float*)d_in[20];
    const float* pfc_b2 = (const float*)d_in[21];
    float* out = (float*)d_out;

    float *GXw, *GXs, *GXr, *GH, *HwA, *HwB, *HsA, *HsB, *HrA, *HrB;
    cudaGetSymbolAddress((void**)&GXw, g_GXw);
    cudaGetSymbolAddress((void**)&GXs, g_GXs);
    cudaGetSymbolAddress((void**)&GXr, g_GXr);
    cudaGetSymbolAddress((void**)&GH,  g_GH);
    cudaGetSymbolAddress((void**)&HwA, g_HwA);
    cudaGetSymbolAddress((void**)&HwB, g_HwB);
    cudaGetSymbolAddress((void**)&HsA, g_HsA);
    cudaGetSymbolAddress((void**)&HsB, g_HsB);
    cudaGetSymbolAddress((void**)&HrA, g_HrA);
    cudaGetSymbolAddress((void**)&HrB, g_HrB);

    // h0 = 0 for the buffers read at t=0
    zero_kernel<<<(NW * HDIM + 255) / 256, 256>>>(HwA, NW * HDIM);
    zero_kernel<<<(NS * HDIM + 255) / 256, 256>>>(HsA, NS * HDIM);
    zero_kernel<<<(NR * HDIM + 255) / 256, 256>>>(HrA, NR * HDIM);

    // ---- word level: gx = emb[idx] @ w_Wih^T + w_bih  (M = 131072, K = 200) ----
    {
        dim3 grid(GDIM / BN, (NW * TWSTEPS + BM - 1) / BM);
        sgemm_kernel<true><<<grid, 256>>>(emb, idx, w_Wih, w_bih, GXw,
                                          NW * TWSTEPS, EDIM, GDIM);
    }
    // word GRU: 32 steps over 4096 sequences
    {
        float* h[2] = {HwA, HwB};
        dim3 ggrid(GDIM / BN, (NW + BM - 1) / BM);
        for (int t = 0; t < TWSTEPS; t++) {
            sgemm_kernel<false><<<ggrid, 256>>>(h[t & 1], nullptr, w_Whh, w_bhh, GH,
                                                NW, HDIM, GDIM);
            gru_update_kernel<<<(NW * HDIM + 255) / 256, 256>>>(GXw, GH, h[t & 1],
                                                                h[(t + 1) & 1], NW, TWSTEPS, t);
        }
    }
    // sent_h = HwA (TWSTEPS even). Sentence input gates: M = 4096, K = 256.
    {
        dim3 grid(GDIM / BN, (NS * TSSTEPS + BM - 1) / BM);
        sgemm_kernel<false><<<grid, 256>>>(HwA, nullptr, s_Wih, s_bih, GXs,
                                           NS * TSSTEPS, HDIM, GDIM);
    }
    // sentence GRU: 16 steps over 256 sequences
    {
        float* h[2] = {HsA, HsB};
        dim3 ggrid(GDIM / BN, (NS + BM - 1) / BM);
        for (int t = 0; t < TSSTEPS; t++) {
            sgemm_kernel<false><<<ggrid, 256>>>(h[t & 1], nullptr, s_Whh, s_bhh, GH,
                                                NS, HDIM, GDIM);
            gru_update_kernel<<<(NS * HDIM + 255) / 256, 256>>>(GXs, GH, h[t & 1],
                                                                h[(t + 1) & 1], NS, TSSTEPS, t);
        }
    }
    // p_batch = HsA. r_stars -> out[16 .. 272)
    mlp_kernel<<<NS, 128>>>(HsA, rfc_W1, rfc_b1, rfc_W2, rfc_b2, out + NR);

    // review input gates: M = 256, K = 256
    {
        dim3 grid(GDIM / BN, (NR * TRSTEPS + BM - 1) / BM);
        sgemm_kernel<false><<<grid, 256>>>(HsA, nullptr, r_Wih, r_bih, GXr,
                                           NR * TRSTEPS, HDIM, GDIM);
    }
    // review GRU: 16 steps over 16 sequences
    {
        float* h[2] = {HrA, HrB};
        dim3 ggrid(GDIM / BN, (NR + BM - 1) / BM);
        for (int t = 0; t < TRSTEPS; t++) {
            sgemm_kernel<false><<<ggrid, 256>>>(h[t & 1], nullptr, r_Whh, r_bhh, GH,
                                                NR, HDIM, GDIM);
            gru_update_kernel<<<(NR * HDIM + 255) / 256, 256>>>(GXr, GH, h[t & 1],
                                                                h[(t + 1) & 1], NR, TRSTEPS, t);
        }
    }
    // biz_h = HrA. b_stars -> out[0 .. 16)
    mlp_kernel<<<NR, 128>>>(HrA, pfc_W1, pfc_b1, pfc_W2, pfc_b2, out);
}

// round 2
// speedup vs baseline: 1.2689x; 1.2689x over previous
#include <cuda_runtime.h>
#include <math.h>

// ---------------- problem dims ----------------
#define HDIM 256
#define GDIM 768           // 3*H
#define EDIM 200
#define NW 4096            // B*R*S word sequences
#define TWSTEPS 32
#define NS 256             // B*R
#define TSSTEPS 16
#define NR 16              // B
#define TRSTEPS 16

typedef unsigned long long ull;

// ---------------- scratch (static device globals; no allocs allowed) --------
__device__ float g_GXw[(size_t)NW * TWSTEPS * GDIM];   // 402 MB: word input gates
__device__ float g_GXs[(size_t)NS * TSSTEPS * GDIM];   // 12.6 MB
__device__ float g_GXr[(size_t)NR * TRSTEPS * GDIM];   // 0.8 MB
__device__ float g_HwA[NW * HDIM], g_HwB[NW * HDIM];
__device__ float g_HsA[NS * HDIM], g_HsB[NS * HDIM];
__device__ float g_HrA[NR * HDIM], g_HrB[NR * HDIM];

// ---------------- packed f32x2 helpers ----------------
__device__ __forceinline__ ull pack2(float lo, float hi) {
    ull r; asm("mov.b64 %0, {%1, %2};" : "=l"(r) : "f"(lo), "f"(hi)); return r;
}
__device__ __forceinline__ ull dup2(float v) { return pack2(v, v); }
__device__ __forceinline__ void ffma2(ull& d, ull a, ull b) {
    asm("fma.rn.f32x2 %0, %1, %2, %3;" : "=l"(d) : "l"(a), "l"(b), "l"(d));
}
__device__ __forceinline__ float2 unpack2(ull v) {
    float2 f; asm("mov.b64 {%0, %1}, %2;" : "=f"(f.x), "=f"(f.y) : "l"(v)); return f;
}
__device__ __forceinline__ float sigmoid_f(float x) { return 1.f / (1.f + expf(-x)); }

// ---------------- SGEMM: C[M,N] = A[M,K] @ W[N,K]^T + bias[N] ----------------
// FFMA2 inner loop, vectorized LDS, register prefetch. K % 8 == 0.
#define BM 128
#define BN 128
#define BK 8

template <bool GATHER>
__global__ __launch_bounds__(256, 2)
void sgemm_f32x2(const float* __restrict__ A, const int* __restrict__ idx,
                 const float* __restrict__ W, const float* __restrict__ bias,
                 float* __restrict__ C, int M, int K, int N)
{
    __shared__ float As[BK][BM];
    __shared__ float Bs[BK][BN];

    const int tid = threadIdx.x;
    const int m0 = blockIdx.y * BM;
    const int n0 = blockIdx.x * BN;

    const int a_m  = tid & 127;
    const int a_kq = tid >> 7;       // 0..1 -> k offset a_kq*4
    const int b_n  = tid >> 1;
    const int b_kq = tid & 1;

    const bool a_valid = (m0 + a_m) < M;
    const float* Arow = A;  // safe dummy
    if (a_valid) {
        if (GATHER) Arow = A + (size_t)idx[m0 + a_m] * K;
        else        Arow = A + (size_t)(m0 + a_m) * K;
    }
    const float* Brow = W + (size_t)(n0 + b_n) * K;

    const int tx = tid & 15;   // n micro-tile (8 cols = 4 pairs)
    const int ty = tid >> 4;   // m micro-tile (8 rows)

    ull acc2[8][4];
#pragma unroll
    for (int i = 0; i < 8; i++)
#pragma unroll
        for (int j = 0; j < 4; j++) acc2[i][j] = 0ull;

    float4 av = make_float4(0.f, 0.f, 0.f, 0.f);
    if (a_valid) av = *reinterpret_cast<const float4*>(Arow + a_kq * 4);
    float4 bv = *reinterpret_cast<const float4*>(Brow + b_kq * 4);

    for (int kk = 0; kk < K; kk += BK) {
        As[a_kq * 4 + 0][a_m] = av.x;
        As[a_kq * 4 + 1][a_m] = av.y;
        As[a_kq * 4 + 2][a_m] = av.z;
        As[a_kq * 4 + 3][a_m] = av.w;
        Bs[b_kq * 4 + 0][b_n] = bv.x;
        Bs[b_kq * 4 + 1][b_n] = bv.y;
        Bs[b_kq * 4 + 2][b_n] = bv.z;
        Bs[b_kq * 4 + 3][b_n] = bv.w;
        __syncthreads();

        if (kk + BK < K) {
            if (a_valid) av = *reinterpret_cast<const float4*>(Arow + kk + BK + a_kq * 4);
            bv = *reinterpret_cast<const float4*>(Brow + kk + BK + b_kq * 4);
        }

#pragma unroll
        for (int k = 0; k < BK; k++) {
            float4 a0 = *reinterpret_cast<const float4*>(&As[k][ty * 8]);
            float4 a1 = *reinterpret_cast<const float4*>(&As[k][ty * 8 + 4]);
            float4 b0 = *reinterpret_cast<const float4*>(&Bs[k][tx * 8]);
            float4 b1 = *reinterpret_cast<const float4*>(&Bs[k][tx * 8 + 4]);
            ull bp[4];
            bp[0] = pack2(b0.x, b0.y); bp[1] = pack2(b0.z, b0.w);
            bp[2] = pack2(b1.x, b1.y); bp[3] = pack2(b1.z, b1.w);
            float a[8] = {a0.x, a0.y, a0.z, a0.w, a1.x, a1.y, a1.z, a1.w};
#pragma unroll
            for (int i = 0; i < 8; i++) {
                ull ad = dup2(a[i]);
#pragma unroll
                for (int j = 0; j < 4; j++) ffma2(acc2[i][j], ad, bp[j]);
            }
        }
        __syncthreads();
    }

#pragma unroll
    for (int i = 0; i < 8; i++) {
        int row = m0 + ty * 8 + i;
        if (row >= M) continue;
#pragma unroll
        for (int j = 0; j < 4; j++) {
            int col = n0 + tx * 8 + j * 2;
            float2 p = unpack2(acc2[i][j]);
            float2 bb = *reinterpret_cast<const float2*>(bias + col);
            float2 o; o.x = p.x + bb.x; o.y = p.y + bb.y;
            *reinterpret_cast<float2*>(C + (size_t)row * N + col) = o;
        }
    }
}

// ---------------- fused GRU step: gh = h @ Whh^T + bhh, then gate update -----
// Gate-aware tiling: CTA (n0, m0) computes gate slices [n0,n0+64) of r,z,n for
// rows [m0,m0+128) and writes hout directly. grid = (HDIM/64, ceil(M/128)).
__global__ __launch_bounds__(256)
void gru_step_fused(const float* __restrict__ hin, const float* __restrict__ Whh,
                    const float* __restrict__ bhh, const float* __restrict__ gx,
                    int T, int t, float* __restrict__ hout, int M)
{
    __shared__ float As[BK][BM];       // h tile
    __shared__ float Bs[3][BK][64];    // Whh tiles for r,z,n

    const int tid = threadIdx.x;
    const int n0 = blockIdx.x * 64;    // h-column tile
    const int m0 = blockIdx.y * BM;
    const int tx = tid & 15;           // 4 cols (2 pairs) per gate
    const int ty = tid >> 4;           // 8 rows

    const int a_m  = tid & 127;
    const int a_kq = tid >> 7;
    const bool a_valid = (m0 + a_m) < M;
    const float* Arow = hin + (size_t)(a_valid ? (m0 + a_m) : 0) * HDIM;

    // B tasks: 192 (gate,col) rows x 2 float4 chunks = 384; thread does task tid
    // and (tid<128) task tid+256.
    const int r1 = tid >> 1,            kq1 = tid & 1;
    const int g1 = r1 >> 6,             c1  = r1 & 63;
    const int t2 = tid + 256;
    const int r2 = t2 >> 1,             kq2 = t2 & 1;
    const int g2 = r2 >> 6,             c2  = r2 & 63;
    const float* Bp1 = Whh + ((size_t)(g1 * HDIM + n0 + c1)) * HDIM + kq1 * 4;
    const float* Bp2 = Whh + ((size_t)(g2 * HDIM + n0 + c2)) * HDIM + kq2 * 4;

    ull acc[3][8][2];
#pragma unroll
    for (int g = 0; g < 3; g++)
#pragma unroll
        for (int i = 0; i < 8; i++) { acc[g][i][0] = 0ull; acc[g][i][1] = 0ull; }

    float4 av = make_float4(0.f, 0.f, 0.f, 0.f);
    if (a_valid) av = *reinterpret_cast<const float4*>(Arow + a_kq * 4);
    float4 bv1 = *reinterpret_cast<const float4*>(Bp1);
    float4 bv2 = make_float4(0.f, 0.f, 0.f, 0.f);
    if (tid < 128) bv2 = *reinterpret_cast<const float4*>(Bp2);

    for (int kk = 0; kk < HDIM; kk += BK) {
        As[a_kq * 4 + 0][a_m] = av.x;
        As[a_kq * 4 + 1][a_m] = av.y;
        As[a_kq * 4 + 2][a_m] = av.z;
        As[a_kq * 4 + 3][a_m] = av.w;
        Bs[g1][kq1 * 4 + 0][c1] = bv1.x;
        Bs[g1][kq1 * 4 + 1][c1] = bv1.y;
        Bs[g1][kq1 * 4 + 2][c1] = bv1.z;
        Bs[g1][kq1 * 4 + 3][c1] = bv1.w;
        if (tid < 128) {
            Bs[g2][kq2 * 4 + 0][c2] = bv2.x;
            Bs[g2][kq2 * 4 + 1][c2] = bv2.y;
            Bs[g2][kq2 * 4 + 2][c2] = bv2.z;
            Bs[g2][kq2 * 4 + 3][c2] = bv2.w;
        }
        __syncthreads();

        if (kk + BK < HDIM) {
            if (a_valid) av = *reinterpret_cast<const float4*>(Arow + kk + BK + a_kq * 4);
            bv1 = *reinterpret_cast<const float4*>(Bp1 + kk + BK);
            if (tid < 128) bv2 = *reinterpret_cast<const float4*>(Bp2 + kk + BK);
        }

#pragma unroll
        for (int k = 0; k < BK; k++) {
            float4 a0 = *reinterpret_cast<const float4*>(&As[k][ty * 8]);
            float4 a1 = *reinterpret_cast<const float4*>(&As[k][ty * 8 + 4]);
            float a[8] = {a0.x, a0.y, a0.z, a0.w, a1.x, a1.y, a1.z, a1.w};
            ull bp[3][2];
#pragma unroll
            for (int g = 0; g < 3; g++) {
                float4 b = *reinterpret_cast<const float4*>(&Bs[g][k][tx * 4]);
                bp[g][0] = pack2(b.x, b.y);
                bp[g][1] = pack2(b.z, b.w);
            }
#pragma unroll
            for (int i = 0; i < 8; i++) {
                ull ad = dup2(a[i]);
#pragma unroll
                for (int g = 0; g < 3; g++) {
                    ffma2(acc[g][i][0], ad, bp[g][0]);
                    ffma2(acc[g][i][1], ad, bp[g][1]);
                }
            }
        }
        __syncthreads();
    }

    // epilogue: GRU gate math. bias pairs hoisted (same for all rows).
    const int jb = n0 + tx * 4;
    float2 br[2], bz[2], bn[2];
#pragma unroll
    for (int p = 0; p < 2; p++) {
        br[p] = *reinterpret_cast<const float2*>(bhh + jb + p * 2);
        bz[p] = *reinterpret_cast<const float2*>(bhh + HDIM + jb + p * 2);
        bn[p] = *reinterpret_cast<const float2*>(bhh + 2 * HDIM + jb + p * 2);
    }

#pragma unroll
    for (int i = 0; i < 8; i++) {
        int row = m0 + ty * 8 + i;
        if (row >= M) continue;
        const float* gxp = gx + ((size_t)row * T + t) * GDIM;
        const float* hp  = hin + (size_t)row * HDIM;
        float*       op  = hout + (size_t)row * HDIM;
#pragma unroll
        for (int p = 0; p < 2; p++) {
            int j = jb + p * 2;
            float2 ar = unpack2(acc[0][i][p]);
            float2 az = unpack2(acc[1][i][p]);
            float2 an = unpack2(acc[2][i][p]);
            float2 xr = *reinterpret_cast<const float2*>(gxp + j);
            float2 xz = *reinterpret_cast<const float2*>(gxp + HDIM + j);
            float2 xn = *reinterpret_cast<const float2*>(gxp + 2 * HDIM + j);
            float2 h  = *reinterpret_cast<const float2*>(hp + j);
            float r0 = sigmoid_f(xr.x + ar.x + br[p].x);
            float r1v = sigmoid_f(xr.y + ar.y + br[p].y);
            float z0 = sigmoid_f(xz.x + az.x + bz[p].x);
            float z1 = sigmoid_f(xz.y + az.y + bz[p].y);
            float n0v = tanhf(xn.x + r0 * (an.x + bn[p].x));
            float n1v = tanhf(xn.y + r1v * (an.y + bn[p].y));
            float2 o;
            o.x = (1.f - z0) * n0v + z0 * h.x;
            o.y = (1.f - z1) * n1v + z1 * h.y;
            *reinterpret_cast<float2*>(op + j) = o;
        }
    }
}

// ---------------- t = 0 GRU step (h0 = 0): h1 = f(gx[:,0,:], bhh) ------------
__global__ void gru_init_kernel(const float* __restrict__ gx, const float* __restrict__ bhh,
                                float* __restrict__ hout, int Mseq, int T)
{
    int i = blockIdx.x * blockDim.x + threadIdx.x;
    if (i >= Mseq * HDIM) return;
    int seq = i >> 8;
    int j   = i & 255;
    const float* g = gx + (size_t)seq * T * GDIM;
    float r = sigmoid_f(g[j] + bhh[j]);
    float z = sigmoid_f(g[j + HDIM] + bhh[j + HDIM]);
    float n = tanhf(g[j + 2 * HDIM] + r * bhh[j + 2 * HDIM]);
    hout[i] = (1.f - z) * n;
}

// ---------------- MLP: out[row] = W2 @ selu(x @ W1^T + b1) + b2 --------------
__global__ __launch_bounds__(128)
void mlp_kernel(const float* __restrict__ X,
                const float* __restrict__ W1, const float* __restrict__ b1,
                const float* __restrict__ W2, const float* __restrict__ b2,
                float* __restrict__ out)
{
    const int row = blockIdx.x;
    const int i = threadIdx.x;
    __shared__ float xs[HDIM];
    __shared__ float red[4];

    xs[i]       = X[(size_t)row * HDIM + i];
    xs[i + 128] = X[(size_t)row * HDIM + i + 128];
    __syncthreads();

    const float* w = W1 + (size_t)i * HDIM;
    float acc = b1[i];
#pragma unroll 8
    for (int k = 0; k < HDIM; k += 4) {
        float4 wv = *reinterpret_cast<const float4*>(w + k);
        acc = fmaf(wv.x, xs[k], acc);
        acc = fmaf(wv.y, xs[k + 1], acc);
        acc = fmaf(wv.z, xs[k + 2], acc);
        acc = fmaf(wv.w, xs[k + 3], acc);
    }
    const float scale = 1.0507009873554805f;
    const float alpha = 1.6732632423543772f;
    float s = scale * (acc > 0.f ? acc : alpha * (expf(acc) - 1.f));
    float v = s * W2[i];
#pragma unroll
    for (int off = 16; off > 0; off >>= 1)
        v += __shfl_down_sync(0xffffffffu, v, off);
    if ((i & 31) == 0) red[i >> 5] = v;
    __syncthreads();
    if (i == 0) out[row] = red[0] + red[1] + red[2] + red[3] + b2[0];
}

// ---------------- host orchestration ----------------
extern "C" void kernel_launch(void* const* d_in, const int* in_sizes, int n_in,
                              void* d_out, int out_size)
{
    (void)in_sizes; (void)n_in; (void)out_size;

    const int*   idx    = (const int*)  d_in[0];
    const float* emb    = (const float*)d_in[1];
    const float* w_Wih  = (const float*)d_in[2];
    const float* w_Whh  = (const float*)d_in[3];
    const float* w_bih  = (const float*)d_in[4];
    const float* w_bhh  = (const float*)d_in[5];
    const float* s_Wih  = (const float*)d_in[6];
    const float* s_Whh  = (const float*)d_in[7];
    const float* s_bih  = (const float*)d_in[8];
    const float* s_bhh  = (const float*)d_in[9];
    const float* r_Wih  = (const float*)d_in[10];
    const float* r_Whh  = (const float*)d_in[11];
    const float* r_bih  = (const float*)d_in[12];
    const float* r_bhh  = (const float*)d_in[13];
    const float* rfc_W1 = (const float*)d_in[14];
    const float* rfc_b1 = (const float*)d_in[15];
    const float* rfc_W2 = (const float*)d_in[16];
    const float* rfc_b2 = (const float*)d_in[17];
    const float* pfc_W1 = (const float*)d_in[18];
    const float* pfc_b1 = (const float*)d_in[19];
    const float* pfc_W2 = (const float*)d_in[20];
    const float* pfc_b2 = (const float*)d_in[21];
    float* out = (float*)d_out;

    float *GXw, *GXs, *GXr, *HwA, *HwB, *HsA, *HsB, *HrA, *HrB;
    cudaGetSymbolAddress((void**)&GXw, g_GXw);
    cudaGetSymbolAddress((void**)&GXs, g_GXs);
    cudaGetSymbolAddress((void**)&GXr, g_GXr);
    cudaGetSymbolAddress((void**)&HwA, g_HwA);
    cudaGetSymbolAddress((void**)&HwB, g_HwB);
    cudaGetSymbolAddress((void**)&HsA, g_HsA);
    cudaGetSymbolAddress((void**)&HsB, g_HsB);
    cudaGetSymbolAddress((void**)&HrA, g_HrA);
    cudaGetSymbolAddress((void**)&HrB, g_HrB);

    // ---- word level ----
    {
        dim3 grid(GDIM / BN, (NW * TWSTEPS + BM - 1) / BM);
        sgemm_f32x2<true><<<grid, 256>>>(emb, idx, w_Wih, w_bih, GXw,
                                         NW * TWSTEPS, EDIM, GDIM);
    }
    float* hw[2] = {HwA, HwB};
    int cw = 0;
    gru_init_kernel<<<(NW * HDIM + 255) / 256, 256>>>(GXw, w_bhh, hw[0], NW, TWSTEPS);
    {
        dim3 grid(HDIM / 64, (NW + BM - 1) / BM);
        for (int t = 1; t < TWSTEPS; t++) {
            gru_step_fused<<<grid, 256>>>(hw[cw], w_Whh, w_bhh, GXw, TWSTEPS, t,
                                          hw[1 - cw], NW);
            cw = 1 - cw;
        }
    }
    const float* sent_h = hw[cw];

    // ---- sentence level ----
    {
        dim3 grid(GDIM / BN, (NS * TSSTEPS + BM - 1) / BM);
        sgemm_f32x2<false><<<grid, 256>>>(sent_h, nullptr, s_Wih, s_bih, GXs,
                                          NS * TSSTEPS, HDIM, GDIM);
    }
    float* hs[2] = {HsA, HsB};
    int cs = 0;
    gru_init_kernel<<<(NS * HDIM + 255) / 256, 256>>>(GXs, s_bhh, hs[0], NS, TSSTEPS);
    {
        dim3 grid(HDIM / 64, (NS + BM - 1) / BM);
        for (int t = 1; t < TSSTEPS; t++) {
            gru_step_fused<<<grid, 256>>>(hs[cs], s_Whh, s_bhh, GXs, TSSTEPS, t,
                                          hs[1 - cs], NS);
            cs = 1 - cs;
        }
    }
    const float* p_batch = hs[cs];

    // r_stars -> out[16 .. 272)
    mlp_kernel<<<NS, 128>>>(p_batch, rfc_W1, rfc_b1, rfc_W2, rfc_b2, out + NR);

    // ---- review level ----
    {
        dim3 grid(GDIM / BN, (NR * TRSTEPS + BM - 1) / BM);
        sgemm_f32x2<false><<<grid, 256>>>(p_batch, nullptr, r_Wih, r_bih, GXr,
                                          NR * TRSTEPS, HDIM, GDIM);
    }
    float* hr[2] = {HrA, HrB};
    int cr = 0;
    gru_init_kernel<<<(NR * HDIM + 255) / 256, 256>>>(GXr, r_bhh, hr[0], NR, TRSTEPS);
    {
        dim3 grid(HDIM / 64, (NR + BM - 1) / BM);
        for (int t = 1; t < TRSTEPS; t++) {
            gru_step_fused<<<grid, 256>>>(hr[cr], r_Whh, r_bhh, GXr, TRSTEPS, t,
                                          hr[1 - cr], NR);
            cr = 1 - cr;
        }
    }
    // b_stars -> out[0 .. 16)
    mlp_kernel<<<NR, 128>>>(hr[cr], pfc_W1, pfc_b1, pfc_W2, pfc_b2, out);
}

// round 3
// speedup vs baseline: 1.5397x; 1.2134x over previous
#include <cuda_runtime.h>
#include <math.h>

// ---------------- problem dims ----------------
#define HDIM 256
#define GDIM 768           // 3*H
#define EDIM 200
#define NW 4096            // B*R*S word sequences
#define TWSTEPS 32
#define NS 256             // B*R
#define TSSTEPS 16
#define NR 16              // B
#define TRSTEPS 16

typedef unsigned long long ull;

// ---------------- scratch (static device globals; no allocs allowed) --------
__device__ float g_GXw[(size_t)NW * TWSTEPS * GDIM];   // 402 MB: word input gates
__device__ float g_GXs[(size_t)NS * TSSTEPS * GDIM];   // 12.6 MB
__device__ float g_GXr[(size_t)NR * TRSTEPS * GDIM];   // 0.8 MB
__device__ float g_HwA[NW * HDIM], g_HwB[NW * HDIM];
__device__ float g_HsA[NS * HDIM], g_HsB[NS * HDIM];
__device__ float g_HrA[NR * HDIM], g_HrB[NR * HDIM];

// ---------------- packed f32x2 helpers ----------------
__device__ __forceinline__ ull pack2(float lo, float hi) {
    ull r; asm("mov.b64 %0, {%1, %2};" : "=l"(r) : "f"(lo), "f"(hi)); return r;
}
__device__ __forceinline__ ull dup2(float v) { return pack2(v, v); }
__device__ __forceinline__ void ffma2(ull& d, ull a, ull b) {
    asm("fma.rn.f32x2 %0, %1, %2, %3;" : "=l"(d) : "l"(a), "l"(b), "l"(d));
}
__device__ __forceinline__ float2 unpack2(ull v) {
    float2 f; asm("mov.b64 {%0, %1}, %2;" : "=f"(f.x), "=f"(f.y) : "l"(v)); return f;
}
__device__ __forceinline__ float sigmoid_f(float x) { return 1.f / (1.f + expf(-x)); }

// ---------------- SGEMM: C[M,N] = A[M,K] @ W[N,K]^T + bias[N] ----------------
// FFMA2 inner loop, double-buffered smem (1 sync/tile), register prefetch.
#define BM 128
#define BN 128
#define BK 8

template <bool GATHER>
__global__ __launch_bounds__(256, 2)
void sgemm_f32x2(const float* __restrict__ A, const int* __restrict__ idx,
                 const float* __restrict__ W, const float* __restrict__ bias,
                 float* __restrict__ C, int M, int K, int N)
{
    __shared__ float As[2][BK][BM];
    __shared__ float Bs[2][BK][BN];

    const int tid = threadIdx.x;
    const int m0 = blockIdx.y * BM;
    const int n0 = blockIdx.x * BN;

    const int a_m  = tid & 127;
    const int a_kq = tid >> 7;       // 0..1 -> k offset a_kq*4
    const int b_n  = tid >> 1;
    const int b_kq = tid & 1;

    const bool a_valid = (m0 + a_m) < M;
    const float* Arow = A;
    if (a_valid) {
        if (GATHER) Arow = A + (size_t)idx[m0 + a_m] * K;
        else        Arow = A + (size_t)(m0 + a_m) * K;
    }
    const float* Brow = W + (size_t)(n0 + b_n) * K;

    const int tx = tid & 15;   // n micro-tile (8 cols = 4 pairs)
    const int ty = tid >> 4;   // m micro-tile (8 rows)

    ull acc2[8][4];
#pragma unroll
    for (int i = 0; i < 8; i++)
#pragma unroll
        for (int j = 0; j < 4; j++) acc2[i][j] = 0ull;

    // prologue: tile 0 -> smem[0]
    float4 av = make_float4(0.f, 0.f, 0.f, 0.f);
    if (a_valid) av = *reinterpret_cast<const float4*>(Arow + a_kq * 4);
    float4 bv = *reinterpret_cast<const float4*>(Brow + b_kq * 4);
    As[0][a_kq * 4 + 0][a_m] = av.x;  As[0][a_kq * 4 + 1][a_m] = av.y;
    As[0][a_kq * 4 + 2][a_m] = av.z;  As[0][a_kq * 4 + 3][a_m] = av.w;
    Bs[0][b_kq * 4 + 0][b_n] = bv.x;  Bs[0][b_kq * 4 + 1][b_n] = bv.y;
    Bs[0][b_kq * 4 + 2][b_n] = bv.z;  Bs[0][b_kq * 4 + 3][b_n] = bv.w;
    __syncthreads();

    int buf = 0;
    for (int kk = 0; kk < K; kk += BK) {
        const bool has_next = (kk + BK) < K;
        if (has_next) {
            if (a_valid) av = *reinterpret_cast<const float4*>(Arow + kk + BK + a_kq * 4);
            bv = *reinterpret_cast<const float4*>(Brow + kk + BK + b_kq * 4);
        }

#pragma unroll
        for (int k = 0; k < BK; k++) {
            float4 a0 = *reinterpret_cast<const float4*>(&As[buf][k][ty * 8]);
            float4 a1 = *reinterpret_cast<const float4*>(&As[buf][k][ty * 8 + 4]);
            ulonglong2 bq0 = *reinterpret_cast<const ulonglong2*>(&Bs[buf][k][tx * 8]);
            ulonglong2 bq1 = *reinterpret_cast<const ulonglong2*>(&Bs[buf][k][tx * 8 + 4]);
            ull bp[4] = {bq0.x, bq0.y, bq1.x, bq1.y};
            float a[8] = {a0.x, a0.y, a0.z, a0.w, a1.x, a1.y, a1.z, a1.w};
#pragma unroll
            for (int i = 0; i < 8; i++) {
                ull ad = dup2(a[i]);
#pragma unroll
                for (int j = 0; j < 4; j++) ffma2(acc2[i][j], ad, bp[j]);
            }
        }

        if (has_next) {
            int nb = buf ^ 1;
            As[nb][a_kq * 4 + 0][a_m] = av.x;  As[nb][a_kq * 4 + 1][a_m] = av.y;
            As[nb][a_kq * 4 + 2][a_m] = av.z;  As[nb][a_kq * 4 + 3][a_m] = av.w;
            Bs[nb][b_kq * 4 + 0][b_n] = bv.x;  Bs[nb][b_kq * 4 + 1][b_n] = bv.y;
            Bs[nb][b_kq * 4 + 2][b_n] = bv.z;  Bs[nb][b_kq * 4 + 3][b_n] = bv.w;
            __syncthreads();
            buf = nb;
        }
    }

#pragma unroll
    for (int i = 0; i < 8; i++) {
        int row = m0 + ty * 8 + i;
        if (row >= M) continue;
#pragma unroll
        for (int j = 0; j < 4; j++) {
            int col = n0 + tx * 8 + j * 2;
            float2 p = unpack2(acc2[i][j]);
            float2 bb = *reinterpret_cast<const float2*>(bias + col);
            float2 o; o.x = p.x + bb.x; o.y = p.y + bb.y;
            *reinterpret_cast<float2*>(C + (size_t)row * N + col) = o;
        }
    }
}

// ---------------- fused GRU step (large M): 128 rows x 64 h-cols / CTA -------
__global__ __launch_bounds__(256)
void gru_step_fused(const float* __restrict__ hin, const float* __restrict__ Whh,
                    const float* __restrict__ bhh, const float* __restrict__ gx,
                    int T, int t, float* __restrict__ hout, int M)
{
    __shared__ float As[2][BK][BM];       // h tile
    __shared__ float Bs[2][3][BK][64];    // Whh tiles for r,z,n

    const int tid = threadIdx.x;
    const int n0 = blockIdx.x * 64;
    const int m0 = blockIdx.y * BM;
    const int tx = tid & 15;           // 4 cols (2 pairs) per gate
    const int ty = tid >> 4;           // 8 rows

    const int a_m  = tid & 127;
    const int a_kq = tid >> 7;
    const bool a_valid = (m0 + a_m) < M;
    const float* Arow = hin + (size_t)(a_valid ? (m0 + a_m) : 0) * HDIM;

    const int r1 = tid >> 1,  kq1 = tid & 1;
    const int g1 = r1 >> 6,   c1  = r1 & 63;
    const int t2 = tid + 256;
    const int r2 = t2 >> 1,   kq2 = t2 & 1;
    const int g2 = r2 >> 6,   c2  = r2 & 63;
    const float* Bp1 = Whh + ((size_t)(g1 * HDIM + n0 + c1)) * HDIM + kq1 * 4;
    const float* Bp2 = Whh + ((size_t)(g2 * HDIM + n0 + c2)) * HDIM + kq2 * 4;

    ull acc[3][8][2];
#pragma unroll
    for (int g = 0; g < 3; g++)
#pragma unroll
        for (int i = 0; i < 8; i++) { acc[g][i][0] = 0ull; acc[g][i][1] = 0ull; }

    // prologue
    float4 av = make_float4(0.f, 0.f, 0.f, 0.f);
    if (a_valid) av = *reinterpret_cast<const float4*>(Arow + a_kq * 4);
    float4 bv1 = *reinterpret_cast<const float4*>(Bp1);
    float4 bv2 = make_float4(0.f, 0.f, 0.f, 0.f);
    if (tid < 128) bv2 = *reinterpret_cast<const float4*>(Bp2);
    As[0][a_kq * 4 + 0][a_m] = av.x;  As[0][a_kq * 4 + 1][a_m] = av.y;
    As[0][a_kq * 4 + 2][a_m] = av.z;  As[0][a_kq * 4 + 3][a_m] = av.w;
    Bs[0][g1][kq1 * 4 + 0][c1] = bv1.x;  Bs[0][g1][kq1 * 4 + 1][c1] = bv1.y;
    Bs[0][g1][kq1 * 4 + 2][c1] = bv1.z;  Bs[0][g1][kq1 * 4 + 3][c1] = bv1.w;
    if (tid < 128) {
        Bs[0][g2][kq2 * 4 + 0][c2] = bv2.x;  Bs[0][g2][kq2 * 4 + 1][c2] = bv2.y;
        Bs[0][g2][kq2 * 4 + 2][c2] = bv2.z;  Bs[0][g2][kq2 * 4 + 3][c2] = bv2.w;
    }
    __syncthreads();

    int buf = 0;
    for (int kk = 0; kk < HDIM; kk += BK) {
        const bool has_next = (kk + BK) < HDIM;
        if (has_next) {
            if (a_valid) av = *reinterpret_cast<const float4*>(Arow + kk + BK + a_kq * 4);
            bv1 = *reinterpret_cast<const float4*>(Bp1 + kk + BK);
            if (tid < 128) bv2 = *reinterpret_cast<const float4*>(Bp2 + kk + BK);
        }

#pragma unroll
        for (int k = 0; k < BK; k++) {
            float4 a0 = *reinterpret_cast<const float4*>(&As[buf][k][ty * 8]);
            float4 a1 = *reinterpret_cast<const float4*>(&As[buf][k][ty * 8 + 4]);
            float a[8] = {a0.x, a0.y, a0.z, a0.w, a1.x, a1.y, a1.z, a1.w};
            ull bp[3][2];
#pragma unroll
            for (int g = 0; g < 3; g++) {
                ulonglong2 bq = *reinterpret_cast<const ulonglong2*>(&Bs[buf][g][k][tx * 4]);
                bp[g][0] = bq.x; bp[g][1] = bq.y;
            }
#pragma unroll
            for (int i = 0; i < 8; i++) {
                ull ad = dup2(a[i]);
#pragma unroll
                for (int g = 0; g < 3; g++) {
                    ffma2(acc[g][i][0], ad, bp[g][0]);
                    ffma2(acc[g][i][1], ad, bp[g][1]);
                }
            }
        }

        if (has_next) {
            int nb = buf ^ 1;
            As[nb][a_kq * 4 + 0][a_m] = av.x;  As[nb][a_kq * 4 + 1][a_m] = av.y;
            As[nb][a_kq * 4 + 2][a_m] = av.z;  As[nb][a_kq * 4 + 3][a_m] = av.w;
            Bs[nb][g1][kq1 * 4 + 0][c1] = bv1.x;  Bs[nb][g1][kq1 * 4 + 1][c1] = bv1.y;
            Bs[nb][g1][kq1 * 4 + 2][c1] = bv1.z;  Bs[nb][g1][kq1 * 4 + 3][c1] = bv1.w;
            if (tid < 128) {
                Bs[nb][g2][kq2 * 4 + 0][c2] = bv2.x;  Bs[nb][g2][kq2 * 4 + 1][c2] = bv2.y;
                Bs[nb][g2][kq2 * 4 + 2][c2] = bv2.z;  Bs[nb][g2][kq2 * 4 + 3][c2] = bv2.w;
            }
            __syncthreads();
            buf = nb;
        }
    }

    const int jb = n0 + tx * 4;
    float2 br[2], bz[2], bn[2];
#pragma unroll
    for (int p = 0; p < 2; p++) {
        br[p] = *reinterpret_cast<const float2*>(bhh + jb + p * 2);
        bz[p] = *reinterpret_cast<const float2*>(bhh + HDIM + jb + p * 2);
        bn[p] = *reinterpret_cast<const float2*>(bhh + 2 * HDIM + jb + p * 2);
    }

#pragma unroll
    for (int i = 0; i < 8; i++) {
        int row = m0 + ty * 8 + i;
        if (row >= M) continue;
        const float* gxp = gx + ((size_t)row * T + t) * GDIM;
        const float* hp  = hin + (size_t)row * HDIM;
        float*       op  = hout + (size_t)row * HDIM;
#pragma unroll
        for (int p = 0; p < 2; p++) {
            int j = jb + p * 2;
            float2 ar = unpack2(acc[0][i][p]);
            float2 az = unpack2(acc[1][i][p]);
            float2 an = unpack2(acc[2][i][p]);
            float2 xr = *reinterpret_cast<const float2*>(gxp + j);
            float2 xz = *reinterpret_cast<const float2*>(gxp + HDIM + j);
            float2 xn = *reinterpret_cast<const float2*>(gxp + 2 * HDIM + j);
            float2 h  = *reinterpret_cast<const float2*>(hp + j);
            float r0 = sigmoid_f(xr.x + ar.x + br[p].x);
            float r1v = sigmoid_f(xr.y + ar.y + br[p].y);
            float z0 = sigmoid_f(xz.x + az.x + bz[p].x);
            float z1 = sigmoid_f(xz.y + az.y + bz[p].y);
            float n0v = tanhf(xn.x + r0 * (an.x + bn[p].x));
            float n1v = tanhf(xn.y + r1v * (an.y + bn[p].y));
            float2 o;
            o.x = (1.f - z0) * n0v + z0 * h.x;
            o.y = (1.f - z1) * n1v + z1 * h.y;
            *reinterpret_cast<float2*>(op + j) = o;
        }
    }
}

// ---------------- small-M GRU step: 32 rows x 32 h-cols / CTA ----------------
// grid = (HDIM/32, ceil(M/32)), 256 threads. K=256, BK=16.
#define SBK 16
__global__ __launch_bounds__(256)
void gru_step_small(const float* __restrict__ hin, const float* __restrict__ Whh,
                    const float* __restrict__ bhh, const float* __restrict__ gx,
                    int T, int t, float* __restrict__ hout, int M)
{
    __shared__ float As[2][SBK][32];
    __shared__ float Bs[2][3][SBK][32];

    const int tid = threadIdx.x;
    const int n0 = blockIdx.x * 32;
    const int m0 = blockIdx.y * 32;
    const int tx = tid & 7;            // 4 cols (2 pairs) per gate
    const int ty = tid >> 3;           // 1 row

    // A loads: 32 rows x 16 k = 512 floats -> float2 per thread
    const int a_m  = tid & 31;
    const int a_kq = tid >> 5;         // 0..7 -> k offset a_kq*2
    const bool a_valid = (m0 + a_m) < M;
    const float* Arow = hin + (size_t)(a_valid ? (m0 + a_m) : 0) * HDIM;

    // B loads: 96 gate-cols x 4 float4-chunks = 384 tasks; thread: tid, tid+256(<128)
    const int r1 = tid >> 2,  kq1 = tid & 3;
    const int g1 = r1 >> 5,   c1  = r1 & 31;
    const int r2 = (tid + 256) >> 2;
    const int g2 = r2 >> 5,   c2  = r2 & 31;
    const float* Bp1 = Whh + ((size_t)(g1 * HDIM + n0 + c1)) * HDIM + kq1 * 4;
    const float* Bp2 = Whh + ((size_t)(g2 * HDIM + n0 + c2)) * HDIM + kq1 * 4;

    ull acc[3][2];
#pragma unroll
    for (int g = 0; g < 3; g++) { acc[g][0] = 0ull; acc[g][1] = 0ull; }

    float2 av = make_float2(0.f, 0.f);
    if (a_valid) av = *reinterpret_cast<const float2*>(Arow + a_kq * 2);
    float4 bv1 = *reinterpret_cast<const float4*>(Bp1);
    float4 bv2 = make_float4(0.f, 0.f, 0.f, 0.f);
    if (tid < 128) bv2 = *reinterpret_cast<const float4*>(Bp2);
    As[0][a_kq * 2 + 0][a_m] = av.x;  As[0][a_kq * 2 + 1][a_m] = av.y;
    Bs[0][g1][kq1 * 4 + 0][c1] = bv1.x;  Bs[0][g1][kq1 * 4 + 1][c1] = bv1.y;
    Bs[0][g1][kq1 * 4 + 2][c1] = bv1.z;  Bs[0][g1][kq1 * 4 + 3][c1] = bv1.w;
    if (tid < 128) {
        Bs[0][g2][kq1 * 4 + 0][c2] = bv2.x;  Bs[0][g2][kq1 * 4 + 1][c2] = bv2.y;
        Bs[0][g2][kq1 * 4 + 2][c2] = bv2.z;  Bs[0][g2][kq1 * 4 + 3][c2] = bv2.w;
    }
    __syncthreads();

    int buf = 0;
    for (int kk = 0; kk < HDIM; kk += SBK) {
        const bool has_next = (kk + SBK) < HDIM;
        if (has_next) {
            if (a_valid) av = *reinterpret_cast<const float2*>(Arow + kk + SBK + a_kq * 2);
            bv1 = *reinterpret_cast<const float4*>(Bp1 + kk + SBK);
            if (tid < 128) bv2 = *reinterpret_cast<const float4*>(Bp2 + kk + SBK);
        }

#pragma unroll
        for (int k = 0; k < SBK; k++) {
            ull ad = dup2(As[buf][k][ty]);
#pragma unroll
            for (int g = 0; g < 3; g++) {
                ulonglong2 bq = *reinterpret_cast<const ulonglong2*>(&Bs[buf][g][k][tx * 4]);
                ffma2(acc[g][0], ad, bq.x);
                ffma2(acc[g][1], ad, bq.y);
            }
        }

        if (has_next) {
            int nb = buf ^ 1;
            As[nb][a_kq * 2 + 0][a_m] = av.x;  As[nb][a_kq * 2 + 1][a_m] = av.y;
            Bs[nb][g1][kq1 * 4 + 0][c1] = bv1.x;  Bs[nb][g1][kq1 * 4 + 1][c1] = bv1.y;
            Bs[nb][g1][kq1 * 4 + 2][c1] = bv1.z;  Bs[nb][g1][kq1 * 4 + 3][c1] = bv1.w;
            if (tid < 128) {
                Bs[nb][g2][kq1 * 4 + 0][c2] = bv2.x;  Bs[nb][g2][kq1 * 4 + 1][c2] = bv2.y;
                Bs[nb][g2][kq1 * 4 + 2][c2] = bv2.z;  Bs[nb][g2][kq1 * 4 + 3][c2] = bv2.w;
            }
            __syncthreads();
            buf = nb;
        }
    }

    const int row = m0 + ty;
    if (row >= M) return;
    const int jb = n0 + tx * 4;
    const float* gxp = gx + ((size_t)row * T + t) * GDIM;
    const float* hp  = hin + (size_t)row * HDIM;
    float*       op  = hout + (size_t)row * HDIM;
#pragma unroll
    for (int p = 0; p < 2; p++) {
        int j = jb + p * 2;
        float2 br = *reinterpret_cast<const float2*>(bhh + j);
        float2 bz = *reinterpret_cast<const float2*>(bhh + HDIM + j);
        float2 bn = *reinterpret_cast<const float2*>(bhh + 2 * HDIM + j);
        float2 ar = unpack2(acc[0][p]);
        float2 az = unpack2(acc[1][p]);
        float2 an = unpack2(acc[2][p]);
        float2 xr = *reinterpret_cast<const float2*>(gxp + j);
        float2 xz = *reinterpret_cast<const float2*>(gxp + HDIM + j);
        float2 xn = *reinterpret_cast<const float2*>(gxp + 2 * HDIM + j);
        float2 h  = *reinterpret_cast<const float2*>(hp + j);
        float r0 = sigmoid_f(xr.x + ar.x + br.x);
        float r1v = sigmoid_f(xr.y + ar.y + br.y);
        float z0 = sigmoid_f(xz.x + az.x + bz.x);
        float z1 = sigmoid_f(xz.y + az.y + bz.y);
        float n0v = tanhf(xn.x + r0 * (an.x + bn.x));
        float n1v = tanhf(xn.y + r1v * (an.y + bn.y));
        float2 o;
        o.x = (1.f - z0) * n0v + z0 * h.x;
        o.y = (1.f - z1) * n1v + z1 * h.y;
        *reinterpret_cast<float2*>(op + j) = o;
    }
}

// ---------------- t = 0 GRU step (h0 = 0): h1 = f(gx[:,0,:], bhh) ------------
__global__ void gru_init_kernel(const float* __restrict__ gx, const float* __restrict__ bhh,
                                float* __restrict__ hout, int Mseq, int T)
{
    int i = blockIdx.x * blockDim.x + threadIdx.x;
    if (i >= Mseq * HDIM) return;
    int seq = i >> 8;
    int j   = i & 255;
    const float* g = gx + (size_t)seq * T * GDIM;
    float r = sigmoid_f(g[j] + bhh[j]);
    float z = sigmoid_f(g[j + HDIM] + bhh[j + HDIM]);
    float n = tanhf(g[j + 2 * HDIM] + r * bhh[j + 2 * HDIM]);
    hout[i] = (1.f - z) * n;
}

// ---------------- MLP: out[row] = W2 @ selu(x @ W1^T + b1) + b2 --------------
__global__ __launch_bounds__(128)
void mlp_kernel(const float* __restrict__ X,
                const float* __restrict__ W1, const float* __restrict__ b1,
                const float* __restrict__ W2, const float* __restrict__ b2,
                float* __restrict__ out)
{
    const int row = blockIdx.x;
    const int i = threadIdx.x;
    __shared__ float xs[HDIM];
    __shared__ float red[4];

    xs[i]       = X[(size_t)row * HDIM + i];
    xs[i + 128] = X[(size_t)row * HDIM + i + 128];
    __syncthreads();

    const float* w = W1 + (size_t)i * HDIM;
    float acc = b1[i];
#pragma unroll 8
    for (int k = 0; k < HDIM; k += 4) {
        float4 wv = *reinterpret_cast<const float4*>(w + k);
        acc = fmaf(wv.x, xs[k], acc);
        acc = fmaf(wv.y, xs[k + 1], acc);
        acc = fmaf(wv.z, xs[k + 2], acc);
        acc = fmaf(wv.w, xs[k + 3], acc);
    }
    const float scale = 1.0507009873554805f;
    const float alpha = 1.6732632423543772f;
    float s = scale * (acc > 0.f ? acc : alpha * (expf(acc) - 1.f));
    float v = s * W2[i];
#pragma unroll
    for (int off = 16; off > 0; off >>= 1)
        v += __shfl_down_sync(0xffffffffu, v, off);
    if ((i & 31) == 0) red[i >> 5] = v;
    __syncthreads();
    if (i == 0) out[row] = red[0] + red[1] + red[2] + red[3] + b2[0];
}

// ---------------- host orchestration ----------------
extern "C" void kernel_launch(void* const* d_in, const int* in_sizes, int n_in,
                              void* d_out, int out_size)
{
    (void)in_sizes; (void)n_in; (void)out_size;

    const int*   idx    = (const int*)  d_in[0];
    const float* emb    = (const float*)d_in[1];
    const float* w_Wih  = (const float*)d_in[2];
    const float* w_Whh  = (const float*)d_in[3];
    const float* w_bih  = (const float*)d_in[4];
    const float* w_bhh  = (const float*)d_in[5];
    const float* s_Wih  = (const float*)d_in[6];
    const float* s_Whh  = (const float*)d_in[7];
    const float* s_bih  = (const float*)d_in[8];
    const float* s_bhh  = (const float*)d_in[9];
    const float* r_Wih  = (const float*)d_in[10];
    const float* r_Whh  = (const float*)d_in[11];
    const float* r_bih  = (const float*)d_in[12];
    const float* r_bhh  = (const float*)d_in[13];
    const float* rfc_W1 = (const float*)d_in[14];
    const float* rfc_b1 = (const float*)d_in[15];
    const float* rfc_W2 = (const float*)d_in[16];
    const float* rfc_b2 = (const float*)d_in[17];
    const float* pfc_W1 = (const float*)d_in[18];
    const float* pfc_b1 = (const float*)d_in[19];
    const float* pfc_W2 = (const float*)d_in[20];
    const float* pfc_b2 = (const float*)d_in[21];
    float* out = (float*)d_out;

    float *GXw, *GXs, *GXr, *HwA, *HwB, *HsA, *HsB, *HrA, *HrB;
    cudaGetSymbolAddress((void**)&GXw, g_GXw);
    cudaGetSymbolAddress((void**)&GXs, g_GXs);
    cudaGetSymbolAddress((void**)&GXr, g_GXr);
    cudaGetSymbolAddress((void**)&HwA, g_HwA);
    cudaGetSymbolAddress((void**)&HwB, g_HwB);
    cudaGetSymbolAddress((void**)&HsA, g_HsA);
    cudaGetSymbolAddress((void**)&HsB, g_HsB);
    cudaGetSymbolAddress((void**)&HrA, g_HrA);
    cudaGetSymbolAddress((void**)&HrB, g_HrB);

    // ---- word level ----
    {
        dim3 grid(GDIM / BN, (NW * TWSTEPS + BM - 1) / BM);
        sgemm_f32x2<true><<<grid, 256>>>(emb, idx, w_Wih, w_bih, GXw,
                                         NW * TWSTEPS, EDIM, GDIM);
    }
    float* hw[2] = {HwA, HwB};
    int cw = 0;
    gru_init_kernel<<<(NW * HDIM + 255) / 256, 256>>>(GXw, w_bhh, hw[0], NW, TWSTEPS);
    {
        dim3 grid(HDIM / 64, (NW + BM - 1) / BM);
        for (int t = 1; t < TWSTEPS; t++) {
            gru_step_fused<<<grid, 256>>>(hw[cw], w_Whh, w_bhh, GXw, TWSTEPS, t,
                                          hw[1 - cw], NW);
            cw = 1 - cw;
        }
    }
    const float* sent_h = hw[cw];

    // ---- sentence level ----
    {
        dim3 grid(GDIM / BN, (NS * TSSTEPS + BM - 1) / BM);
        sgemm_f32x2<false><<<grid, 256>>>(sent_h, nullptr, s_Wih, s_bih, GXs,
                                          NS * TSSTEPS, HDIM, GDIM);
    }
    float* hs[2] = {HsA, HsB};
    int cs = 0;
    gru_init_kernel<<<(NS * HDIM + 255) / 256, 256>>>(GXs, s_bhh, hs[0], NS, TSSTEPS);
    {
        dim3 grid(HDIM / 32, (NS + 31) / 32);
        for (int t = 1; t < TSSTEPS; t++) {
            gru_step_small<<<grid, 256>>>(hs[cs], s_Whh, s_bhh, GXs, TSSTEPS, t,
                                          hs[1 - cs], NS);
            cs = 1 - cs;
        }
    }
    const float* p_batch = hs[cs];

    // r_stars -> out[16 .. 272)
    mlp_kernel<<<NS, 128>>>(p_batch, rfc_W1, rfc_b1, rfc_W2, rfc_b2, out + NR);

    // ---- review level ----
    {
        dim3 grid(GDIM / BN, (NR * TRSTEPS + BM - 1) / BM);
        sgemm_f32x2<false><<<grid, 256>>>(p_batch, nullptr, r_Wih, r_bih, GXr,
                                          NR * TRSTEPS, HDIM, GDIM);
    }
    float* hr[2] = {HrA, HrB};
    int cr = 0;
    gru_init_kernel<<<(NR * HDIM + 255) / 256, 256>>>(GXr, r_bhh, hr[0], NR, TRSTEPS);
    {
        dim3 grid(HDIM / 32, (NR + 31) / 32);
        for (int t = 1; t < TRSTEPS; t++) {
            gru_step_small<<<grid, 256>>>(hr[cr], r_Whh, r_bhh, GXr, TRSTEPS, t,
                                          hr[1 - cr], NR);
            cr = 1 - cr;
        }
    }
    // b_stars -> out[0 .. 16)
    mlp_kernel<<<NR, 128>>>(hr[cr], pfc_W1, pfc_b1, pfc_W2, pfc_b2, out);
}

// round 5
// speedup vs baseline: 1.8822x; 1.2224x over previous
#include <cuda_runtime.h>
#include <cuda_bf16.h>
#include <mma.h>
#include <math.h>
#include <stdint.h>

using namespace nvcuda;

// ---------------- problem dims ----------------
#define HDIM 256
#define GDIM 768           // 3*H
#define EDIM 200
#define NW 4096            // B*R*S word sequences
#define TWSTEPS 32
#define NS 256             // B*R
#define TSSTEPS 16
#define NR 16              // B
#define TRSTEPS 16
#define MW (NW * TWSTEPS)  // 131072 word-gx rows
#define KPAD 256           // padded K for word gx (EDIM=200 -> 256)

typedef unsigned long long ull;
typedef __nv_bfloat16 bf16;

// ---------------- scratch (static device globals; no allocs allowed) --------
__device__ float g_GXw[(size_t)MW * GDIM];             // 402 MB word input gates
__device__ float g_GXs[(size_t)NS * TSSTEPS * GDIM];
__device__ float g_GXr[(size_t)NR * TRSTEPS * GDIM];
__device__ float g_GH [(size_t)NW * GDIM];             // recurrent gates scratch
__device__ float g_HwA[NW * HDIM], g_HwB[NW * HDIM];
__device__ float g_HsA[NS * HDIM], g_HsB[NS * HDIM];
__device__ float g_HrA[NR * HDIM], g_HrB[NR * HDIM];
// split-precision bf16 buffers
__device__ __align__(16) bf16 g_Xhi[(size_t)MW * KPAD];
__device__ __align__(16) bf16 g_Xlo[(size_t)MW * KPAD];
__device__ __align__(16) bf16 g_WihHi[GDIM * KPAD], g_WihLo[GDIM * KPAD];
__device__ __align__(16) bf16 g_WhhHi[GDIM * HDIM], g_WhhLo[GDIM * HDIM];
__device__ __align__(16) bf16 g_WsHi[GDIM * HDIM],  g_WsLo[GDIM * HDIM];
__device__ __align__(16) bf16 g_SHiA[NW * HDIM], g_SHiB[NW * HDIM];
__device__ __align__(16) bf16 g_SLoA[NW * HDIM], g_SLoB[NW * HDIM];

// ---------------- small helpers ----------------
__device__ __forceinline__ float sigmoid_f(float x) { return 1.f / (1.f + expf(-x)); }
__device__ __forceinline__ ull pack2(float lo, float hi) {
    ull r; asm("mov.b64 %0, {%1, %2};" : "=l"(r) : "f"(lo), "f"(hi)); return r;
}
__device__ __forceinline__ ull dup2(float v) { return pack2(v, v); }
__device__ __forceinline__ void ffma2(ull& d, ull a, ull b) {
    asm("fma.rn.f32x2 %0, %1, %2, %3;" : "=l"(d) : "l"(a), "l"(b), "l"(d));
}
__device__ __forceinline__ float2 unpack2(ull v) {
    float2 f; asm("mov.b64 {%0, %1}, %2;" : "=f"(f.x), "=f"(f.y) : "l"(v)); return f;
}

// ---------------- split / gather prep kernels ----------------
__global__ void split_mat_kernel(const float* __restrict__ src, bf16* __restrict__ hi,
                                 bf16* __restrict__ lo, int rows, int cs, int cd)
{
    int i = blockIdx.x * blockDim.x + threadIdx.x;
    if (i >= rows * cd) return;
    int r = i / cd, c = i - r * cd;
    float v = (c < cs) ? src[(size_t)r * cs + c] : 0.f;
    bf16 h = __float2bfloat16(v);
    hi[i] = h;
    lo[i] = __float2bfloat16(v - __bfloat162float(h));
}

__global__ void gather_split_kernel(const int* __restrict__ idx, const float* __restrict__ emb,
                                    bf16* __restrict__ hi, bf16* __restrict__ lo)
{
    size_t i = (size_t)blockIdx.x * blockDim.x + threadIdx.x;
    if (i >= (size_t)MW * KPAD) return;
    int row = (int)(i >> 8);
    int c = (int)(i & 255);
    float v = (c < EDIM) ? emb[(size_t)idx[row] * EDIM + c] : 0.f;
    bf16 h = __float2bfloat16(v);
    hi[i] = h;
    lo[i] = __float2bfloat16(v - __bfloat162float(h));
}

// ---------------- wmma bf16 split GEMM: C[M,N] = A @ W^T + bias -------------
// A[M,K] hi/lo, W[N,K] hi/lo row-major. CTA tile 128x128, 8 warps of 32x64.
// K multiple of 16, M multiple of 128, N multiple of 128.
#define LDT 24   // padded smem tile row (bf16 elems), 48B = multiple of 16B

__global__ __launch_bounds__(256, 1)
void gemm_wmma(const bf16* __restrict__ Ahi, const bf16* __restrict__ Alo,
               const bf16* __restrict__ Whi, const bf16* __restrict__ Wlo,
               const float* __restrict__ bias, float* __restrict__ C,
               int K, int N)
{
    extern __shared__ char sm[];
    bf16 (*sAh)[LDT] = reinterpret_cast<bf16(*)[LDT]>(sm);
    bf16 (*sAl)[LDT] = reinterpret_cast<bf16(*)[LDT]>(sm + 6144);
    bf16 (*sBh)[LDT] = reinterpret_cast<bf16(*)[LDT]>(sm + 12288);
    bf16 (*sBl)[LDT] = reinterpret_cast<bf16(*)[LDT]>(sm + 18432);
    float* scratch = reinterpret_cast<float*>(sm);   // 128x128 fp32, used after loop

    const int tid = threadIdx.x;
    const int wid = tid >> 5;
    const int m0 = blockIdx.y * 128, n0 = blockIdx.x * 128;
    const int wm = wid & 3;        // warp row tile: 32 rows
    const int wn = wid >> 2;       // warp col tile: 64 cols

    const int lr = tid >> 1;            // load row 0..127
    const int lk = (tid & 1) * 8;       // k offset (8 bf16 = 16B)

    const bf16* Ah = Ahi + (size_t)(m0 + lr) * K + lk;
    const bf16* Al = Alo + (size_t)(m0 + lr) * K + lk;
    const bf16* Bh = Whi + (size_t)(n0 + lr) * K + lk;
    const bf16* Bl = Wlo + (size_t)(n0 + lr) * K + lk;

    wmma::fragment<wmma::accumulator, 16, 16, 16, float> cf[2][4];
#pragma unroll
    for (int i = 0; i < 2; i++)
#pragma unroll
        for (int j = 0; j < 4; j++) wmma::fill_fragment(cf[i][j], 0.0f);

    uint4 va_h = *reinterpret_cast<const uint4*>(Ah);
    uint4 va_l = *reinterpret_cast<const uint4*>(Al);
    uint4 vb_h = *reinterpret_cast<const uint4*>(Bh);
    uint4 vb_l = *reinterpret_cast<const uint4*>(Bl);

    for (int kk = 0; kk < K; kk += 16) {
        *reinterpret_cast<uint4*>(&sAh[lr][lk]) = va_h;
        *reinterpret_cast<uint4*>(&sAl[lr][lk]) = va_l;
        *reinterpret_cast<uint4*>(&sBh[lr][lk]) = vb_h;
        *reinterpret_cast<uint4*>(&sBl[lr][lk]) = vb_l;
        __syncthreads();

        if (kk + 16 < K) {
            va_h = *reinterpret_cast<const uint4*>(Ah + kk + 16);
            va_l = *reinterpret_cast<const uint4*>(Al + kk + 16);
            vb_h = *reinterpret_cast<const uint4*>(Bh + kk + 16);
            vb_l = *reinterpret_cast<const uint4*>(Bl + kk + 16);
        }

        wmma::fragment<wmma::matrix_a, 16, 16, 16, bf16, wmma::row_major> ah[2], al[2];
        wmma::fragment<wmma::matrix_b, 16, 16, 16, bf16, wmma::col_major> bh[4], bl[4];
#pragma unroll
        for (int i = 0; i < 2; i++) {
            wmma::load_matrix_sync(ah[i], &sAh[wm * 32 + i * 16][0], LDT);
            wmma::load_matrix_sync(al[i], &sAl[wm * 32 + i * 16][0], LDT);
        }
#pragma unroll
        for (int j = 0; j < 4; j++) {
            wmma::load_matrix_sync(bh[j], &sBh[wn * 64 + j * 16][0], LDT);
            wmma::load_matrix_sync(bl[j], &sBl[wn * 64 + j * 16][0], LDT);
        }
#pragma unroll
        for (int i = 0; i < 2; i++)
#pragma unroll
            for (int j = 0; j < 4; j++) {
                wmma::mma_sync(cf[i][j], ah[i], bh[j], cf[i][j]);
                wmma::mma_sync(cf[i][j], ah[i], bl[j], cf[i][j]);
                wmma::mma_sync(cf[i][j], al[i], bh[j], cf[i][j]);
            }
        __syncthreads();
    }

    // epilogue: frags -> smem scratch -> +bias -> gmem
#pragma unroll
    for (int i = 0; i < 2; i++)
#pragma unroll
        for (int j = 0; j < 4; j++)
            wmma::store_matrix_sync(&scratch[(wm * 32 + i * 16) * 128 + wn * 64 + j * 16],
                                    cf[i][j], 128, wmma::mem_row_major);
    __syncthreads();

#pragma unroll
    for (int it = 0; it < 16; it++) {
        int idx4 = tid + it * 256;       // 4096 float4 = 128x128
        int r = idx4 >> 5;
        int c4 = (idx4 & 31) * 4;
        float4 v = *reinterpret_cast<const float4*>(&scratch[r * 128 + c4]);
        float4 b = *reinterpret_cast<const float4*>(&bias[n0 + c4]);
        v.x += b.x; v.y += b.y; v.z += b.z; v.w += b.w;
        *reinterpret_cast<float4*>(&C[(size_t)(m0 + r) * N + n0 + c4]) = v;
    }
}

// ---------------- GRU elementwise update + split ----------------
__global__ void gru_update_split(const float* __restrict__ gx, const float* __restrict__ gh,
                                 const float* __restrict__ hin, float* __restrict__ hout,
                                 bf16* __restrict__ hi, bf16* __restrict__ lo,
                                 int Mseq, int T, int t)
{
    int i = blockIdx.x * blockDim.x + threadIdx.x;
    if (i >= Mseq * HDIM) return;
    int seq = i >> 8, j = i & 255;
    const float* gxp = gx + ((size_t)seq * T + t) * GDIM;
    const float* ghp = gh + (size_t)seq * GDIM;
    float r = sigmoid_f(gxp[j] + ghp[j]);
    float z = sigmoid_f(gxp[j + HDIM] + ghp[j + HDIM]);
    float n = tanhf(gxp[j + 2 * HDIM] + r * ghp[j + 2 * HDIM]);
    float h = (1.f - z) * n + z * hin[i];
    hout[i] = h;
    bf16 hb = __float2bfloat16(h);
    hi[i] = hb;
    lo[i] = __float2bfloat16(h - __bfloat162float(hb));
}

// ---------------- t=0 GRU steps ----------------
__global__ void gru_init_split(const float* __restrict__ gx, const float* __restrict__ bhh,
                               float* __restrict__ hout, bf16* __restrict__ hi,
                               bf16* __restrict__ lo, int Mseq, int T)
{
    int i = blockIdx.x * blockDim.x + threadIdx.x;
    if (i >= Mseq * HDIM) return;
    int seq = i >> 8, j = i & 255;
    const float* g = gx + (size_t)seq * T * GDIM;
    float r = sigmoid_f(g[j] + bhh[j]);
    float z = sigmoid_f(g[j + HDIM] + bhh[j + HDIM]);
    float n = tanhf(g[j + 2 * HDIM] + r * bhh[j + 2 * HDIM]);
    float h = (1.f - z) * n;
    hout[i] = h;
    bf16 hb = __float2bfloat16(h);
    hi[i] = hb;
    lo[i] = __float2bfloat16(h - __bfloat162float(hb));
}

__global__ void gru_init_plain(const float* __restrict__ gx, const float* __restrict__ bhh,
                               float* __restrict__ hout, int Mseq, int T)
{
    int i = blockIdx.x * blockDim.x + threadIdx.x;
    if (i >= Mseq * HDIM) return;
    int seq = i >> 8, j = i & 255;
    const float* g = gx + (size_t)seq * T * GDIM;
    float r = sigmoid_f(g[j] + bhh[j]);
    float z = sigmoid_f(g[j + HDIM] + bhh[j + HDIM]);
    float n = tanhf(g[j + 2 * HDIM] + r * bhh[j + 2 * HDIM]);
    hout[i] = (1.f - z) * n;
}

// ---------------- fp32 SGEMM (review gx) ----------------
#define BM 128
#define BN 128
#define BK 8
__global__ __launch_bounds__(256, 2)
void sgemm_f32x2(const float* __restrict__ A, const float* __restrict__ W,
                 const float* __restrict__ bias, float* __restrict__ C,
                 int M, int K, int N)
{
    __shared__ float As[2][BK][BM];
    __shared__ float Bs[2][BK][BN];
    const int tid = threadIdx.x;
    const int m0 = blockIdx.y * BM;
    const int n0 = blockIdx.x * BN;
    const int a_m = tid & 127, a_kq = tid >> 7;
    const int b_n = tid >> 1,  b_kq = tid & 1;
    const bool a_valid = (m0 + a_m) < M;
    const float* Arow = A + (size_t)(a_valid ? (m0 + a_m) : 0) * K;
    const float* Brow = W + (size_t)(n0 + b_n) * K;
    const int tx = tid & 15, ty = tid >> 4;

    ull acc2[8][4];
#pragma unroll
    for (int i = 0; i < 8; i++)
#pragma unroll
        for (int j = 0; j < 4; j++) acc2[i][j] = 0ull;

    float4 av = make_float4(0.f, 0.f, 0.f, 0.f);
    if (a_valid) av = *reinterpret_cast<const float4*>(Arow + a_kq * 4);
    float4 bv = *reinterpret_cast<const float4*>(Brow + b_kq * 4);
    As[0][a_kq * 4 + 0][a_m] = av.x;  As[0][a_kq * 4 + 1][a_m] = av.y;
    As[0][a_kq * 4 + 2][a_m] = av.z;  As[0][a_kq * 4 + 3][a_m] = av.w;
    Bs[0][b_kq * 4 + 0][b_n] = bv.x;  Bs[0][b_kq * 4 + 1][b_n] = bv.y;
    Bs[0][b_kq * 4 + 2][b_n] = bv.z;  Bs[0][b_kq * 4 + 3][b_n] = bv.w;
    __syncthreads();

    int buf = 0;
    for (int kk = 0; kk < K; kk += BK) {
        const bool has_next = (kk + BK) < K;
        if (has_next) {
            if (a_valid) av = *reinterpret_cast<const float4*>(Arow + kk + BK + a_kq * 4);
            bv = *reinterpret_cast<const float4*>(Brow + kk + BK + b_kq * 4);
        }
#pragma unroll
        for (int k = 0; k < BK; k++) {
            float4 a0 = *reinterpret_cast<const float4*>(&As[buf][k][ty * 8]);
            float4 a1 = *reinterpret_cast<const float4*>(&As[buf][k][ty * 8 + 4]);
            ulonglong2 bq0 = *reinterpret_cast<const ulonglong2*>(&Bs[buf][k][tx * 8]);
            ulonglong2 bq1 = *reinterpret_cast<const ulonglong2*>(&Bs[buf][k][tx * 8 + 4]);
            ull bp[4] = {bq0.x, bq0.y, bq1.x, bq1.y};
            float a[8] = {a0.x, a0.y, a0.z, a0.w, a1.x, a1.y, a1.z, a1.w};
#pragma unroll
            for (int i = 0; i < 8; i++) {
                ull ad = dup2(a[i]);
#pragma unroll
                for (int j = 0; j < 4; j++) ffma2(acc2[i][j], ad, bp[j]);
            }
        }
        if (has_next) {
            int nb = buf ^ 1;
            As[nb][a_kq * 4 + 0][a_m] = av.x;  As[nb][a_kq * 4 + 1][a_m] = av.y;
            As[nb][a_kq * 4 + 2][a_m] = av.z;  As[nb][a_kq * 4 + 3][a_m] = av.w;
            Bs[nb][b_kq * 4 + 0][b_n] = bv.x;  Bs[nb][b_kq * 4 + 1][b_n] = bv.y;
            Bs[nb][b_kq * 4 + 2][b_n] = bv.z;  Bs[nb][b_kq * 4 + 3][b_n] = bv.w;
            __syncthreads();
            buf = nb;
        }
    }
#pragma unroll
    for (int i = 0; i < 8; i++) {
        int row = m0 + ty * 8 + i;
        if (row >= M) continue;
#pragma unroll
        for (int j = 0; j < 4; j++) {
            int col = n0 + tx * 8 + j * 2;
            float2 p = unpack2(acc2[i][j]);
            float2 bb = *reinterpret_cast<const float2*>(bias + col);
            float2 o; o.x = p.x + bb.x; o.y = p.y + bb.y;
            *reinterpret_cast<float2*>(C + (size_t)row * N + col) = o;
        }
    }
}

// ---------------- small-M GRU step: 32 rows x 32 h-cols / CTA ----------------
#define SBK 16
__global__ __launch_bounds__(256)
void gru_step_small(const float* __restrict__ hin, const float* __restrict__ Whh,
                    const float* __restrict__ bhh, const float* __restrict__ gx,
                    int T, int t, float* __restrict__ hout, int M)
{
    __shared__ float As[2][SBK][32];
    __shared__ float Bs[2][3][SBK][32];
    const int tid = threadIdx.x;
    const int n0 = blockIdx.x * 32;
    const int m0 = blockIdx.y * 32;
    const int tx = tid & 7, ty = tid >> 3;
    const int a_m = tid & 31, a_kq = tid >> 5;
    const bool a_valid = (m0 + a_m) < M;
    const float* Arow = hin + (size_t)(a_valid ? (m0 + a_m) : 0) * HDIM;
    const int r1 = tid >> 2, kq1 = tid & 3;
    const int g1 = r1 >> 5, c1 = r1 & 31;
    const int r2 = (tid + 256) >> 2;
    const int g2 = r2 >> 5, c2 = r2 & 31;
    const float* Bp1 = Whh + ((size_t)(g1 * HDIM + n0 + c1)) * HDIM + kq1 * 4;
    const float* Bp2 = Whh + ((size_t)(g2 * HDIM + n0 + c2)) * HDIM + kq1 * 4;

    ull acc[3][2];
#pragma unroll
    for (int g = 0; g < 3; g++) { acc[g][0] = 0ull; acc[g][1] = 0ull; }

    float2 av = make_float2(0.f, 0.f);
    if (a_valid) av = *reinterpret_cast<const float2*>(Arow + a_kq * 2);
    float4 bv1 = *reinterpret_cast<const float4*>(Bp1);
    float4 bv2 = make_float4(0.f, 0.f, 0.f, 0.f);
    if (tid < 128) bv2 = *reinterpret_cast<const float4*>(Bp2);
    As[0][a_kq * 2 + 0][a_m] = av.x;  As[0][a_kq * 2 + 1][a_m] = av.y;
    Bs[0][g1][kq1 * 4 + 0][c1] = bv1.x;  Bs[0][g1][kq1 * 4 + 1][c1] = bv1.y;
    Bs[0][g1][kq1 * 4 + 2][c1] = bv1.z;  Bs[0][g1][kq1 * 4 + 3][c1] = bv1.w;
    if (tid < 128) {
        Bs[0][g2][kq1 * 4 + 0][c2] = bv2.x;  Bs[0][g2][kq1 * 4 + 1][c2] = bv2.y;
        Bs[0][g2][kq1 * 4 + 2][c2] = bv2.z;  Bs[0][g2][kq1 * 4 + 3][c2] = bv2.w;
    }
    __syncthreads();

    int buf = 0;
    for (int kk = 0; kk < HDIM; kk += SBK) {
        const bool has_next = (kk + SBK) < HDIM;
        if (has_next) {
            if (a_valid) av = *reinterpret_cast<const float2*>(Arow + kk + SBK + a_kq * 2);
            bv1 = *reinterpret_cast<const float4*>(Bp1 + kk + SBK);
            if (tid < 128) bv2 = *reinterpret_cast<const float4*>(Bp2 + kk + SBK);
        }
#pragma unroll
        for (int k = 0; k < SBK; k++) {
            ull ad = dup2(As[buf][k][ty]);
#pragma unroll
            for (int g = 0; g < 3; g++) {
                ulonglong2 bq = *reinterpret_cast<const ulonglong2*>(&Bs[buf][g][k][tx * 4]);
                ffma2(acc[g][0], ad, bq.x);
                ffma2(acc[g][1], ad, bq.y);
            }
        }
        if (has_next) {
            int nb = buf ^ 1;
            As[nb][a_kq * 2 + 0][a_m] = av.x;  As[nb][a_kq * 2 + 1][a_m] = av.y;
            Bs[nb][g1][kq1 * 4 + 0][c1] = bv1.x;  Bs[nb][g1][kq1 * 4 + 1][c1] = bv1.y;
            Bs[nb][g1][kq1 * 4 + 2][c1] = bv1.z;  Bs[nb][g1][kq1 * 4 + 3][c1] = bv1.w;
            if (tid < 128) {
                Bs[nb][g2][kq1 * 4 + 0][c2] = bv2.x;  Bs[nb][g2][kq1 * 4 + 1][c2] = bv2.y;
                Bs[nb][g2][kq1 * 4 + 2][c2] = bv2.z;  Bs[nb][g2][kq1 * 4 + 3][c2] = bv2.w;
            }
            __syncthreads();
            buf = nb;
        }
    }

    const int row = m0 + ty;
    if (row >= M) return;
    const int jb = n0 + tx * 4;
    const float* gxp = gx + ((size_t)row * T + t) * GDIM;
    const float* hp  = hin + (size_t)row * HDIM;
    float*       op  = hout + (size_t)row * HDIM;
#pragma unroll
    for (int p = 0; p < 2; p++) {
        int j = jb + p * 2;
        float2 br = *reinterpret_cast<const float2*>(bhh + j);
        float2 bz = *reinterpret_cast<const float2*>(bhh + HDIM + j);
        float2 bn = *reinterpret_cast<const float2*>(bhh + 2 * HDIM + j);
        float2 ar = unpack2(acc[0][p]);
        float2 az = unpack2(acc[1][p]);
        float2 an = unpack2(acc[2][p]);
        float2 xr = *reinterpret_cast<const float2*>(gxp + j);
        float2 xz = *reinterpret_cast<const float2*>(gxp + HDIM + j);
        float2 xn = *reinterpret_cast<const float2*>(gxp + 2 * HDIM + j);
        float2 h  = *reinterpret_cast<const float2*>(hp + j);
        float r0 = sigmoid_f(xr.x + ar.x + br.x);
        float r1v = sigmoid_f(xr.y + ar.y + br.y);
        float z0 = sigmoid_f(xz.x + az.x + bz.x);
        float z1 = sigmoid_f(xz.y + az.y + bz.y);
        float n0v = tanhf(xn.x + r0 * (an.x + bn.x));
        float n1v = tanhf(xn.y + r1v * (an.y + bn.y));
        float2 o;
        o.x = (1.f - z0) * n0v + z0 * h.x;
        o.y = (1.f - z1) * n1v + z1 * h.y;
        *reinterpret_cast<float2*>(op + j) = o;
    }
}

// ---------------- MLP ----------------
__global__ __launch_bounds__(128)
void mlp_kernel(const float* __restrict__ X,
                const float* __restrict__ W1, const float* __restrict__ b1,
                const float* __restrict__ W2, const float* __restrict__ b2,
                float* __restrict__ out)
{
    const int row = blockIdx.x;
    const int i = threadIdx.x;
    __shared__ float xs[HDIM];
    __shared__ float red[4];
    xs[i]       = X[(size_t)row * HDIM + i];
    xs[i + 128] = X[(size_t)row * HDIM + i + 128];
    __syncthreads();
    const float* w = W1 + (size_t)i * HDIM;
    float acc = b1[i];
#pragma unroll 8
    for (int k = 0; k < HDIM; k += 4) {
        float4 wv = *reinterpret_cast<const float4*>(w + k);
        acc = fmaf(wv.x, xs[k], acc);
        acc = fmaf(wv.y, xs[k + 1], acc);
        acc = fmaf(wv.z, xs[k + 2], acc);
        acc = fmaf(wv.w, xs[k + 3], acc);
    }
    const float scale = 1.0507009873554805f;
    const float alpha = 1.6732632423543772f;
    float s = scale * (acc > 0.f ? acc : alpha * (expf(acc) - 1.f));
    float v = s * W2[i];
#pragma unroll
    for (int off = 16; off > 0; off >>= 1)
        v += __shfl_down_sync(0xffffffffu, v, off);
    if ((i & 31) == 0) red[i >> 5] = v;
    __syncthreads();
    if (i == 0) out[row] = red[0] + red[1] + red[2] + red[3] + b2[0];
}

// ---------------- host orchestration ----------------
extern "C" void kernel_launch(void* const* d_in, const int* in_sizes, int n_in,
                              void* d_out, int out_size)
{
    (void)in_sizes; (void)n_in; (void)out_size;

    const int*   idx    = (const int*)  d_in[0];
    const float* emb    = (const float*)d_in[1];
    const float* w_Wih  = (const float*)d_in[2];
    const float* w_Whh  = (const float*)d_in[3];
    const float* w_bih  = (const float*)d_in[4];
    const float* w_bhh  = (const float*)d_in[5];
    const float* s_Wih  = (const float*)d_in[6];
    const float* s_Whh  = (const float*)d_in[7];
    const float* s_bih  = (const float*)d_in[8];
    const float* s_bhh  = (const float*)d_in[9];
    const float* r_Wih  = (const float*)d_in[10];
    const float* r_Whh  = (const float*)d_in[11];
    const float* r_bih  = (const float*)d_in[12];
    const float* r_bhh  = (const float*)d_in[13];
    const float* rfc_W1 = (const float*)d_in[14];
    const float* rfc_b1 = (const float*)d_in[15];
    const float* rfc_W2 = (const float*)d_in[16];
    const float* rfc_b2 = (const float*)d_in[17];
    const float* pfc_W1 = (const float*)d_in[18];
    const float* pfc_b1 = (const float*)d_in[19];
    const float* pfc_W2 = (const float*)d_in[20];
    const float* pfc_b2 = (const float*)d_in[21];
    float* out = (float*)d_out;

    float *GXw, *GXs, *GXr, *GH, *HwA, *HwB, *HsA, *HsB, *HrA, *HrB;
    bf16 *Xhi, *Xlo, *WihHi, *WihLo, *WhhHi, *WhhLo, *WsHi, *WsLo;
    bf16 *SHiA, *SHiB, *SLoA, *SLoB;
    cudaGetSymbolAddress((void**)&GXw, g_GXw);
    cudaGetSymbolAddress((void**)&GXs, g_GXs);
    cudaGetSymbolAddress((void**)&GXr, g_GXr);
    cudaGetSymbolAddress((void**)&GH,  g_GH);
    cudaGetSymbolAddress((void**)&HwA, g_HwA);
    cudaGetSymbolAddress((void**)&HwB, g_HwB);
    cudaGetSymbolAddress((void**)&HsA, g_HsA);
    cudaGetSymbolAddress((void**)&HsB, g_HsB);
    cudaGetSymbolAddress((void**)&HrA, g_HrA);
    cudaGetSymbolAddress((void**)&HrB, g_HrB);
    cudaGetSymbolAddress((void**)&Xhi, g_Xhi);
    cudaGetSymbolAddress((void**)&Xlo, g_Xlo);
    cudaGetSymbolAddress((void**)&WihHi, g_WihHi);
    cudaGetSymbolAddress((void**)&WihLo, g_WihLo);
    cudaGetSymbolAddress((void**)&WhhHi, g_WhhHi);
    cudaGetSymbolAddress((void**)&WhhLo, g_WhhLo);
    cudaGetSymbolAddress((void**)&WsHi, g_WsHi);
    cudaGetSymbolAddress((void**)&WsLo, g_WsLo);
    cudaGetSymbolAddress((void**)&SHiA, g_SHiA);
    cudaGetSymbolAddress((void**)&SHiB, g_SHiB);
    cudaGetSymbolAddress((void**)&SLoA, g_SLoA);
    cudaGetSymbolAddress((void**)&SLoB, g_SLoB);

    const int SMEM_WMMA = 65536;   // max(tiles 24KB, scratch 64KB)
    cudaFuncSetAttribute(gemm_wmma, cudaFuncAttributeMaxDynamicSharedMemorySize, SMEM_WMMA);

    // ---- prep: split weights + gather/split embeddings ----
    split_mat_kernel<<<(GDIM * KPAD + 255) / 256, 256>>>(w_Wih, WihHi, WihLo, GDIM, EDIM, KPAD);
    split_mat_kernel<<<(GDIM * HDIM + 255) / 256, 256>>>(w_Whh, WhhHi, WhhLo, GDIM, HDIM, HDIM);
    split_mat_kernel<<<(GDIM * HDIM + 255) / 256, 256>>>(s_Wih, WsHi, WsLo, GDIM, HDIM, HDIM);
    gather_split_kernel<<<(int)(((size_t)MW * KPAD + 255) / 256), 256>>>(idx, emb, Xhi, Xlo);

    // ---- word level: gx = emb[idx] @ Wih^T + bih (wmma) ----
    gemm_wmma<<<dim3(GDIM / 128, MW / 128), 256, SMEM_WMMA>>>(Xhi, Xlo, WihHi, WihLo,
                                                              w_bih, GXw, KPAD, GDIM);

    float* hw[2] = {HwA, HwB};
    bf16*  shi[2] = {SHiA, SHiB};
    bf16*  slo[2] = {SLoA, SLoB};
    int cw = 0;
    gru_init_split<<<(NW * HDIM + 255) / 256, 256>>>(GXw, w_bhh, hw[0], shi[0], slo[0],
                                                     NW, TWSTEPS);
    for (int t = 1; t < TWSTEPS; t++) {
        gemm_wmma<<<dim3(GDIM / 128, NW / 128), 256, SMEM_WMMA>>>(
            shi[cw], slo[cw], WhhHi, WhhLo, w_bhh, GH, HDIM, GDIM);
        gru_update_split<<<(NW * HDIM + 255) / 256, 256>>>(
            GXw, GH, hw[cw], hw[1 - cw], shi[1 - cw], slo[1 - cw], NW, TWSTEPS, t);
        cw = 1 - cw;
    }
    const float* sent_h = hw[cw];
    (void)sent_h;

    // ---- sentence level: gx via wmma using final word-h splits ----
    gemm_wmma<<<dim3(GDIM / 128, (NS * TSSTEPS) / 128), 256, SMEM_WMMA>>>(
        shi[cw], slo[cw], WsHi, WsLo, s_bih, GXs, HDIM, GDIM);

    float* hs[2] = {HsA, HsB};
    int cs = 0;
    gru_init_plain<<<(NS * HDIM + 255) / 256, 256>>>(GXs, s_bhh, hs[0], NS, TSSTEPS);
    {
        dim3 grid(HDIM / 32, (NS + 31) / 32);
        for (int t = 1; t < TSSTEPS; t++) {
            gru_step_small<<<grid, 256>>>(hs[cs], s_Whh, s_bhh, GXs, TSSTEPS, t,
                                          hs[1 - cs], NS);
            cs = 1 - cs;
        }
    }
    const float* p_batch = hs[cs];

    // r_stars -> out[16 .. 272)
    mlp_kernel<<<NS, 128>>>(p_batch, rfc_W1, rfc_b1, rfc_W2, rfc_b2, out + NR);

    // ---- review level (fp32 path) ----
    {
        dim3 grid(GDIM / BN, (NR * TRSTEPS + BM - 1) / BM);
        sgemm_f32x2<<<grid, 256>>>(p_batch, r_Wih, r_bih, GXr, NR * TRSTEPS, HDIM, GDIM);
    }
    float* hr[2] = {HrA, HrB};
    int cr = 0;
    gru_init_plain<<<(NR * HDIM + 255) / 256, 256>>>(GXr, r_bhh, hr[0], NR, TRSTEPS);
    {
        dim3 grid(HDIM / 32, (NR + 31) / 32);
        for (int t = 1; t < TRSTEPS; t++) {
            gru_step_small<<<grid, 256>>>(hr[cr], r_Whh, r_bhh, GXr, TRSTEPS, t,
                                          hr[1 - cr], NR);
            cr = 1 - cr;
        }
    }
    // b_stars -> out[0 .. 16)
    mlp_kernel<<<NR, 128>>>(hr[cr], pfc_W1, pfc_b1, pfc_W2, pfc_b2, out);
}

// round 6
// speedup vs baseline: 1.9329x; 1.0269x over previous
#include <cuda_runtime.h>
#include <cuda_bf16.h>
#include <mma.h>
#include <math.h>
#include <stdint.h>

using namespace nvcuda;

// ---------------- problem dims ----------------
#define HDIM 256
#define GDIM 768           // 3*H
#define EDIM 200
#define NW 4096            // B*R*S word sequences
#define TWSTEPS 32
#define NS 256             // B*R
#define TSSTEPS 16
#define NR 16              // B
#define TRSTEPS 16
#define MW (NW * TWSTEPS)  // 131072 word-gx rows
#define KPAD 256           // padded K for word gx

typedef unsigned long long ull;
typedef __nv_bfloat16 bf16;

// ---------------- scratch (static device globals) ----------------
__device__ float g_GXw[(size_t)MW * GDIM];             // 402 MB word input gates
__device__ float g_GXs[(size_t)NS * TSSTEPS * GDIM];
__device__ float g_GXr[(size_t)NR * TRSTEPS * GDIM];
__device__ float g_HwA[NW * HDIM], g_HwB[NW * HDIM];
__device__ float g_HsA[NS * HDIM], g_HsB[NS * HDIM];
__device__ float g_HrA[NR * HDIM], g_HrB[NR * HDIM];
__device__ __align__(16) bf16 g_Xhi[(size_t)MW * KPAD];
__device__ __align__(16) bf16 g_Xlo[(size_t)MW * KPAD];
__device__ __align__(16) bf16 g_WihHi[GDIM * KPAD], g_WihLo[GDIM * KPAD];
__device__ __align__(16) bf16 g_WhhHi[GDIM * HDIM], g_WhhLo[GDIM * HDIM];
__device__ __align__(16) bf16 g_WsHi[GDIM * HDIM],  g_WsLo[GDIM * HDIM];
__device__ __align__(16) bf16 g_SHiA[NW * HDIM], g_SHiB[NW * HDIM];
__device__ __align__(16) bf16 g_SLoA[NW * HDIM], g_SLoB[NW * HDIM];

// ---------------- helpers ----------------
__device__ __forceinline__ float sigmoid_f(float x) { return 1.f / (1.f + expf(-x)); }
__device__ __forceinline__ ull pack2(float lo, float hi) {
    ull r; asm("mov.b64 %0, {%1, %2};" : "=l"(r) : "f"(lo), "f"(hi)); return r;
}
__device__ __forceinline__ ull dup2(float v) { return pack2(v, v); }
__device__ __forceinline__ void ffma2(ull& d, ull a, ull b) {
    asm("fma.rn.f32x2 %0, %1, %2, %3;" : "=l"(d) : "l"(a), "l"(b), "l"(d));
}
__device__ __forceinline__ float2 unpack2(ull v) {
    float2 f; asm("mov.b64 {%0, %1}, %2;" : "=f"(f.x), "=f"(f.y) : "l"(v)); return f;
}
__device__ __forceinline__ void cp16(uint32_t s, const void* g) {
    asm volatile("cp.async.cg.shared.global [%0], [%1], 16;" :: "r"(s), "l"(g));
}
#define CP_COMMIT() asm volatile("cp.async.commit_group;" ::: "memory")
#define CP_WAIT(n)  asm volatile("cp.async.wait_group %0;" :: "n"(n) : "memory")

// ---------------- split / gather prep ----------------
__global__ void split_mat_kernel(const float* __restrict__ src, bf16* __restrict__ hi,
                                 bf16* __restrict__ lo, int rows, int cs, int cd)
{
    int i = blockIdx.x * blockDim.x + threadIdx.x;
    if (i >= rows * cd) return;
    int r = i / cd, c = i - r * cd;
    float v = (c < cs) ? src[(size_t)r * cs + c] : 0.f;
    bf16 h = __float2bfloat16(v);
    hi[i] = h;
    lo[i] = __float2bfloat16(v - __bfloat162float(h));
}

// one float4 per thread; KPAD/4 = 64 chunks per row
__global__ void gather_split_kernel(const int* __restrict__ idx, const float* __restrict__ emb,
                                    bf16* __restrict__ hi, bf16* __restrict__ lo)
{
    size_t id = (size_t)blockIdx.x * blockDim.x + threadIdx.x;
    if (id >= (size_t)MW * 64) return;
    int row = (int)(id >> 6);
    int c4 = (int)(id & 63) * 4;
    float4 v = make_float4(0.f, 0.f, 0.f, 0.f);
    if (c4 < EDIM)
        v = *reinterpret_cast<const float4*>(emb + (size_t)idx[row] * EDIM + c4);
    float vv[4] = {v.x, v.y, v.z, v.w};
    bf16 hb[4], lb[4];
#pragma unroll
    for (int u = 0; u < 4; u++) {
        hb[u] = __float2bfloat16(vv[u]);
        lb[u] = __float2bfloat16(vv[u] - __bfloat162float(hb[u]));
    }
    size_t o = (size_t)row * KPAD + c4;
    *reinterpret_cast<ull*>(hi + o) = *reinterpret_cast<ull*>(hb);
    *reinterpret_cast<ull*>(lo + o) = *reinterpret_cast<ull*>(lb);
}

// ---------------- wmma split GEMM v2: cp.async, K-tile 32 -------------------
// C[M,N] = A@W^T + bias. CTA 128x128, 8 warps 32x64. M%128==0, N%128==0, K%32==0.
#define LDT2 48                      // smem row stride (bf16 elems), 96B
#define TBY (128 * LDT2 * 2)         // 12288B per matrix tile

__global__ __launch_bounds__(256, 1)
void gemm_wmma2(const bf16* __restrict__ Ahi, const bf16* __restrict__ Alo,
                const bf16* __restrict__ Whi, const bf16* __restrict__ Wlo,
                const float* __restrict__ bias, float* __restrict__ C,
                int K, int N)
{
    extern __shared__ __align__(128) char sm[];
    // layout: buf(0|1) x {Ah, Al, Bh, Bl}, each TBY bytes
    const uint32_t sbase = (uint32_t)__cvta_generic_to_shared(sm);
    float* scratch = reinterpret_cast<float*>(sm);

    const int tid = threadIdx.x;
    const int wid = tid >> 5;
    const int m0 = blockIdx.y * 128, n0 = blockIdx.x * 128;
    const int wm = wid & 3, wn = wid >> 2;

    const int lr = tid >> 1;            // 0..127
    const int lq = (tid & 1) * 16;      // elem offset 0 / 16

    const bf16* gA[2] = {Ahi + (size_t)(m0 + lr) * K + lq, Alo + (size_t)(m0 + lr) * K + lq};
    const bf16* gB[2] = {Whi + (size_t)(n0 + lr) * K + lq, Wlo + (size_t)(n0 + lr) * K + lq};
    const uint32_t srow = lr * LDT2 * 2 + lq * 2;   // byte offset within tile

    const int ntile = K / 32;

    wmma::fragment<wmma::accumulator, 16, 16, 16, float> cf[2][4];
#pragma unroll
    for (int i = 0; i < 2; i++)
#pragma unroll
        for (int j = 0; j < 4; j++) wmma::fill_fragment(cf[i][j], 0.0f);

    // issue loads for tile `it` into buffer `b`
    auto issue = [&](int it, int b) {
        const int kk = it * 32;
        uint32_t base = sbase + b * (4 * TBY);
#pragma unroll
        for (int s = 0; s < 2; s++) {
            cp16(base + s * TBY + srow,      gA[s] + kk);
            cp16(base + s * TBY + srow + 16, gA[s] + kk + 8);
            cp16(base + (2 + s) * TBY + srow,      gB[s] + kk);
            cp16(base + (2 + s) * TBY + srow + 16, gB[s] + kk + 8);
        }
    };

    issue(0, 0); CP_COMMIT();

    for (int it = 0; it < ntile; it++) {
        const int b = it & 1;
        if (it + 1 < ntile) { issue(it + 1, b ^ 1); CP_COMMIT(); CP_WAIT(1); }
        else                { CP_WAIT(0); }
        __syncthreads();

        const bf16* tAh = reinterpret_cast<const bf16*>(sm + b * (4 * TBY));
        const bf16* tAl = tAh + 128 * LDT2;
        const bf16* tBh = tAl + 128 * LDT2;
        const bf16* tBl = tBh + 128 * LDT2;

#pragma unroll
        for (int ks = 0; ks < 32; ks += 16) {
            wmma::fragment<wmma::matrix_a, 16, 16, 16, bf16, wmma::row_major> ah[2], al[2];
            wmma::fragment<wmma::matrix_b, 16, 16, 16, bf16, wmma::col_major> bh[4], bl[4];
#pragma unroll
            for (int i = 0; i < 2; i++) {
                wmma::load_matrix_sync(ah[i], tAh + (wm * 32 + i * 16) * LDT2 + ks, LDT2);
                wmma::load_matrix_sync(al[i], tAl + (wm * 32 + i * 16) * LDT2 + ks, LDT2);
            }
#pragma unroll
            for (int j = 0; j < 4; j++) {
                wmma::load_matrix_sync(bh[j], tBh + (wn * 64 + j * 16) * LDT2 + ks, LDT2);
                wmma::load_matrix_sync(bl[j], tBl + (wn * 64 + j * 16) * LDT2 + ks, LDT2);
            }
#pragma unroll
            for (int i = 0; i < 2; i++)
#pragma unroll
                for (int j = 0; j < 4; j++) {
                    wmma::mma_sync(cf[i][j], ah[i], bh[j], cf[i][j]);
                    wmma::mma_sync(cf[i][j], ah[i], bl[j], cf[i][j]);
                    wmma::mma_sync(cf[i][j], al[i], bh[j], cf[i][j]);
                }
        }
        __syncthreads();
    }

    // epilogue via smem scratch
#pragma unroll
    for (int i = 0; i < 2; i++)
#pragma unroll
        for (int j = 0; j < 4; j++)
            wmma::store_matrix_sync(&scratch[(wm * 32 + i * 16) * 128 + wn * 64 + j * 16],
                                    cf[i][j], 128, wmma::mem_row_major);
    __syncthreads();

#pragma unroll
    for (int itx = 0; itx < 16; itx++) {
        int idx4 = tid + itx * 256;
        int r = idx4 >> 5;
        int c4 = (idx4 & 31) * 4;
        float4 v = *reinterpret_cast<const float4*>(&scratch[r * 128 + c4]);
        float4 b = *reinterpret_cast<const float4*>(&bias[n0 + c4]);
        v.x += b.x; v.y += b.y; v.z += b.z; v.w += b.w;
        *reinterpret_cast<float4*>(&C[(size_t)(m0 + r) * N + n0 + c4]) = v;
    }
}

// ---------------- fused wmma GRU step --------------------------------------
// CTA: 128 rows x 64 h-cols x 3 gates (B tile = 192 weight rows). K = 256.
// grid = (HDIM/64 = 4, NW/128). 8 warps: wm=wid&3 (32 rows), wn=wid>>2 (96 cols).
#define GB_ROWS 192
#define ATBY (128 * LDT2 * 2)     // 12288
#define BTBY (GB_ROWS * LDT2 * 2) // 18432
#define GBUF (2 * ATBY + 2 * BTBY) // 61440 per buffer

__global__ __launch_bounds__(256, 1)
void gru_step_wmma(const float* __restrict__ hin,
                   const bf16* __restrict__ Hhi, const bf16* __restrict__ Hlo,
                   const bf16* __restrict__ Whi, const bf16* __restrict__ Wlo,
                   const float* __restrict__ bhh, const float* __restrict__ gx,
                   int T, int t, float* __restrict__ hout,
                   bf16* __restrict__ HhiOut, bf16* __restrict__ HloOut)
{
    extern __shared__ __align__(128) char sm[];
    const uint32_t sbase = (uint32_t)__cvta_generic_to_shared(sm);
    float* scratch = reinterpret_cast<float*>(sm);   // 128x192 fp32 after compute

    const int tid = threadIdx.x;
    const int wid = tid >> 5;
    const int n0 = blockIdx.x * 64;
    const int m0 = blockIdx.y * 128;
    const int wm = wid & 3, wn = wid >> 2;

    const int lr = tid >> 1;
    const int lq = (tid & 1) * 16;
    const bf16* gA[2] = {Hhi + (size_t)(m0 + lr) * HDIM + lq,
                         Hlo + (size_t)(m0 + lr) * HDIM + lq};
    const uint32_t arow = lr * LDT2 * 2 + lq * 2;

    auto issue = [&](int it, int b) {
        const int kk = it * 32;
        uint32_t base = sbase + b * GBUF;
#pragma unroll
        for (int s = 0; s < 2; s++) {
            cp16(base + s * ATBY + arow,      gA[s] + kk);
            cp16(base + s * ATBY + arow + 16, gA[s] + kk + 8);
        }
        // B: 192 rows x 2 half-rows = 384 tasks
        for (int task = tid; task < 384; task += 256) {
            int rt = task >> 1;
            int q = (task & 1) * 16;
            int gate = rt / 64, col = rt - gate * 64;
            size_t srcoff = (size_t)(gate * HDIM + n0 + col) * HDIM + kk + q;
            uint32_t soff = rt * LDT2 * 2 + q * 2;
            cp16(base + 2 * ATBY + soff,            Whi + srcoff);
            cp16(base + 2 * ATBY + soff + 16,       Whi + srcoff + 8);
            cp16(base + 2 * ATBY + BTBY + soff,     Wlo + srcoff);
            cp16(base + 2 * ATBY + BTBY + soff + 16, Wlo + srcoff + 8);
        }
    };

    wmma::fragment<wmma::accumulator, 16, 16, 16, float> cf[2][6];
#pragma unroll
    for (int i = 0; i < 2; i++)
#pragma unroll
        for (int j = 0; j < 6; j++) wmma::fill_fragment(cf[i][j], 0.0f);

    issue(0, 0); CP_COMMIT();

    const int ntile = HDIM / 32;   // 8
    for (int it = 0; it < ntile; it++) {
        const int b = it & 1;
        if (it + 1 < ntile) { issue(it + 1, b ^ 1); CP_COMMIT(); CP_WAIT(1); }
        else                { CP_WAIT(0); }
        __syncthreads();

        const bf16* tAh = reinterpret_cast<const bf16*>(sm + b * GBUF);
        const bf16* tAl = tAh + 128 * LDT2;
        const bf16* tBh = tAl + 128 * LDT2;
        const bf16* tBl = tBh + GB_ROWS * LDT2;

#pragma unroll
        for (int ks = 0; ks < 32; ks += 16) {
            wmma::fragment<wmma::matrix_a, 16, 16, 16, bf16, wmma::row_major> ah[2], al[2];
#pragma unroll
            for (int i = 0; i < 2; i++) {
                wmma::load_matrix_sync(ah[i], tAh + (wm * 32 + i * 16) * LDT2 + ks, LDT2);
                wmma::load_matrix_sync(al[i], tAl + (wm * 32 + i * 16) * LDT2 + ks, LDT2);
            }
#pragma unroll
            for (int j = 0; j < 6; j++) {
                wmma::fragment<wmma::matrix_b, 16, 16, 16, bf16, wmma::col_major> bh, bl;
                wmma::load_matrix_sync(bh, tBh + (wn * 96 + j * 16) * LDT2 + ks, LDT2);
                wmma::load_matrix_sync(bl, tBl + (wn * 96 + j * 16) * LDT2 + ks, LDT2);
#pragma unroll
                for (int i = 0; i < 2; i++) {
                    wmma::mma_sync(cf[i][j], ah[i], bh, cf[i][j]);
                    wmma::mma_sync(cf[i][j], ah[i], bl, cf[i][j]);
                    wmma::mma_sync(cf[i][j], al[i], bh, cf[i][j]);
                }
            }
        }
        __syncthreads();
    }

    // stash gates to scratch [128][192]
#pragma unroll
    for (int i = 0; i < 2; i++)
#pragma unroll
        for (int j = 0; j < 6; j++)
            wmma::store_matrix_sync(&scratch[(wm * 32 + i * 16) * 192 + wn * 96 + j * 16],
                                    cf[i][j], 192, wmma::mem_row_major);
    __syncthreads();

    // fused GRU epilogue: 128 rows x 64 cols, 4-wide chunks -> 2048 tasks
#pragma unroll
    for (int itx = 0; itx < 8; itx++) {
        int task = tid + itx * 256;
        int r = task >> 4;
        int c4 = (task & 15) * 4;
        const int row = m0 + r;
        const int j = n0 + c4;
        const float* srow2 = &scratch[r * 192];
        float gr[4], gz[4], gn[4];
        *reinterpret_cast<float4*>(gr) = *reinterpret_cast<const float4*>(srow2 + c4);
        *reinterpret_cast<float4*>(gz) = *reinterpret_cast<const float4*>(srow2 + 64 + c4);
        *reinterpret_cast<float4*>(gn) = *reinterpret_cast<const float4*>(srow2 + 128 + c4);
        float br[4], bz[4], bn[4], xr[4], xz[4], xn[4], hh[4];
        *reinterpret_cast<float4*>(br) = *reinterpret_cast<const float4*>(bhh + j);
        *reinterpret_cast<float4*>(bz) = *reinterpret_cast<const float4*>(bhh + HDIM + j);
        *reinterpret_cast<float4*>(bn) = *reinterpret_cast<const float4*>(bhh + 2 * HDIM + j);
        const float* gxp = gx + ((size_t)row * T + t) * GDIM;
        *reinterpret_cast<float4*>(xr) = *reinterpret_cast<const float4*>(gxp + j);
        *reinterpret_cast<float4*>(xz) = *reinterpret_cast<const float4*>(gxp + HDIM + j);
        *reinterpret_cast<float4*>(xn) = *reinterpret_cast<const float4*>(gxp + 2 * HDIM + j);
        *reinterpret_cast<float4*>(hh) = *reinterpret_cast<const float4*>(hin + (size_t)row * HDIM + j);
        float o[4];
        bf16 hb[4], lb[4];
#pragma unroll
        for (int u = 0; u < 4; u++) {
            float rr = sigmoid_f(xr[u] + gr[u] + br[u]);
            float zz = sigmoid_f(xz[u] + gz[u] + bz[u]);
            float nv = tanhf(xn[u] + rr * (gn[u] + bn[u]));
            float h = (1.f - zz) * nv + zz * hh[u];
            o[u] = h;
            hb[u] = __float2bfloat16(h);
            lb[u] = __float2bfloat16(h - __bfloat162float(hb[u]));
        }
        *reinterpret_cast<float4*>(hout + (size_t)row * HDIM + j) = *reinterpret_cast<float4*>(o);
        *reinterpret_cast<ull*>(HhiOut + (size_t)row * HDIM + j) = *reinterpret_cast<ull*>(hb);
        *reinterpret_cast<ull*>(HloOut + (size_t)row * HDIM + j) = *reinterpret_cast<ull*>(lb);
    }
}

// ---------------- t=0 GRU steps ----------------
__global__ void gru_init_split(const float* __restrict__ gx, const float* __restrict__ bhh,
                               float* __restrict__ hout, bf16* __restrict__ hi,
                               bf16* __restrict__ lo, int Mseq, int T)
{
    int i = blockIdx.x * blockDim.x + threadIdx.x;
    if (i >= Mseq * HDIM) return;
    int seq = i >> 8, j = i & 255;
    const float* g = gx + (size_t)seq * T * GDIM;
    float r = sigmoid_f(g[j] + bhh[j]);
    float z = sigmoid_f(g[j + HDIM] + bhh[j + HDIM]);
    float n = tanhf(g[j + 2 * HDIM] + r * bhh[j + 2 * HDIM]);
    float h = (1.f - z) * n;
    hout[i] = h;
    bf16 hb = __float2bfloat16(h);
    hi[i] = hb;
    lo[i] = __float2bfloat16(h - __bfloat162float(hb));
}

__global__ void gru_init_plain(const float* __restrict__ gx, const float* __restrict__ bhh,
                               float* __restrict__ hout, int Mseq, int T)
{
    int i = blockIdx.x * blockDim.x + threadIdx.x;
    if (i >= Mseq * HDIM) return;
    int seq = i >> 8, j = i & 255;
    const float* g = gx + (size_t)seq * T * GDIM;
    float r = sigmoid_f(g[j] + bhh[j]);
    float z = sigmoid_f(g[j + HDIM] + bhh[j + HDIM]);
    float n = tanhf(g[j + 2 * HDIM] + r * bhh[j + 2 * HDIM]);
    hout[i] = (1.f - z) * n;
}

// ---------------- fp32 SGEMM (review gx) ----------------
#define BM 128
#define BN 128
#define BK 8
__global__ __launch_bounds__(256, 2)
void sgemm_f32x2(const float* __restrict__ A, const float* __restrict__ W,
                 const float* __restrict__ bias, float* __restrict__ C,
                 int M, int K, int N)
{
    __shared__ float As[2][BK][BM];
    __shared__ float Bs[2][BK][BN];
    const int tid = threadIdx.x;
    const int m0 = blockIdx.y * BM;
    const int n0 = blockIdx.x * BN;
    const int a_m = tid & 127, a_kq = tid >> 7;
    const int b_n = tid >> 1,  b_kq = tid & 1;
    const bool a_valid = (m0 + a_m) < M;
    const float* Arow = A + (size_t)(a_valid ? (m0 + a_m) : 0) * K;
    const float* Brow = W + (size_t)(n0 + b_n) * K;
    const int tx = tid & 15, ty = tid >> 4;

    ull acc2[8][4];
#pragma unroll
    for (int i = 0; i < 8; i++)
#pragma unroll
        for (int j = 0; j < 4; j++) acc2[i][j] = 0ull;

    float4 av = make_float4(0.f, 0.f, 0.f, 0.f);
    if (a_valid) av = *reinterpret_cast<const float4*>(Arow + a_kq * 4);
    float4 bv = *reinterpret_cast<const float4*>(Brow + b_kq * 4);
    As[0][a_kq * 4 + 0][a_m] = av.x;  As[0][a_kq * 4 + 1][a_m] = av.y;
    As[0][a_kq * 4 + 2][a_m] = av.z;  As[0][a_kq * 4 + 3][a_m] = av.w;
    Bs[0][b_kq * 4 + 0][b_n] = bv.x;  Bs[0][b_kq * 4 + 1][b_n] = bv.y;
    Bs[0][b_kq * 4 + 2][b_n] = bv.z;  Bs[0][b_kq * 4 + 3][b_n] = bv.w;
    __syncthreads();

    int buf = 0;
    for (int kk = 0; kk < K; kk += BK) {
        const bool has_next = (kk + BK) < K;
        if (has_next) {
            if (a_valid) av = *reinterpret_cast<const float4*>(Arow + kk + BK + a_kq * 4);
            bv = *reinterpret_cast<const float4*>(Brow + kk + BK + b_kq * 4);
        }
#pragma unroll
        for (int k = 0; k < BK; k++) {
            float4 a0 = *reinterpret_cast<const float4*>(&As[buf][k][ty * 8]);
            float4 a1 = *reinterpret_cast<const float4*>(&As[buf][k][ty * 8 + 4]);
            ulonglong2 bq0 = *reinterpret_cast<const ulonglong2*>(&Bs[buf][k][tx * 8]);
            ulonglong2 bq1 = *reinterpret_cast<const ulonglong2*>(&Bs[buf][k][tx * 8 + 4]);
            ull bp[4] = {bq0.x, bq0.y, bq1.x, bq1.y};
            float a[8] = {a0.x, a0.y, a0.z, a0.w, a1.x, a1.y, a1.z, a1.w};
#pragma unroll
            for (int i = 0; i < 8; i++) {
                ull ad = dup2(a[i]);
#pragma unroll
                for (int j = 0; j < 4; j++) ffma2(acc2[i][j], ad, bp[j]);
            }
        }
        if (has_next) {
            int nb = buf ^ 1;
            As[nb][a_kq * 4 + 0][a_m] = av.x;  As[nb][a_kq * 4 + 1][a_m] = av.y;
            As[nb][a_kq * 4 + 2][a_m] = av.z;  As[nb][a_kq * 4 + 3][a_m] = av.w;
            Bs[nb][b_kq * 4 + 0][b_n] = bv.x;  Bs[nb][b_kq * 4 + 1][b_n] = bv.y;
            Bs[nb][b_kq * 4 + 2][b_n] = bv.z;  Bs[nb][b_kq * 4 + 3][b_n] = bv.w;
            __syncthreads();
            buf = nb;
        }
    }
#pragma unroll
    for (int i = 0; i < 8; i++) {
        int row = m0 + ty * 8 + i;
        if (row >= M) continue;
#pragma unroll
        for (int j = 0; j < 4; j++) {
            int col = n0 + tx * 8 + j * 2;
            float2 p = unpack2(acc2[i][j]);
            float2 bb = *reinterpret_cast<const float2*>(bias + col);
            float2 o; o.x = p.x + bb.x; o.y = p.y + bb.y;
            *reinterpret_cast<float2*>(C + (size_t)row * N + col) = o;
        }
    }
}

// ---------------- small-M GRU step: 32 rows x 32 h-cols / CTA ----------------
#define SBK 16
__global__ __launch_bounds__(256)
void gru_step_small(const float* __restrict__ hin, const float* __restrict__ Whh,
                    const float* __restrict__ bhh, const float* __restrict__ gx,
                    int T, int t, float* __restrict__ hout, int M)
{
    __shared__ float As[2][SBK][32];
    __shared__ float Bs[2][3][SBK][32];
    const int tid = threadIdx.x;
    const int n0 = blockIdx.x * 32;
    const int m0 = blockIdx.y * 32;
    const int tx = tid & 7, ty = tid >> 3;
    const int a_m = tid & 31, a_kq = tid >> 5;
    const bool a_valid = (m0 + a_m) < M;
    const float* Arow = hin + (size_t)(a_valid ? (m0 + a_m) : 0) * HDIM;
    const int r1 = tid >> 2, kq1 = tid & 3;
    const int g1 = r1 >> 5, c1 = r1 & 31;
    const int r2 = (tid + 256) >> 2;
    const int g2 = r2 >> 5, c2 = r2 & 31;
    const float* Bp1 = Whh + ((size_t)(g1 * HDIM + n0 + c1)) * HDIM + kq1 * 4;
    const float* Bp2 = Whh + ((size_t)(g2 * HDIM + n0 + c2)) * HDIM + kq1 * 4;

    ull acc[3][2];
#pragma unroll
    for (int g = 0; g < 3; g++) { acc[g][0] = 0ull; acc[g][1] = 0ull; }

    float2 av = make_float2(0.f, 0.f);
    if (a_valid) av = *reinterpret_cast<const float2*>(Arow + a_kq * 2);
    float4 bv1 = *reinterpret_cast<const float4*>(Bp1);
    float4 bv2 = make_float4(0.f, 0.f, 0.f, 0.f);
    if (tid < 128) bv2 = *reinterpret_cast<const float4*>(Bp2);
    As[0][a_kq * 2 + 0][a_m] = av.x;  As[0][a_kq * 2 + 1][a_m] = av.y;
    Bs[0][g1][kq1 * 4 + 0][c1] = bv1.x;  Bs[0][g1][kq1 * 4 + 1][c1] = bv1.y;
    Bs[0][g1][kq1 * 4 + 2][c1] = bv1.z;  Bs[0][g1][kq1 * 4 + 3][c1] = bv1.w;
    if (tid < 128) {
        Bs[0][g2][kq1 * 4 + 0][c2] = bv2.x;  Bs[0][g2][kq1 * 4 + 1][c2] = bv2.y;
        Bs[0][g2][kq1 * 4 + 2][c2] = bv2.z;  Bs[0][g2][kq1 * 4 + 3][c2] = bv2.w;
    }
    __syncthreads();

    int buf = 0;
    for (int kk = 0; kk < HDIM; kk += SBK) {
        const bool has_next = (kk + SBK) < HDIM;
        if (has_next) {
            if (a_valid) av = *reinterpret_cast<const float2*>(Arow + kk + SBK + a_kq * 2);
            bv1 = *reinterpret_cast<const float4*>(Bp1 + kk + SBK);
            if (tid < 128) bv2 = *reinterpret_cast<const float4*>(Bp2 + kk + SBK);
        }
#pragma unroll
        for (int k = 0; k < SBK; k++) {
            ull ad = dup2(As[buf][k][ty]);
#pragma unroll
            for (int g = 0; g < 3; g++) {
                ulonglong2 bq = *reinterpret_cast<const ulonglong2*>(&Bs[buf][g][k][tx * 4]);
                ffma2(acc[g][0], ad, bq.x);
                ffma2(acc[g][1], ad, bq.y);
            }
        }
        if (has_next) {
            int nb = buf ^ 1;
            As[nb][a_kq * 2 + 0][a_m] = av.x;  As[nb][a_kq * 2 + 1][a_m] = av.y;
            Bs[nb][g1][kq1 * 4 + 0][c1] = bv1.x;  Bs[nb][g1][kq1 * 4 + 1][c1] = bv1.y;
            Bs[nb][g1][kq1 * 4 + 2][c1] = bv1.z;  Bs[nb][g1][kq1 * 4 + 3][c1] = bv1.w;
            if (tid < 128) {
                Bs[nb][g2][kq1 * 4 + 0][c2] = bv2.x;  Bs[nb][g2][kq1 * 4 + 1][c2] = bv2.y;
                Bs[nb][g2][kq1 * 4 + 2][c2] = bv2.z;  Bs[nb][g2][kq1 * 4 + 3][c2] = bv2.w;
            }
            __syncthreads();
            buf = nb;
        }
    }

    const int row = m0 + ty;
    if (row >= M) return;
    const int jb = n0 + tx * 4;
    const float* gxp = gx + ((size_t)row * T + t) * GDIM;
    const float* hp  = hin + (size_t)row * HDIM;
    float*       op  = hout + (size_t)row * HDIM;
#pragma unroll
    for (int p = 0; p < 2; p++) {
        int j = jb + p * 2;
        float2 br = *reinterpret_cast<const float2*>(bhh + j);
        float2 bz = *reinterpret_cast<const float2*>(bhh + HDIM + j);
        float2 bn = *reinterpret_cast<const float2*>(bhh + 2 * HDIM + j);
        float2 ar = unpack2(acc[0][p]);
        float2 az = unpack2(acc[1][p]);
        float2 an = unpack2(acc[2][p]);
        float2 xr = *reinterpret_cast<const float2*>(gxp + j);
        float2 xz = *reinterpret_cast<const float2*>(gxp + HDIM + j);
        float2 xn = *reinterpret_cast<const float2*>(gxp + 2 * HDIM + j);
        float2 h  = *reinterpret_cast<const float2*>(hp + j);
        float r0 = sigmoid_f(xr.x + ar.x + br.x);
        float r1v = sigmoid_f(xr.y + ar.y + br.y);
        float z0 = sigmoid_f(xz.x + az.x + bz.x);
        float z1 = sigmoid_f(xz.y + az.y + bz.y);
        float n0v = tanhf(xn.x + r0 * (an.x + bn.x));
        float n1v = tanhf(xn.y + r1v * (an.y + bn.y));
        float2 o;
        o.x = (1.f - z0) * n0v + z0 * h.x;
        o.y = (1.f - z1) * n1v + z1 * h.y;
        *reinterpret_cast<float2*>(op + j) = o;
    }
}

// ---------------- MLP ----------------
__global__ __launch_bounds__(128)
void mlp_kernel(const float* __restrict__ X,
                const float* __restrict__ W1, const float* __restrict__ b1,
                const float* __restrict__ W2, const float* __restrict__ b2,
                float* __restrict__ out)
{
    const int row = blockIdx.x;
    const int i = threadIdx.x;
    __shared__ float xs[HDIM];
    __shared__ float red[4];
    xs[i]       = X[(size_t)row * HDIM + i];
    xs[i + 128] = X[(size_t)row * HDIM + i + 128];
    __syncthreads();
    const float* w = W1 + (size_t)i * HDIM;
    float acc = b1[i];
#pragma unroll 8
    for (int k = 0; k < HDIM; k += 4) {
        float4 wv = *reinterpret_cast<const float4*>(w + k);
        acc = fmaf(wv.x, xs[k], acc);
        acc = fmaf(wv.y, xs[k + 1], acc);
        acc = fmaf(wv.z, xs[k + 2], acc);
        acc = fmaf(wv.w, xs[k + 3], acc);
    }
    const float scale = 1.0507009873554805f;
    const float alpha = 1.6732632423543772f;
    float s = scale * (acc > 0.f ? acc : alpha * (expf(acc) - 1.f));
    float v = s * W2[i];
#pragma unroll
    for (int off = 16; off > 0; off >>= 1)
        v += __shfl_down_sync(0xffffffffu, v, off);
    if ((i & 31) == 0) red[i >> 5] = v;
    __syncthreads();
    if (i == 0) out[row] = red[0] + red[1] + red[2] + red[3] + b2[0];
}

// ---------------- host orchestration ----------------
extern "C" void kernel_launch(void* const* d_in, const int* in_sizes, int n_in,
                              void* d_out, int out_size)
{
    (void)in_sizes; (void)n_in; (void)out_size;

    const int*   idx    = (const int*)  d_in[0];
    const float* emb    = (const float*)d_in[1];
    const float* w_Wih  = (const float*)d_in[2];
    const float* w_Whh  = (const float*)d_in[3];
    const float* w_bih  = (const float*)d_in[4];
    const float* w_bhh  = (const float*)d_in[5];
    const float* s_Wih  = (const float*)d_in[6];
    const float* s_Whh  = (const float*)d_in[7];
    const float* s_bih  = (const float*)d_in[8];
    const float* s_bhh  = (const float*)d_in[9];
    const float* r_Wih  = (const float*)d_in[10];
    const float* r_Whh  = (const float*)d_in[11];
    const float* r_bih  = (const float*)d_in[12];
    const float* r_bhh  = (const float*)d_in[13];
    const float* rfc_W1 = (const float*)d_in[14];
    const float* rfc_b1 = (const float*)d_in[15];
    const float* rfc_W2 = (const float*)d_in[16];
    const float* rfc_b2 = (const float*)d_in[17];
    const float* pfc_W1 = (const float*)d_in[18];
    const float* pfc_b1 = (const float*)d_in[19];
    const float* pfc_W2 = (const float*)d_in[20];
    const float* pfc_b2 = (const float*)d_in[21];
    float* out = (float*)d_out;

    float *GXw, *GXs, *GXr, *HwA, *HwB, *HsA, *HsB, *HrA, *HrB;
    bf16 *Xhi, *Xlo, *WihHi, *WihLo, *WhhHi, *WhhLo, *WsHi, *WsLo;
    bf16 *SHiA, *SHiB, *SLoA, *SLoB;
    cudaGetSymbolAddress((void**)&GXw, g_GXw);
    cudaGetSymbolAddress((void**)&GXs, g_GXs);
    cudaGetSymbolAddress((void**)&GXr, g_GXr);
    cudaGetSymbolAddress((void**)&HwA, g_HwA);
    cudaGetSymbolAddress((void**)&HwB, g_HwB);
    cudaGetSymbolAddress((void**)&HsA, g_HsA);
    cudaGetSymbolAddress((void**)&HsB, g_HsB);
    cudaGetSymbolAddress((void**)&HrA, g_HrA);
    cudaGetSymbolAddress((void**)&HrB, g_HrB);
    cudaGetSymbolAddress((void**)&Xhi, g_Xhi);
    cudaGetSymbolAddress((void**)&Xlo, g_Xlo);
    cudaGetSymbolAddress((void**)&WihHi, g_WihHi);
    cudaGetSymbolAddress((void**)&WihLo, g_WihLo);
    cudaGetSymbolAddress((void**)&WhhHi, g_WhhHi);
    cudaGetSymbolAddress((void**)&WhhLo, g_WhhLo);
    cudaGetSymbolAddress((void**)&WsHi, g_WsHi);
    cudaGetSymbolAddress((void**)&WsLo, g_WsLo);
    cudaGetSymbolAddress((void**)&SHiA, g_SHiA);
    cudaGetSymbolAddress((void**)&SHiB, g_SHiB);
    cudaGetSymbolAddress((void**)&SLoA, g_SLoA);
    cudaGetSymbolAddress((void**)&SLoB, g_SLoB);

    const int SMEM_GEMM = 98304;    // 2 bufs x 4 matrices x 12288
    const int SMEM_GRU  = 122880;   // 2 x (2x12288 + 2x18432)
    cudaFuncSetAttribute(gemm_wmma2, cudaFuncAttributeMaxDynamicSharedMemorySize, SMEM_GEMM);
    cudaFuncSetAttribute(gru_step_wmma, cudaFuncAttributeMaxDynamicSharedMemorySize, SMEM_GRU);

    // ---- prep ----
    split_mat_kernel<<<(GDIM * KPAD + 255) / 256, 256>>>(w_Wih, WihHi, WihLo, GDIM, EDIM, KPAD);
    split_mat_kernel<<<(GDIM * HDIM + 255) / 256, 256>>>(w_Whh, WhhHi, WhhLo, GDIM, HDIM, HDIM);
    split_mat_kernel<<<(GDIM * HDIM + 255) / 256, 256>>>(s_Wih, WsHi, WsLo, GDIM, HDIM, HDIM);
    gather_split_kernel<<<(int)(((size_t)MW * 64 + 255) / 256), 256>>>(idx, emb, Xhi, Xlo);

    // ---- word level: gx ----
    gemm_wmma2<<<dim3(GDIM / 128, MW / 128), 256, SMEM_GEMM>>>(Xhi, Xlo, WihHi, WihLo,
                                                               w_bih, GXw, KPAD, GDIM);

    float* hw[2] = {HwA, HwB};
    bf16*  shi[2] = {SHiA, SHiB};
    bf16*  slo[2] = {SLoA, SLoB};
    int cw = 0;
    gru_init_split<<<(NW * HDIM + 255) / 256, 256>>>(GXw, w_bhh, hw[0], shi[0], slo[0],
                                                     NW, TWSTEPS);
    for (int t = 1; t < TWSTEPS; t++) {
        gru_step_wmma<<<dim3(HDIM / 64, NW / 128), 256, SMEM_GRU>>>(
            hw[cw], shi[cw], slo[cw], WhhHi, WhhLo, w_bhh, GXw, TWSTEPS, t,
            hw[1 - cw], shi[1 - cw], slo[1 - cw]);
        cw = 1 - cw;
    }

    // ---- sentence level gx (wmma on final word-h splits) ----
    gemm_wmma2<<<dim3(GDIM / 128, (NS * TSSTEPS) / 128), 256, SMEM_GEMM>>>(
        shi[cw], slo[cw], WsHi, WsLo, s_bih, GXs, HDIM, GDIM);

    float* hs[2] = {HsA, HsB};
    int cs = 0;
    gru_init_plain<<<(NS * HDIM + 255) / 256, 256>>>(GXs, s_bhh, hs[0], NS, TSSTEPS);
    {
        dim3 grid(HDIM / 32, (NS + 31) / 32);
        for (int t = 1; t < TSSTEPS; t++) {
            gru_step_small<<<grid, 256>>>(hs[cs], s_Whh, s_bhh, GXs, TSSTEPS, t,
                                          hs[1 - cs], NS);
            cs = 1 - cs;
        }
    }
    const float* p_batch = hs[cs];

    // r_stars -> out[16 .. 272)
    mlp_kernel<<<NS, 128>>>(p_batch, rfc_W1, rfc_b1, rfc_W2, rfc_b2, out + NR);

    // ---- review level (fp32 path) ----
    {
        dim3 grid(GDIM / BN, (NR * TRSTEPS + BM - 1) / BM);
        sgemm_f32x2<<<grid, 256>>>(p_batch, r_Wih, r_bih, GXr, NR * TRSTEPS, HDIM, GDIM);
    }
    float* hr[2] = {HrA, HrB};
    int cr = 0;
    gru_init_plain<<<(NR * HDIM + 255) / 256, 256>>>(GXr, r_bhh, hr[0], NR, TRSTEPS);
    {
        dim3 grid(HDIM / 32, (NR + 31) / 32);
        for (int t = 1; t < TRSTEPS; t++) {
            gru_step_small<<<grid, 256>>>(hr[cr], r_Whh, r_bhh, GXr, TRSTEPS, t,
                                          hr[1 - cr], NR);
            cr = 1 - cr;
        }
    }
    // b_stars -> out[0 .. 16)
    mlp_kernel<<<NR, 128>>>(hr[cr], pfc_W1, pfc_b1, pfc_W2, pfc_b2, out);
}

// round 7
// speedup vs baseline: 2.7215x; 1.4080x over previous
#include <cuda_runtime.h>
#include <cuda_fp16.h>
#include <mma.h>
#include <math.h>
#include <stdint.h>

using namespace nvcuda;

// ---------------- problem dims ----------------
#define HDIM 256
#define GDIM 768           // 3*H
#define EDIM 200
#define NW 4096            // B*R*S word sequences
#define TWSTEPS 32
#define NS 256             // B*R
#define TSSTEPS 16
#define NR 16              // B
#define TRSTEPS 16
#define MW (NW * TWSTEPS)  // 131072 word-gx rows
#define KPAD 224           // padded K for word gx (EDIM=200 -> 224, %32)
#define KP4 (KPAD / 4)     // 56 float4 chunks per row

typedef unsigned long long ull;
typedef __half h16;

// ---------------- scratch (static device globals) ----------------
__device__ float g_GXw[(size_t)MW * GDIM];             // 402 MB word input gates
__device__ float g_GXs[(size_t)NS * TSSTEPS * GDIM];
__device__ float g_GXr[(size_t)NR * TRSTEPS * GDIM];
__device__ float g_HwA[NW * HDIM], g_HwB[NW * HDIM];
__device__ float g_HsA[NS * HDIM], g_HsB[NS * HDIM];
__device__ float g_HrA[NR * HDIM], g_HrB[NR * HDIM];
// fp16 split buffers (A operands 2-way split; weights single-rounded)
__device__ __align__(16) h16 g_Xhi[(size_t)MW * KPAD];
__device__ __align__(16) h16 g_Xlo[(size_t)MW * KPAD];
__device__ __align__(16) h16 g_WihH[GDIM * KPAD];
__device__ __align__(16) h16 g_WhhH[GDIM * HDIM];
__device__ __align__(16) h16 g_WsH [GDIM * HDIM];
__device__ __align__(16) h16 g_SHiA[NW * HDIM], g_SHiB[NW * HDIM];
__device__ __align__(16) h16 g_SLoA[NW * HDIM], g_SLoB[NW * HDIM];

// ---------------- helpers ----------------
__device__ __forceinline__ float sigmoid_f(float x) { return 1.f / (1.f + expf(-x)); }
__device__ __forceinline__ ull pack2(float lo, float hi) {
    ull r; asm("mov.b64 %0, {%1, %2};" : "=l"(r) : "f"(lo), "f"(hi)); return r;
}
__device__ __forceinline__ ull dup2(float v) { return pack2(v, v); }
__device__ __forceinline__ void ffma2(ull& d, ull a, ull b) {
    asm("fma.rn.f32x2 %0, %1, %2, %3;" : "=l"(d) : "l"(a), "l"(b), "l"(d));
}
__device__ __forceinline__ float2 unpack2(ull v) {
    float2 f; asm("mov.b64 {%0, %1}, %2;" : "=f"(f.x), "=f"(f.y) : "l"(v)); return f;
}
__device__ __forceinline__ void cp16(uint32_t s, const void* g) {
    asm volatile("cp.async.cg.shared.global [%0], [%1], 16;" :: "r"(s), "l"(g));
}
#define CP_COMMIT() asm volatile("cp.async.commit_group;" ::: "memory")
#define CP_WAIT(n)  asm volatile("cp.async.wait_group %0;" :: "n"(n) : "memory")

// ---------------- prep kernels ----------------
__global__ void split_w_single(const float* __restrict__ src, h16* __restrict__ dst,
                               int rows, int cs, int cd)
{
    int i = blockIdx.x * blockDim.x + threadIdx.x;
    if (i >= rows * cd) return;
    int r = i / cd, c = i - r * cd;
    float v = (c < cs) ? src[(size_t)r * cs + c] : 0.f;
    dst[i] = __float2half_rn(v);
}

// one float4 per thread; KP4 chunks per row
__global__ void gather_split_kernel(const int* __restrict__ idx, const float* __restrict__ emb,
                                    h16* __restrict__ hi, h16* __restrict__ lo)
{
    size_t id = (size_t)blockIdx.x * blockDim.x + threadIdx.x;
    if (id >= (size_t)MW * KP4) return;
    int row = (int)(id / KP4);
    int c4 = (int)(id - (size_t)row * KP4) * 4;
    float4 v = make_float4(0.f, 0.f, 0.f, 0.f);
    if (c4 < EDIM)
        v = *reinterpret_cast<const float4*>(emb + (size_t)idx[row] * EDIM + c4);
    float vv[4] = {v.x, v.y, v.z, v.w};
    h16 hb[4], lb[4];
#pragma unroll
    for (int u = 0; u < 4; u++) {
        hb[u] = __float2half_rn(vv[u]);
        lb[u] = __float2half_rn(vv[u] - __half2float(hb[u]));
    }
    size_t o = (size_t)row * KPAD + c4;
    *reinterpret_cast<ull*>(hi + o) = *reinterpret_cast<ull*>(hb);
    *reinterpret_cast<ull*>(lo + o) = *reinterpret_cast<ull*>(lb);
}

// ---------------- wmma fp16 2-pass GEMM: C = (Ah+Al)@Wh^T + bias ------------
// CTA 128x128, 8 warps 32x64. M%128==0, N%128==0, K%32==0.
#define LDT2 48                      // smem row stride (h16 elems), 96B
#define TBY (128 * LDT2 * 2)         // 12288B per matrix tile
#define GEMM_BUF (3 * TBY)           // Ah, Al, Bh

__global__ __launch_bounds__(256, 1)
void gemm_wmma2(const h16* __restrict__ Ahp, const h16* __restrict__ Alp,
                const h16* __restrict__ Whp, const float* __restrict__ bias,
                float* __restrict__ C, int K, int N)
{
    extern __shared__ __align__(128) char sm[];
    const uint32_t sbase = (uint32_t)__cvta_generic_to_shared(sm);
    float* scratch = reinterpret_cast<float*>(sm);

    const int tid = threadIdx.x;
    const int wid = tid >> 5;
    const int m0 = blockIdx.y * 128, n0 = blockIdx.x * 128;
    const int wm = wid & 3, wn = wid >> 2;

    const int lr = tid >> 1;            // 0..127
    const int lq = (tid & 1) * 16;      // elem offset 0 / 16

    const h16* gA[2] = {Ahp + (size_t)(m0 + lr) * K + lq, Alp + (size_t)(m0 + lr) * K + lq};
    const h16* gB = Whp + (size_t)(n0 + lr) * K + lq;
    const uint32_t srow = lr * LDT2 * 2 + lq * 2;

    const int ntile = K / 32;

    wmma::fragment<wmma::accumulator, 16, 16, 16, float> cf[2][4];
#pragma unroll
    for (int i = 0; i < 2; i++)
#pragma unroll
        for (int j = 0; j < 4; j++) wmma::fill_fragment(cf[i][j], 0.0f);

    auto issue = [&](int it, int b) {
        const int kk = it * 32;
        uint32_t base = sbase + b * GEMM_BUF;
#pragma unroll
        for (int s = 0; s < 2; s++) {
            cp16(base + s * TBY + srow,      gA[s] + kk);
            cp16(base + s * TBY + srow + 16, gA[s] + kk + 8);
        }
        cp16(base + 2 * TBY + srow,      gB + kk);
        cp16(base + 2 * TBY + srow + 16, gB + kk + 8);
    };

    issue(0, 0); CP_COMMIT();

    for (int it = 0; it < ntile; it++) {
        const int b = it & 1;
        if (it + 1 < ntile) { issue(it + 1, b ^ 1); CP_COMMIT(); CP_WAIT(1); }
        else                { CP_WAIT(0); }
        __syncthreads();

        const h16* tAh = reinterpret_cast<const h16*>(sm + b * GEMM_BUF);
        const h16* tAl = tAh + 128 * LDT2;
        const h16* tBh = tAl + 128 * LDT2;

#pragma unroll
        for (int ks = 0; ks < 32; ks += 16) {
            wmma::fragment<wmma::matrix_a, 16, 16, 16, h16, wmma::row_major> ah[2], al[2];
            wmma::fragment<wmma::matrix_b, 16, 16, 16, h16, wmma::col_major> bh[4];
#pragma unroll
            for (int i = 0; i < 2; i++) {
                wmma::load_matrix_sync(ah[i], tAh + (wm * 32 + i * 16) * LDT2 + ks, LDT2);
                wmma::load_matrix_sync(al[i], tAl + (wm * 32 + i * 16) * LDT2 + ks, LDT2);
            }
#pragma unroll
            for (int j = 0; j < 4; j++)
                wmma::load_matrix_sync(bh[j], tBh + (wn * 64 + j * 16) * LDT2 + ks, LDT2);
#pragma unroll
            for (int i = 0; i < 2; i++)
#pragma unroll
                for (int j = 0; j < 4; j++) {
                    wmma::mma_sync(cf[i][j], ah[i], bh[j], cf[i][j]);
                    wmma::mma_sync(cf[i][j], al[i], bh[j], cf[i][j]);
                }
        }
        __syncthreads();
    }

    // epilogue via smem scratch
#pragma unroll
    for (int i = 0; i < 2; i++)
#pragma unroll
        for (int j = 0; j < 4; j++)
            wmma::store_matrix_sync(&scratch[(wm * 32 + i * 16) * 128 + wn * 64 + j * 16],
                                    cf[i][j], 128, wmma::mem_row_major);
    __syncthreads();

#pragma unroll
    for (int itx = 0; itx < 16; itx++) {
        int idx4 = tid + itx * 256;
        int r = idx4 >> 5;
        int c4 = (idx4 & 31) * 4;
        float4 v = *reinterpret_cast<const float4*>(&scratch[r * 128 + c4]);
        float4 b = *reinterpret_cast<const float4*>(&bias[n0 + c4]);
        v.x += b.x; v.y += b.y; v.z += b.z; v.w += b.w;
        *reinterpret_cast<float4*>(&C[(size_t)(m0 + r) * N + n0 + c4]) = v;
    }
}

// ---------------- fused wmma GRU step (fp16 2-pass) --------------------------
// CTA: 128 rows x 64 h-cols x 3 gates (B tile = 192 weight rows). K = 256.
// grid = (HDIM/64 = 4, NW/128). 8 warps: wm (32 rows), wn (96 cols).
#define GB_ROWS 192
#define ATBY (128 * LDT2 * 2)     // 12288
#define BTBY (GB_ROWS * LDT2 * 2) // 18432
#define GBUF (2 * ATBY + BTBY)    // 43008 per buffer

__global__ __launch_bounds__(256, 1)
void gru_step_wmma(const float* __restrict__ hin,
                   const h16* __restrict__ Hhi, const h16* __restrict__ Hlo,
                   const h16* __restrict__ Whp,
                   const float* __restrict__ bhh, const float* __restrict__ gx,
                   int T, int t, float* __restrict__ hout,
                   h16* __restrict__ HhiOut, h16* __restrict__ HloOut)
{
    extern __shared__ __align__(128) char sm[];
    const uint32_t sbase = (uint32_t)__cvta_generic_to_shared(sm);
    float* scratch = reinterpret_cast<float*>(sm);   // 128x192 fp32 after compute

    const int tid = threadIdx.x;
    const int wid = tid >> 5;
    const int n0 = blockIdx.x * 64;
    const int m0 = blockIdx.y * 128;
    const int wm = wid & 3, wn = wid >> 2;

    const int lr = tid >> 1;
    const int lq = (tid & 1) * 16;
    const h16* gA[2] = {Hhi + (size_t)(m0 + lr) * HDIM + lq,
                        Hlo + (size_t)(m0 + lr) * HDIM + lq};
    const uint32_t arow = lr * LDT2 * 2 + lq * 2;

    auto issue = [&](int it, int b) {
        const int kk = it * 32;
        uint32_t base = sbase + b * GBUF;
#pragma unroll
        for (int s = 0; s < 2; s++) {
            cp16(base + s * ATBY + arow,      gA[s] + kk);
            cp16(base + s * ATBY + arow + 16, gA[s] + kk + 8);
        }
        for (int task = tid; task < 384; task += 256) {
            int rt = task >> 1;
            int q = (task & 1) * 16;
            int gate = rt / 64, col = rt - gate * 64;
            size_t srcoff = (size_t)(gate * HDIM + n0 + col) * HDIM + kk + q;
            uint32_t soff = rt * LDT2 * 2 + q * 2;
            cp16(base + 2 * ATBY + soff,      Whp + srcoff);
            cp16(base + 2 * ATBY + soff + 16, Whp + srcoff + 8);
        }
    };

    wmma::fragment<wmma::accumulator, 16, 16, 16, float> cf[2][6];
#pragma unroll
    for (int i = 0; i < 2; i++)
#pragma unroll
        for (int j = 0; j < 6; j++) wmma::fill_fragment(cf[i][j], 0.0f);

    issue(0, 0); CP_COMMIT();

    const int ntile = HDIM / 32;   // 8
    for (int it = 0; it < ntile; it++) {
        const int b = it & 1;
        if (it + 1 < ntile) { issue(it + 1, b ^ 1); CP_COMMIT(); CP_WAIT(1); }
        else                { CP_WAIT(0); }
        __syncthreads();

        const h16* tAh = reinterpret_cast<const h16*>(sm + b * GBUF);
        const h16* tAl = tAh + 128 * LDT2;
        const h16* tBh = tAl + 128 * LDT2;

#pragma unroll
        for (int ks = 0; ks < 32; ks += 16) {
            wmma::fragment<wmma::matrix_a, 16, 16, 16, h16, wmma::row_major> ah[2], al[2];
#pragma unroll
            for (int i = 0; i < 2; i++) {
                wmma::load_matrix_sync(ah[i], tAh + (wm * 32 + i * 16) * LDT2 + ks, LDT2);
                wmma::load_matrix_sync(al[i], tAl + (wm * 32 + i * 16) * LDT2 + ks, LDT2);
            }
#pragma unroll
            for (int j = 0; j < 6; j++) {
                wmma::fragment<wmma::matrix_b, 16, 16, 16, h16, wmma::col_major> bh;
                wmma::load_matrix_sync(bh, tBh + (wn * 96 + j * 16) * LDT2 + ks, LDT2);
#pragma unroll
                for (int i = 0; i < 2; i++) {
                    wmma::mma_sync(cf[i][j], ah[i], bh, cf[i][j]);
                    wmma::mma_sync(cf[i][j], al[i], bh, cf[i][j]);
                }
            }
        }
        __syncthreads();
    }

    // stash gates to scratch [128][192]
#pragma unroll
    for (int i = 0; i < 2; i++)
#pragma unroll
        for (int j = 0; j < 6; j++)
            wmma::store_matrix_sync(&scratch[(wm * 32 + i * 16) * 192 + wn * 96 + j * 16],
                                    cf[i][j], 192, wmma::mem_row_major);
    __syncthreads();

    // fused GRU epilogue
#pragma unroll
    for (int itx = 0; itx < 8; itx++) {
        int task = tid + itx * 256;
        int r = task >> 4;
        int c4 = (task & 15) * 4;
        const int row = m0 + r;
        const int j = n0 + c4;
        const float* srow2 = &scratch[r * 192];
        float gr[4], gz[4], gn[4];
        *reinterpret_cast<float4*>(gr) = *reinterpret_cast<const float4*>(srow2 + c4);
        *reinterpret_cast<float4*>(gz) = *reinterpret_cast<const float4*>(srow2 + 64 + c4);
        *reinterpret_cast<float4*>(gn) = *reinterpret_cast<const float4*>(srow2 + 128 + c4);
        float br[4], bz[4], bn[4], xr[4], xz[4], xn[4], hh[4];
        *reinterpret_cast<float4*>(br) = *reinterpret_cast<const float4*>(bhh + j);
        *reinterpret_cast<float4*>(bz) = *reinterpret_cast<const float4*>(bhh + HDIM + j);
        *reinterpret_cast<float4*>(bn) = *reinterpret_cast<const float4*>(bhh + 2 * HDIM + j);
        const float* gxp = gx + ((size_t)row * T + t) * GDIM;
        *reinterpret_cast<float4*>(xr) = *reinterpret_cast<const float4*>(gxp + j);
        *reinterpret_cast<float4*>(xz) = *reinterpret_cast<const float4*>(gxp + HDIM + j);
        *reinterpret_cast<float4*>(xn) = *reinterpret_cast<const float4*>(gxp + 2 * HDIM + j);
        *reinterpret_cast<float4*>(hh) = *reinterpret_cast<const float4*>(hin + (size_t)row * HDIM + j);
        float o[4];
        h16 hb[4], lb[4];
#pragma unroll
        for (int u = 0; u < 4; u++) {
            float rr = sigmoid_f(xr[u] + gr[u] + br[u]);
            float zz = sigmoid_f(xz[u] + gz[u] + bz[u]);
            float nv = tanhf(xn[u] + rr * (gn[u] + bn[u]));
            float h = (1.f - zz) * nv + zz * hh[u];
            o[u] = h;
            hb[u] = __float2half_rn(h);
            lb[u] = __float2half_rn(h - __half2float(hb[u]));
        }
        *reinterpret_cast<float4*>(hout + (size_t)row * HDIM + j) = *reinterpret_cast<float4*>(o);
        *reinterpret_cast<ull*>(HhiOut + (size_t)row * HDIM + j) = *reinterpret_cast<ull*>(hb);
        *reinterpret_cast<ull*>(HloOut + (size_t)row * HDIM + j) = *reinterpret_cast<ull*>(lb);
    }
}

// ---------------- t=0 GRU steps ----------------
__global__ void gru_init_split(const float* __restrict__ gx, const float* __restrict__ bhh,
                               float* __restrict__ hout, h16* __restrict__ hi,
                               h16* __restrict__ lo, int Mseq, int T)
{
    int i = blockIdx.x * blockDim.x + threadIdx.x;
    if (i >= Mseq * HDIM) return;
    int seq = i >> 8, j = i & 255;
    const float* g = gx + (size_t)seq * T * GDIM;
    float r = sigmoid_f(g[j] + bhh[j]);
    float z = sigmoid_f(g[j + HDIM] + bhh[j + HDIM]);
    float n = tanhf(g[j + 2 * HDIM] + r * bhh[j + 2 * HDIM]);
    float h = (1.f - z) * n;
    hout[i] = h;
    h16 hb = __float2half_rn(h);
    hi[i] = hb;
    lo[i] = __float2half_rn(h - __half2float(hb));
}

__global__ void gru_init_plain(const float* __restrict__ gx, const float* __restrict__ bhh,
                               float* __restrict__ hout, int Mseq, int T)
{
    int i = blockIdx.x * blockDim.x + threadIdx.x;
    if (i >= Mseq * HDIM) return;
    int seq = i >> 8, j = i & 255;
    const float* g = gx + (size_t)seq * T * GDIM;
    float r = sigmoid_f(g[j] + bhh[j]);
    float z = sigmoid_f(g[j + HDIM] + bhh[j + HDIM]);
    float n = tanhf(g[j + 2 * HDIM] + r * bhh[j + 2 * HDIM]);
    hout[i] = (1.f - z) * n;
}

// ---------------- fp32 SGEMM (review gx) ----------------
#define BM 128
#define BN 128
#define BK 8
__global__ __launch_bounds__(256, 2)
void sgemm_f32x2(const float* __restrict__ A, const float* __restrict__ W,
                 const float* __restrict__ bias, float* __restrict__ C,
                 int M, int K, int N)
{
    __shared__ float As[2][BK][BM];
    __shared__ float Bs[2][BK][BN];
    const int tid = threadIdx.x;
    const int m0 = blockIdx.y * BM;
    const int n0 = blockIdx.x * BN;
    const int a_m = tid & 127, a_kq = tid >> 7;
    const int b_n = tid >> 1,  b_kq = tid & 1;
    const bool a_valid = (m0 + a_m) < M;
    const float* Arow = A + (size_t)(a_valid ? (m0 + a_m) : 0) * K;
    const float* Brow = W + (size_t)(n0 + b_n) * K;
    const int tx = tid & 15, ty = tid >> 4;

    ull acc2[8][4];
#pragma unroll
    for (int i = 0; i < 8; i++)
#pragma unroll
        for (int j = 0; j < 4; j++) acc2[i][j] = 0ull;

    float4 av = make_float4(0.f, 0.f, 0.f, 0.f);
    if (a_valid) av = *reinterpret_cast<const float4*>(Arow + a_kq * 4);
    float4 bv = *reinterpret_cast<const float4*>(Brow + b_kq * 4);
    As[0][a_kq * 4 + 0][a_m] = av.x;  As[0][a_kq * 4 + 1][a_m] = av.y;
    As[0][a_kq * 4 + 2][a_m] = av.z;  As[0][a_kq * 4 + 3][a_m] = av.w;
    Bs[0][b_kq * 4 + 0][b_n] = bv.x;  Bs[0][b_kq * 4 + 1][b_n] = bv.y;
    Bs[0][b_kq * 4 + 2][b_n] = bv.z;  Bs[0][b_kq * 4 + 3][b_n] = bv.w;
    __syncthreads();

    int buf = 0;
    for (int kk = 0; kk < K; kk += BK) {
        const bool has_next = (kk + BK) < K;
        if (has_next) {
            if (a_valid) av = *reinterpret_cast<const float4*>(Arow + kk + BK + a_kq * 4);
            bv = *reinterpret_cast<const float4*>(Brow + kk + BK + b_kq * 4);
        }
#pragma unroll
        for (int k = 0; k < BK; k++) {
            float4 a0 = *reinterpret_cast<const float4*>(&As[buf][k][ty * 8]);
            float4 a1 = *reinterpret_cast<const float4*>(&As[buf][k][ty * 8 + 4]);
            ulonglong2 bq0 = *reinterpret_cast<const ulonglong2*>(&Bs[buf][k][tx * 8]);
            ulonglong2 bq1 = *reinterpret_cast<const ulonglong2*>(&Bs[buf][k][tx * 8 + 4]);
            ull bp[4] = {bq0.x, bq0.y, bq1.x, bq1.y};
            float a[8] = {a0.x, a0.y, a0.z, a0.w, a1.x, a1.y, a1.z, a1.w};
#pragma unroll
            for (int i = 0; i < 8; i++) {
                ull ad = dup2(a[i]);
#pragma unroll
                for (int j = 0; j < 4; j++) ffma2(acc2[i][j], ad, bp[j]);
            }
        }
        if (has_next) {
            int nb = buf ^ 1;
            As[nb][a_kq * 4 + 0][a_m] = av.x;  As[nb][a_kq * 4 + 1][a_m] = av.y;
            As[nb][a_kq * 4 + 2][a_m] = av.z;  As[nb][a_kq * 4 + 3][a_m] = av.w;
            Bs[nb][b_kq * 4 + 0][b_n] = bv.x;  Bs[nb][b_kq * 4 + 1][b_n] = bv.y;
            Bs[nb][b_kq * 4 + 2][b_n] = bv.z;  Bs[nb][b_kq * 4 + 3][b_n] = bv.w;
            __syncthreads();
            buf = nb;
        }
    }
#pragma unroll
    for (int i = 0; i < 8; i++) {
        int row = m0 + ty * 8 + i;
        if (row >= M) continue;
#pragma unroll
        for (int j = 0; j < 4; j++) {
            int col = n0 + tx * 8 + j * 2;
            float2 p = unpack2(acc2[i][j]);
            float2 bb = *reinterpret_cast<const float2*>(bias + col);
            float2 o; o.x = p.x + bb.x; o.y = p.y + bb.y;
            *reinterpret_cast<float2*>(C + (size_t)row * N + col) = o;
        }
    }
}

// ---------------- small-M GRU step: 32 rows x 32 h-cols / CTA ----------------
#define SBK 16
__global__ __launch_bounds__(256)
void gru_step_small(const float* __restrict__ hin, const float* __restrict__ Whh,
                    const float* __restrict__ bhh, const float* __restrict__ gx,
                    int T, int t, float* __restrict__ hout, int M)
{
    __shared__ float As[2][SBK][32];
    __shared__ float Bs[2][3][SBK][32];
    const int tid = threadIdx.x;
    const int n0 = blockIdx.x * 32;
    const int m0 = blockIdx.y * 32;
    const int tx = tid & 7, ty = tid >> 3;
    const int a_m = tid & 31, a_kq = tid >> 5;
    const bool a_valid = (m0 + a_m) < M;
    const float* Arow = hin + (size_t)(a_valid ? (m0 + a_m) : 0) * HDIM;
    const int r1 = tid >> 2, kq1 = tid & 3;
    const int g1 = r1 >> 5, c1 = r1 & 31;
    const int r2 = (tid + 256) >> 2;
    const int g2 = r2 >> 5, c2 = r2 & 31;
    const float* Bp1 = Whh + ((size_t)(g1 * HDIM + n0 + c1)) * HDIM + kq1 * 4;
    const float* Bp2 = Whh + ((size_t)(g2 * HDIM + n0 + c2)) * HDIM + kq1 * 4;

    ull acc[3][2];
#pragma unroll
    for (int g = 0; g < 3; g++) { acc[g][0] = 0ull; acc[g][1] = 0ull; }

    float2 av = make_float2(0.f, 0.f);
    if (a_valid) av = *reinterpret_cast<const float2*>(Arow + a_kq * 2);
    float4 bv1 = *reinterpret_cast<const float4*>(Bp1);
    float4 bv2 = make_float4(0.f, 0.f, 0.f, 0.f);
    if (tid < 128) bv2 = *reinterpret_cast<const float4*>(Bp2);
    As[0][a_kq * 2 + 0][a_m] = av.x;  As[0][a_kq * 2 + 1][a_m] = av.y;
    Bs[0][g1][kq1 * 4 + 0][c1] = bv1.x;  Bs[0][g1][kq1 * 4 + 1][c1] = bv1.y;
    Bs[0][g1][kq1 * 4 + 2][c1] = bv1.z;  Bs[0][g1][kq1 * 4 + 3][c1] = bv1.w;
    if (tid < 128) {
        Bs[0][g2][kq1 * 4 + 0][c2] = bv2.x;  Bs[0][g2][kq1 * 4 + 1][c2] = bv2.y;
        Bs[0][g2][kq1 * 4 + 2][c2] = bv2.z;  Bs[0][g2][kq1 * 4 + 3][c2] = bv2.w;
    }
    __syncthreads();

    int buf = 0;
    for (int kk = 0; kk < HDIM; kk += SBK) {
        const bool has_next = (kk + SBK) < HDIM;
        if (has_next) {
            if (a_valid) av = *reinterpret_cast<const float2*>(Arow + kk + SBK + a_kq * 2);
            bv1 = *reinterpret_cast<const float4*>(Bp1 + kk + SBK);
            if (tid < 128) bv2 = *reinterpret_cast<const float4*>(Bp2 + kk + SBK);
        }
#pragma unroll
        for (int k = 0; k < SBK; k++) {
            ull ad = dup2(As[buf][k][ty]);
#pragma unroll
            for (int g = 0; g < 3; g++) {
                ulonglong2 bq = *reinterpret_cast<const ulonglong2*>(&Bs[buf][g][k][tx * 4]);
                ffma2(acc[g][0], ad, bq.x);
                ffma2(acc[g][1], ad, bq.y);
            }
        }
        if (has_next) {
            int nb = buf ^ 1;
            As[nb][a_kq * 2 + 0][a_m] = av.x;  As[nb][a_kq * 2 + 1][a_m] = av.y;
            Bs[nb][g1][kq1 * 4 + 0][c1] = bv1.x;  Bs[nb][g1][kq1 * 4 + 1][c1] = bv1.y;
            Bs[nb][g1][kq1 * 4 + 2][c1] = bv1.z;  Bs[nb][g1][kq1 * 4 + 3][c1] = bv1.w;
            if (tid < 128) {
                Bs[nb][g2][kq1 * 4 + 0][c2] = bv2.x;  Bs[nb][g2][kq1 * 4 + 1][c2] = bv2.y;
                Bs[nb][g2][kq1 * 4 + 2][c2] = bv2.z;  Bs[nb][g2][kq1 * 4 + 3][c2] = bv2.w;
            }
            __syncthreads();
            buf = nb;
        }
    }

    const int row = m0 + ty;
    if (row >= M) return;
    const int jb = n0 + tx * 4;
    const float* gxp = gx + ((size_t)row * T + t) * GDIM;
    const float* hp  = hin + (size_t)row * HDIM;
    float*       op  = hout + (size_t)row * HDIM;
#pragma unroll
    for (int p = 0; p < 2; p++) {
        int j = jb + p * 2;
        float2 br = *reinterpret_cast<const float2*>(bhh + j);
        float2 bz = *reinterpret_cast<const float2*>(bhh + HDIM + j);
        float2 bn = *reinterpret_cast<const float2*>(bhh + 2 * HDIM + j);
        float2 ar = unpack2(acc[0][p]);
        float2 az = unpack2(acc[1][p]);
        float2 an = unpack2(acc[2][p]);
        float2 xr = *reinterpret_cast<const float2*>(gxp + j);
        float2 xz = *reinterpret_cast<const float2*>(gxp + HDIM + j);
        float2 xn = *reinterpret_cast<const float2*>(gxp + 2 * HDIM + j);
        float2 h  = *reinterpret_cast<const float2*>(hp + j);
        float r0 = sigmoid_f(xr.x + ar.x + br.x);
        float r1v = sigmoid_f(xr.y + ar.y + br.y);
        float z0 = sigmoid_f(xz.x + az.x + bz.x);
        float z1 = sigmoid_f(xz.y + az.y + bz.y);
        float n0v = tanhf(xn.x + r0 * (an.x + bn.x));
        float n1v = tanhf(xn.y + r1v * (an.y + bn.y));
        float2 o;
        o.x = (1.f - z0) * n0v + z0 * h.x;
        o.y = (1.f - z1) * n1v + z1 * h.y;
        *reinterpret_cast<float2*>(op + j) = o;
    }
}

// ---------------- MLP ----------------
__global__ __launch_bounds__(128)
void mlp_kernel(const float* __restrict__ X,
                const float* __restrict__ W1, const float* __restrict__ b1,
                const float* __restrict__ W2, const float* __restrict__ b2,
                float* __restrict__ out)
{
    const int row = blockIdx.x;
    const int i = threadIdx.x;
    __shared__ float xs[HDIM];
    __shared__ float red[4];
    xs[i]       = X[(size_t)row * HDIM + i];
    xs[i + 128] = X[(size_t)row * HDIM + i + 128];
    __syncthreads();
    const float* w = W1 + (size_t)i * HDIM;
    float acc = b1[i];
#pragma unroll 8
    for (int k = 0; k < HDIM; k += 4) {
        float4 wv = *reinterpret_cast<const float4*>(w + k);
        acc = fmaf(wv.x, xs[k], acc);
        acc = fmaf(wv.y, xs[k + 1], acc);
        acc = fmaf(wv.z, xs[k + 2], acc);
        acc = fmaf(wv.w, xs[k + 3], acc);
    }
    const float scale = 1.0507009873554805f;
    const float alpha = 1.6732632423543772f;
    float s = scale * (acc > 0.f ? acc : alpha * (expf(acc) - 1.f));
    float v = s * W2[i];
#pragma unroll
    for (int off = 16; off > 0; off >>= 1)
        v += __shfl_down_sync(0xffffffffu, v, off);
    if ((i & 31) == 0) red[i >> 5] = v;
    __syncthreads();
    if (i == 0) out[row] = red[0] + red[1] + red[2] + red[3] + b2[0];
}

// ---------------- host orchestration ----------------
extern "C" void kernel_launch(void* const* d_in, const int* in_sizes, int n_in,
                              void* d_out, int out_size)
{
    (void)in_sizes; (void)n_in; (void)out_size;

    const int*   idx    = (const int*)  d_in[0];
    const float* emb    = (const float*)d_in[1];
    const float* w_Wih  = (const float*)d_in[2];
    const float* w_Whh  = (const float*)d_in[3];
    const float* w_bih  = (const float*)d_in[4];
    const float* w_bhh  = (const float*)d_in[5];
    const float* s_Wih  = (const float*)d_in[6];
    const float* s_Whh  = (const float*)d_in[7];
    const float* s_bih  = (const float*)d_in[8];
    const float* s_bhh  = (const float*)d_in[9];
    const float* r_Wih  = (const float*)d_in[10];
    const float* r_Whh  = (const float*)d_in[11];
    const float* r_bih  = (const float*)d_in[12];
    const float* r_bhh  = (const float*)d_in[13];
    const float* rfc_W1 = (const float*)d_in[14];
    const float* rfc_b1 = (const float*)d_in[15];
    const float* rfc_W2 = (const float*)d_in[16];
    const float* rfc_b2 = (const float*)d_in[17];
    const float* pfc_W1 = (const float*)d_in[18];
    const float* pfc_b1 = (const float*)d_in[19];
    const float* pfc_W2 = (const float*)d_in[20];
    const float* pfc_b2 = (const float*)d_in[21];
    float* out = (float*)d_out;

    float *GXw, *GXs, *GXr, *HwA, *HwB, *HsA, *HsB, *HrA, *HrB;
    h16 *Xhi, *Xlo, *WihH, *WhhH, *WsH, *SHiA, *SHiB, *SLoA, *SLoB;
    cudaGetSymbolAddress((void**)&GXw, g_GXw);
    cudaGetSymbolAddress((void**)&GXs, g_GXs);
    cudaGetSymbolAddress((void**)&GXr, g_GXr);
    cudaGetSymbolAddress((void**)&HwA, g_HwA);
    cudaGetSymbolAddress((void**)&HwB, g_HwB);
    cudaGetSymbolAddress((void**)&HsA, g_HsA);
    cudaGetSymbolAddress((void**)&HsB, g_HsB);
    cudaGetSymbolAddress((void**)&HrA, g_HrA);
    cudaGetSymbolAddress((void**)&HrB, g_HrB);
    cudaGetSymbolAddress((void**)&Xhi, g_Xhi);
    cudaGetSymbolAddress((void**)&Xlo, g_Xlo);
    cudaGetSymbolAddress((void**)&WihH, g_WihH);
    cudaGetSymbolAddress((void**)&WhhH, g_WhhH);
    cudaGetSymbolAddress((void**)&WsH, g_WsH);
    cudaGetSymbolAddress((void**)&SHiA, g_SHiA);
    cudaGetSymbolAddress((void**)&SHiB, g_SHiB);
    cudaGetSymbolAddress((void**)&SLoA, g_SLoA);
    cudaGetSymbolAddress((void**)&SLoB, g_SLoB);

    const int SMEM_GEMM = 2 * GEMM_BUF;             // 73728 (>= 64KB scratch)
    const int SMEM_GRU  = 98304;                    // max(2*GBUF=86016, scratch 98304)
    cudaFuncSetAttribute(gemm_wmma2, cudaFuncAttributeMaxDynamicSharedMemorySize, SMEM_GEMM);
    cudaFuncSetAttribute(gru_step_wmma, cudaFuncAttributeMaxDynamicSharedMemorySize, SMEM_GRU);

    // ---- prep ----
    split_w_single<<<(GDIM * KPAD + 255) / 256, 256>>>(w_Wih, WihH, GDIM, EDIM, KPAD);
    split_w_single<<<(GDIM * HDIM + 255) / 256, 256>>>(w_Whh, WhhH, GDIM, HDIM, HDIM);
    split_w_single<<<(GDIM * HDIM + 255) / 256, 256>>>(s_Wih, WsH, GDIM, HDIM, HDIM);
    gather_split_kernel<<<(int)(((size_t)MW * KP4 + 255) / 256), 256>>>(idx, emb, Xhi, Xlo);

    // ---- word level: gx ----
    gemm_wmma2<<<dim3(GDIM / 128, MW / 128), 256, SMEM_GEMM>>>(Xhi, Xlo, WihH,
                                                               w_bih, GXw, KPAD, GDIM);

    float* hw[2] = {HwA, HwB};
    h16*   shi[2] = {SHiA, SHiB};
    h16*   slo[2] = {SLoA, SLoB};
    int cw = 0;
    gru_init_split<<<(NW * HDIM + 255) / 256, 256>>>(GXw, w_bhh, hw[0], shi[0], slo[0],
                                                     NW, TWSTEPS);
    for (int t = 1; t < TWSTEPS; t++) {
        gru_step_wmma<<<dim3(HDIM / 64, NW / 128), 256, SMEM_GRU>>>(
            hw[cw], shi[cw], slo[cw], WhhH, w_bhh, GXw, TWSTEPS, t,
            hw[1 - cw], shi[1 - cw], slo[1 - cw]);
        cw = 1 - cw;
    }

    // ---- sentence level gx (wmma on final word-h splits) ----
    gemm_wmma2<<<dim3(GDIM / 128, (NS * TSSTEPS) / 128), 256, SMEM_GEMM>>>(
        shi[cw], slo[cw], WsH, s_bih, GXs, HDIM, GDIM);

    float* hs[2] = {HsA, HsB};
    int cs = 0;
    gru_init_plain<<<(NS * HDIM + 255) / 256, 256>>>(GXs, s_bhh, hs[0], NS, TSSTEPS);
    {
        dim3 grid(HDIM / 32, (NS + 31) / 32);
        for (int t = 1; t < TSSTEPS; t++) {
            gru_step_small<<<grid, 256>>>(hs[cs], s_Whh, s_bhh, GXs, TSSTEPS, t,
                                          hs[1 - cs], NS);
            cs = 1 - cs;
        }
    }
    const float* p_batch = hs[cs];

    // r_stars -> out[16 .. 272)
    mlp_kernel<<<NS, 128>>>(p_batch, rfc_W1, rfc_b1, rfc_W2, rfc_b2, out + NR);

    // ---- review level (fp32 path) ----
    {
        dim3 grid(GDIM / BN, (NR * TRSTEPS + BM - 1) / BM);
        sgemm_f32x2<<<grid, 256>>>(p_batch, r_Wih, r_bih, GXr, NR * TRSTEPS, HDIM, GDIM);
    }
    float* hr[2] = {HrA, HrB};
    int cr = 0;
    gru_init_plain<<<(NR * HDIM + 255) / 256, 256>>>(GXr, r_bhh, hr[0], NR, TRSTEPS);
    {
        dim3 grid(HDIM / 32, (NR + 31) / 32);
        for (int t = 1; t < TRSTEPS; t++) {
            gru_step_small<<<grid, 256>>>(hr[cr], r_Whh, r_bhh, GXr, TRSTEPS, t,
                                          hr[1 - cr], NR);
            cr = 1 - cr;
        }
    }
    // b_stars -> out[0 .. 16)
    mlp_kernel<<<NR, 128>>>(hr[cr], pfc_W1, pfc_b1, pfc_W2, pfc_b2, out);
}

// round 8
// speedup vs baseline: 3.3702x; 1.2383x over previous
#include <cuda_runtime.h>
#include <cuda_fp16.h>
#include <mma.h>
#include <math.h>
#include <stdint.h>

using namespace nvcuda;

// ---------------- problem dims ----------------
#define HDIM 256
#define GDIM 768           // 3*H
#define EDIM 200
#define NW 4096            // B*R*S word sequences
#define TWSTEPS 32
#define NS 256             // B*R
#define TSSTEPS 16
#define NR 16              // B
#define TRSTEPS 16
#define MW (NW * TWSTEPS)  // 131072 word-gx rows
#define KPAD 224           // padded K for word gx (EDIM=200 -> 224, %32)
#define KP4 (KPAD / 4)

typedef unsigned long long ull;
typedef __half h16;

// ---------------- scratch (static device globals) ----------------
__device__ float g_GXw[(size_t)MW * GDIM];             // 402 MB word input gates
__device__ float g_GXs[(size_t)NS * TSSTEPS * GDIM];
__device__ float g_GXr[(size_t)NR * TRSTEPS * GDIM];
__device__ float g_HwA[NW * HDIM], g_HwB[NW * HDIM];
__device__ float g_HsA[NS * HDIM], g_HsB[NS * HDIM];
__device__ float g_HrA[NR * HDIM], g_HrB[NR * HDIM];
// fp16 split buffers
__device__ __align__(16) h16 g_Xhi[(size_t)MW * KPAD];
__device__ __align__(16) h16 g_Xlo[(size_t)MW * KPAD];
__device__ __align__(16) h16 g_WihH[GDIM * KPAD];
__device__ __align__(16) h16 g_WhhH[GDIM * HDIM];
__device__ __align__(16) h16 g_WsH [GDIM * HDIM];      // sentence Wih
__device__ __align__(16) h16 g_WshhH[GDIM * HDIM];     // sentence Whh (tail kernel)
__device__ __align__(16) h16 g_WrhhH[GDIM * HDIM];     // review Whh (tail kernel)
__device__ __align__(16) h16 g_SHiA[NW * HDIM], g_SHiB[NW * HDIM];
__device__ __align__(16) h16 g_SLoA[NW * HDIM], g_SLoB[NW * HDIM];

// ---------------- helpers ----------------
__device__ __forceinline__ float sigmoid_f(float x) { return 1.f / (1.f + expf(-x)); }
__device__ __forceinline__ ull pack2(float lo, float hi) {
    ull r; asm("mov.b64 %0, {%1, %2};" : "=l"(r) : "f"(lo), "f"(hi)); return r;
}
__device__ __forceinline__ ull dup2(float v) { return pack2(v, v); }
__device__ __forceinline__ void ffma2(ull& d, ull a, ull b) {
    asm("fma.rn.f32x2 %0, %1, %2, %3;" : "=l"(d) : "l"(a), "l"(b), "l"(d));
}
__device__ __forceinline__ float2 unpack2(ull v) {
    float2 f; asm("mov.b64 {%0, %1}, %2;" : "=f"(f.x), "=f"(f.y) : "l"(v)); return f;
}
__device__ __forceinline__ void cp16(uint32_t s, const void* g) {
    asm volatile("cp.async.cg.shared.global [%0], [%1], 16;" :: "r"(s), "l"(g));
}
#define CP_COMMIT() asm volatile("cp.async.commit_group;" ::: "memory")
#define CP_WAIT(n)  asm volatile("cp.async.wait_group %0;" :: "n"(n) : "memory")

// ---------------- prep kernels ----------------
__global__ void split_w_single(const float* __restrict__ src, h16* __restrict__ dst,
                               int rows, int cs, int cd)
{
    int i = blockIdx.x * blockDim.x + threadIdx.x;
    if (i >= rows * cd) return;
    int r = i / cd, c = i - r * cd;
    float v = (c < cs) ? src[(size_t)r * cs + c] : 0.f;
    dst[i] = __float2half_rn(v);
}

__global__ void gather_split_kernel(const int* __restrict__ idx, const float* __restrict__ emb,
                                    h16* __restrict__ hi, h16* __restrict__ lo)
{
    size_t id = (size_t)blockIdx.x * blockDim.x + threadIdx.x;
    if (id >= (size_t)MW * KP4) return;
    int row = (int)(id / KP4);
    int c4 = (int)(id - (size_t)row * KP4) * 4;
    float4 v = make_float4(0.f, 0.f, 0.f, 0.f);
    if (c4 < EDIM)
        v = *reinterpret_cast<const float4*>(emb + (size_t)idx[row] * EDIM + c4);
    float vv[4] = {v.x, v.y, v.z, v.w};
    h16 hb[4], lb[4];
#pragma unroll
    for (int u = 0; u < 4; u++) {
        hb[u] = __float2half_rn(vv[u]);
        lb[u] = __float2half_rn(vv[u] - __half2float(hb[u]));
    }
    size_t o = (size_t)row * KPAD + c4;
    *reinterpret_cast<ull*>(hi + o) = *reinterpret_cast<ull*>(hb);
    *reinterpret_cast<ull*>(lo + o) = *reinterpret_cast<ull*>(lb);
}

// ---------------- wmma fp16 2-pass GEMM: C = (Ah+Al)@Wh^T + bias ------------
// CTA 128x128, 8 warps 32x64, occupancy 2.
#define LDT2 48
#define TBY (128 * LDT2 * 2)         // 12288B per matrix tile
#define GEMM_BUF (3 * TBY)           // Ah, Al, Bh

__global__ __launch_bounds__(256, 2)
void gemm_wmma2(const h16* __restrict__ Ahp, const h16* __restrict__ Alp,
                const h16* __restrict__ Whp, const float* __restrict__ bias,
                float* __restrict__ C, int K, int N)
{
    extern __shared__ __align__(128) char sm[];
    const uint32_t sbase = (uint32_t)__cvta_generic_to_shared(sm);
    float* scratch = reinterpret_cast<float*>(sm);

    const int tid = threadIdx.x;
    const int wid = tid >> 5;
    const int m0 = blockIdx.y * 128, n0 = blockIdx.x * 128;
    const int wm = wid & 3, wn = wid >> 2;

    const int lr = tid >> 1;
    const int lq = (tid & 1) * 16;

    const h16* gA[2] = {Ahp + (size_t)(m0 + lr) * K + lq, Alp + (size_t)(m0 + lr) * K + lq};
    const h16* gB = Whp + (size_t)(n0 + lr) * K + lq;
    const uint32_t srow = lr * LDT2 * 2 + lq * 2;

    const int ntile = K / 32;

    wmma::fragment<wmma::accumulator, 16, 16, 16, float> cf[2][4];
#pragma unroll
    for (int i = 0; i < 2; i++)
#pragma unroll
        for (int j = 0; j < 4; j++) wmma::fill_fragment(cf[i][j], 0.0f);

    auto issue = [&](int it, int b) {
        const int kk = it * 32;
        uint32_t base = sbase + b * GEMM_BUF;
#pragma unroll
        for (int s = 0; s < 2; s++) {
            cp16(base + s * TBY + srow,      gA[s] + kk);
            cp16(base + s * TBY + srow + 16, gA[s] + kk + 8);
        }
        cp16(base + 2 * TBY + srow,      gB + kk);
        cp16(base + 2 * TBY + srow + 16, gB + kk + 8);
    };

    issue(0, 0); CP_COMMIT();

    for (int it = 0; it < ntile; it++) {
        const int b = it & 1;
        if (it + 1 < ntile) { issue(it + 1, b ^ 1); CP_COMMIT(); CP_WAIT(1); }
        else                { CP_WAIT(0); }
        __syncthreads();

        const h16* tAh = reinterpret_cast<const h16*>(sm + b * GEMM_BUF);
        const h16* tAl = tAh + 128 * LDT2;
        const h16* tBh = tAl + 128 * LDT2;

#pragma unroll
        for (int ks = 0; ks < 32; ks += 16) {
            wmma::fragment<wmma::matrix_a, 16, 16, 16, h16, wmma::row_major> ah[2], al[2];
            wmma::fragment<wmma::matrix_b, 16, 16, 16, h16, wmma::col_major> bh[4];
#pragma unroll
            for (int i = 0; i < 2; i++) {
                wmma::load_matrix_sync(ah[i], tAh + (wm * 32 + i * 16) * LDT2 + ks, LDT2);
                wmma::load_matrix_sync(al[i], tAl + (wm * 32 + i * 16) * LDT2 + ks, LDT2);
            }
#pragma unroll
            for (int j = 0; j < 4; j++)
                wmma::load_matrix_sync(bh[j], tBh + (wn * 64 + j * 16) * LDT2 + ks, LDT2);
#pragma unroll
            for (int i = 0; i < 2; i++)
#pragma unroll
                for (int j = 0; j < 4; j++) {
                    wmma::mma_sync(cf[i][j], ah[i], bh[j], cf[i][j]);
                    wmma::mma_sync(cf[i][j], al[i], bh[j], cf[i][j]);
                }
        }
        __syncthreads();
    }

#pragma unroll
    for (int i = 0; i < 2; i++)
#pragma unroll
        for (int j = 0; j < 4; j++)
            wmma::store_matrix_sync(&scratch[(wm * 32 + i * 16) * 128 + wn * 64 + j * 16],
                                    cf[i][j], 128, wmma::mem_row_major);
    __syncthreads();

#pragma unroll
    for (int itx = 0; itx < 16; itx++) {
        int idx4 = tid + itx * 256;
        int r = idx4 >> 5;
        int c4 = (idx4 & 31) * 4;
        float4 v = *reinterpret_cast<const float4*>(&scratch[r * 128 + c4]);
        float4 b = *reinterpret_cast<const float4*>(&bias[n0 + c4]);
        v.x += b.x; v.y += b.y; v.z += b.z; v.w += b.w;
        *reinterpret_cast<float4*>(&C[(size_t)(m0 + r) * N + n0 + c4]) = v;
    }
}

// ---------------- fused wmma GRU step (64 rows x 64 h-cols x 3 gates) -------
// grid = (HDIM/64 = 4, NW/64 = 64) = 256 CTAs, occupancy 2.
#define GB_ROWS 192
#define A64BY (64 * LDT2 * 2)       // 6144
#define B64BY (GB_ROWS * LDT2 * 2)  // 18432
#define GBUF2 (2 * A64BY + B64BY)   // 30720 per buffer

__global__ __launch_bounds__(256, 2)
void gru_step_wmma(const float* __restrict__ hin,
                   const h16* __restrict__ Hhi, const h16* __restrict__ Hlo,
                   const h16* __restrict__ Whp,
                   const float* __restrict__ bhh, const float* __restrict__ gx,
                   int T, int t, float* __restrict__ hout,
                   h16* __restrict__ HhiOut, h16* __restrict__ HloOut)
{
    extern __shared__ __align__(128) char sm[];
    const uint32_t sbase = (uint32_t)__cvta_generic_to_shared(sm);
    float* scratch = reinterpret_cast<float*>(sm);   // 64x192 fp32 after compute

    const int tid = threadIdx.x;
    const int wid = tid >> 5;
    const int n0 = blockIdx.x * 64;
    const int m0 = blockIdx.y * 64;
    const int wm = wid & 1;        // 2 m-tiles of 32 rows
    const int wn = wid >> 1;       // 4 n-tiles of 48 cols (of 192)

    const int lr = tid >> 2;             // 0..63
    const int lq = (tid & 3) * 8;        // elem offset 0/8/16/24
    const h16* gAh = Hhi + (size_t)(m0 + lr) * HDIM + lq;
    const h16* gAl = Hlo + (size_t)(m0 + lr) * HDIM + lq;
    const uint32_t arow = lr * (LDT2 * 2) + lq * 2;

    auto issue = [&](int it, int b) {
        const int kk = it * 32;
        uint32_t base = sbase + b * GBUF2;
        cp16(base + arow,         gAh + kk);
        cp16(base + A64BY + arow, gAl + kk);
#pragma unroll
        for (int rep = 0; rep < 3; rep++) {
            int task = tid + rep * 256;       // 768 tasks: 192 rows x 4 chunks
            int rt = task >> 2;
            int q = (task & 3) * 8;
            int gate = rt / 64, col = rt - gate * 64;
            size_t srcoff = (size_t)(gate * HDIM + n0 + col) * HDIM + kk + q;
            cp16(base + 2 * A64BY + rt * (LDT2 * 2) + q * 2, Whp + srcoff);
        }
    };

    wmma::fragment<wmma::accumulator, 16, 16, 16, float> cf[2][3];
#pragma unroll
    for (int i = 0; i < 2; i++)
#pragma unroll
        for (int j = 0; j < 3; j++) wmma::fill_fragment(cf[i][j], 0.0f);

    issue(0, 0); CP_COMMIT();

    const int ntile = HDIM / 32;   // 8
    for (int it = 0; it < ntile; it++) {
        const int b = it & 1;
        if (it + 1 < ntile) { issue(it + 1, b ^ 1); CP_COMMIT(); CP_WAIT(1); }
        else                { CP_WAIT(0); }
        __syncthreads();

        const h16* tAh = reinterpret_cast<const h16*>(sm + b * GBUF2);
        const h16* tAl = tAh + 64 * LDT2;
        const h16* tB  = tAl + 64 * LDT2;

#pragma unroll
        for (int ks = 0; ks < 32; ks += 16) {
            wmma::fragment<wmma::matrix_a, 16, 16, 16, h16, wmma::row_major> ah[2], al[2];
#pragma unroll
            for (int i = 0; i < 2; i++) {
                wmma::load_matrix_sync(ah[i], tAh + (wm * 32 + i * 16) * LDT2 + ks, LDT2);
                wmma::load_matrix_sync(al[i], tAl + (wm * 32 + i * 16) * LDT2 + ks, LDT2);
            }
#pragma unroll
            for (int j = 0; j < 3; j++) {
                wmma::fragment<wmma::matrix_b, 16, 16, 16, h16, wmma::col_major> bh;
                wmma::load_matrix_sync(bh, tB + (wn * 48 + j * 16) * LDT2 + ks, LDT2);
#pragma unroll
                for (int i = 0; i < 2; i++) {
                    wmma::mma_sync(cf[i][j], ah[i], bh, cf[i][j]);
                    wmma::mma_sync(cf[i][j], al[i], bh, cf[i][j]);
                }
            }
        }
        __syncthreads();
    }

    // stash gates to scratch [64][192]
#pragma unroll
    for (int i = 0; i < 2; i++)
#pragma unroll
        for (int j = 0; j < 3; j++)
            wmma::store_matrix_sync(&scratch[(wm * 32 + i * 16) * 192 + wn * 48 + j * 16],
                                    cf[i][j], 192, wmma::mem_row_major);
    __syncthreads();

    // fused GRU epilogue: 64 rows x 64 cols -> 1024 float4 tasks
#pragma unroll
    for (int itx = 0; itx < 4; itx++) {
        int task = tid + itx * 256;
        int r = task >> 4;
        int c4 = (task & 15) * 4;
        const int row = m0 + r;
        const int j = n0 + c4;
        const float* srow2 = &scratch[r * 192];
        float gr[4], gz[4], gn[4];
        *reinterpret_cast<float4*>(gr) = *reinterpret_cast<const float4*>(srow2 + c4);
        *reinterpret_cast<float4*>(gz) = *reinterpret_cast<const float4*>(srow2 + 64 + c4);
        *reinterpret_cast<float4*>(gn) = *reinterpret_cast<const float4*>(srow2 + 128 + c4);
        float br[4], bz[4], bn[4], xr[4], xz[4], xn[4], hh[4];
        *reinterpret_cast<float4*>(br) = *reinterpret_cast<const float4*>(bhh + j);
        *reinterpret_cast<float4*>(bz) = *reinterpret_cast<const float4*>(bhh + HDIM + j);
        *reinterpret_cast<float4*>(bn) = *reinterpret_cast<const float4*>(bhh + 2 * HDIM + j);
        const float* gxp = gx + ((size_t)row * T + t) * GDIM;
        *reinterpret_cast<float4*>(xr) = *reinterpret_cast<const float4*>(gxp + j);
        *reinterpret_cast<float4*>(xz) = *reinterpret_cast<const float4*>(gxp + HDIM + j);
        *reinterpret_cast<float4*>(xn) = *reinterpret_cast<const float4*>(gxp + 2 * HDIM + j);
        *reinterpret_cast<float4*>(hh) = *reinterpret_cast<const float4*>(hin + (size_t)row * HDIM + j);
        float o[4];
        h16 hb[4], lb[4];
#pragma unroll
        for (int u = 0; u < 4; u++) {
            float rr = sigmoid_f(xr[u] + gr[u] + br[u]);
            float zz = sigmoid_f(xz[u] + gz[u] + bz[u]);
            float nv = tanhf(xn[u] + rr * (gn[u] + bn[u]));
            float h = (1.f - zz) * nv + zz * hh[u];
            o[u] = h;
            hb[u] = __float2half_rn(h);
            lb[u] = __float2half_rn(h - __half2float(hb[u]));
        }
        *reinterpret_cast<float4*>(hout + (size_t)row * HDIM + j) = *reinterpret_cast<float4*>(o);
        *reinterpret_cast<ull*>(HhiOut + (size_t)row * HDIM + j) = *reinterpret_cast<ull*>(hb);
        *reinterpret_cast<ull*>(HloOut + (size_t)row * HDIM + j) = *reinterpret_cast<ull*>(lb);
    }
}

// ---------------- t=0 GRU steps ----------------
__global__ void gru_init_split(const float* __restrict__ gx, const float* __restrict__ bhh,
                               float* __restrict__ hout, h16* __restrict__ hi,
                               h16* __restrict__ lo, int Mseq, int T)
{
    int i = blockIdx.x * blockDim.x + threadIdx.x;
    if (i >= Mseq * HDIM) return;
    int seq = i >> 8, j = i & 255;
    const float* g = gx + (size_t)seq * T * GDIM;
    float r = sigmoid_f(g[j] + bhh[j]);
    float z = sigmoid_f(g[j + HDIM] + bhh[j + HDIM]);
    float n = tanhf(g[j + 2 * HDIM] + r * bhh[j + 2 * HDIM]);
    float h = (1.f - z) * n;
    hout[i] = h;
    h16 hb = __float2half_rn(h);
    hi[i] = hb;
    lo[i] = __float2half_rn(h - __half2float(hb));
}

__global__ void gru_init_plain(const float* __restrict__ gx, const float* __restrict__ bhh,
                               float* __restrict__ hout, int Mseq, int T)
{
    int i = blockIdx.x * blockDim.x + threadIdx.x;
    if (i >= Mseq * HDIM) return;
    int seq = i >> 8, j = i & 255;
    const float* g = gx + (size_t)seq * T * GDIM;
    float r = sigmoid_f(g[j] + bhh[j]);
    float z = sigmoid_f(g[j + HDIM] + bhh[j + HDIM]);
    float n = tanhf(g[j + 2 * HDIM] + r * bhh[j + 2 * HDIM]);
    hout[i] = (1.f - z) * n;
}

// ---------------- fused multi-step GRU tail ----------------------------------
// One launch runs steps t=1..T-1 for all sequences. Each CTA owns NSEQ seqs;
// h lives in smem; weights (fp16) stream from L2 each step. No cross-CTA deps.
template <int NSEQ>
__global__ __launch_bounds__(256)
void gru_tail_fused(const float* __restrict__ h0, const h16* __restrict__ W16,
                    const float* __restrict__ bhh, const float* __restrict__ gx,
                    int T, float* __restrict__ hfinal)
{
    __shared__ float hs[HDIM][NSEQ];
    const int tid = threadIdx.x;
    const int seq0 = blockIdx.x * NSEQ;

    for (int i = tid; i < NSEQ * HDIM; i += 256) {
        int s = i / HDIM, k = i - s * HDIM;
        hs[k][s] = h0[(size_t)(seq0 + s) * HDIM + k];
    }
    __syncthreads();

    const int j = tid;   // one h-column per thread
    const h16* wr = W16 + (size_t)j * HDIM;
    const h16* wz = W16 + (size_t)(HDIM + j) * HDIM;
    const h16* wn_ = W16 + (size_t)(2 * HDIM + j) * HDIM;
    const float br = bhh[j], bz = bhh[HDIM + j], bn = bhh[2 * HDIM + j];

    for (int t = 1; t < T; t++) {
        float ar[NSEQ], az[NSEQ], an[NSEQ];
#pragma unroll
        for (int s = 0; s < NSEQ; s++) { ar[s] = 0.f; az[s] = 0.f; an[s] = 0.f; }

#pragma unroll 4
        for (int k = 0; k < HDIM; k += 8) {
            uint4 vr = *reinterpret_cast<const uint4*>(wr + k);
            uint4 vz = *reinterpret_cast<const uint4*>(wz + k);
            uint4 vn = *reinterpret_cast<const uint4*>(wn_ + k);
            const h16* pr = reinterpret_cast<const h16*>(&vr);
            const h16* pz = reinterpret_cast<const h16*>(&vz);
            const h16* pn = reinterpret_cast<const h16*>(&vn);
#pragma unroll
            for (int u = 0; u < 8; u++) {
                float fr = __half2float(pr[u]);
                float fz = __half2float(pz[u]);
                float fn = __half2float(pn[u]);
#pragma unroll
                for (int s = 0; s < NSEQ; s++) {
                    float hv = hs[k + u][s];
                    ar[s] = fmaf(fr, hv, ar[s]);
                    az[s] = fmaf(fz, hv, az[s]);
                    an[s] = fmaf(fn, hv, an[s]);
                }
            }
        }
        __syncthreads();   // all dot-product reads of hs done

        float hnew[NSEQ];
#pragma unroll
        for (int s = 0; s < NSEQ; s++) {
            const float* gxp = gx + ((size_t)(seq0 + s) * T + t) * GDIM;
            float r = sigmoid_f(gxp[j] + ar[s] + br);
            float z = sigmoid_f(gxp[HDIM + j] + az[s] + bz);
            float n = tanhf(gxp[2 * HDIM + j] + r * (an[s] + bn));
            hnew[s] = (1.f - z) * n + z * hs[j][s];
        }
#pragma unroll
        for (int s = 0; s < NSEQ; s++) hs[j][s] = hnew[s];
        __syncthreads();
    }

    for (int i = tid; i < NSEQ * HDIM; i += 256) {
        int s = i / HDIM, k = i - s * HDIM;
        hfinal[(size_t)(seq0 + s) * HDIM + k] = hs[k][s];
    }
}

// ---------------- fp32 SGEMM (review gx) ----------------
#define BM 128
#define BN 128
#define BK 8
__global__ __launch_bounds__(256, 2)
void sgemm_f32x2(const float* __restrict__ A, const float* __restrict__ W,
                 const float* __restrict__ bias, float* __restrict__ C,
                 int M, int K, int N)
{
    __shared__ float As[2][BK][BM];
    __shared__ float Bs[2][BK][BN];
    const int tid = threadIdx.x;
    const int m0 = blockIdx.y * BM;
    const int n0 = blockIdx.x * BN;
    const int a_m = tid & 127, a_kq = tid >> 7;
    const int b_n = tid >> 1,  b_kq = tid & 1;
    const bool a_valid = (m0 + a_m) < M;
    const float* Arow = A + (size_t)(a_valid ? (m0 + a_m) : 0) * K;
    const float* Brow = W + (size_t)(n0 + b_n) * K;
    const int tx = tid & 15, ty = tid >> 4;

    ull acc2[8][4];
#pragma unroll
    for (int i = 0; i < 8; i++)
#pragma unroll
        for (int j = 0; j < 4; j++) acc2[i][j] = 0ull;

    float4 av = make_float4(0.f, 0.f, 0.f, 0.f);
    if (a_valid) av = *reinterpret_cast<const float4*>(Arow + a_kq * 4);
    float4 bv = *reinterpret_cast<const float4*>(Brow + b_kq * 4);
    As[0][a_kq * 4 + 0][a_m] = av.x;  As[0][a_kq * 4 + 1][a_m] = av.y;
    As[0][a_kq * 4 + 2][a_m] = av.z;  As[0][a_kq * 4 + 3][a_m] = av.w;
    Bs[0][b_kq * 4 + 0][b_n] = bv.x;  Bs[0][b_kq * 4 + 1][b_n] = bv.y;
    Bs[0][b_kq * 4 + 2][b_n] = bv.z;  Bs[0][b_kq * 4 + 3][b_n] = bv.w;
    __syncthreads();

    int buf = 0;
    for (int kk = 0; kk < K; kk += BK) {
        const bool has_next = (kk + BK) < K;
        if (has_next) {
            if (a_valid) av = *reinterpret_cast<const float4*>(Arow + kk + BK + a_kq * 4);
            bv = *reinterpret_cast<const float4*>(Brow + kk + BK + b_kq * 4);
        }
#pragma unroll
        for (int k = 0; k < BK; k++) {
            float4 a0 = *reinterpret_cast<const float4*>(&As[buf][k][ty * 8]);
            float4 a1 = *reinterpret_cast<const float4*>(&As[buf][k][ty * 8 + 4]);
            ulonglong2 bq0 = *reinterpret_cast<const ulonglong2*>(&Bs[buf][k][tx * 8]);
            ulonglong2 bq1 = *reinterpret_cast<const ulonglong2*>(&Bs[buf][k][tx * 8 + 4]);
            ull bp[4] = {bq0.x, bq0.y, bq1.x, bq1.y};
            float a[8] = {a0.x, a0.y, a0.z, a0.w, a1.x, a1.y, a1.z, a1.w};
#pragma unroll
            for (int i = 0; i < 8; i++) {
                ull ad = dup2(a[i]);
#pragma unroll
                for (int j = 0; j < 4; j++) ffma2(acc2[i][j], ad, bp[j]);
            }
        }
        if (has_next) {
            int nb = buf ^ 1;
            As[nb][a_kq * 4 + 0][a_m] = av.x;  As[nb][a_kq * 4 + 1][a_m] = av.y;
            As[nb][a_kq * 4 + 2][a_m] = av.z;  As[nb][a_kq * 4 + 3][a_m] = av.w;
            Bs[nb][b_kq * 4 + 0][b_n] = bv.x;  Bs[nb][b_kq * 4 + 1][b_n] = bv.y;
            Bs[nb][b_kq * 4 + 2][b_n] = bv.z;  Bs[nb][b_kq * 4 + 3][b_n] = bv.w;
            __syncthreads();
            buf = nb;
        }
    }
#pragma unroll
    for (int i = 0; i < 8; i++) {
        int row = m0 + ty * 8 + i;
        if (row >= M) continue;
#pragma unroll
        for (int j = 0; j < 4; j++) {
            int col = n0 + tx * 8 + j * 2;
            float2 p = unpack2(acc2[i][j]);
            float2 bb = *reinterpret_cast<const float2*>(bias + col);
            float2 o; o.x = p.x + bb.x; o.y = p.y + bb.y;
            *reinterpret_cast<float2*>(C + (size_t)row * N + col) = o;
        }
    }
}

// ---------------- MLP ----------------
__global__ __launch_bounds__(128)
void mlp_kernel(const float* __restrict__ X,
                const float* __restrict__ W1, const float* __restrict__ b1,
                const float* __restrict__ W2, const float* __restrict__ b2,
                float* __restrict__ out)
{
    const int row = blockIdx.x;
    const int i = threadIdx.x;
    __shared__ float xs[HDIM];
    __shared__ float red[4];
    xs[i]       = X[(size_t)row * HDIM + i];
    xs[i + 128] = X[(size_t)row * HDIM + i + 128];
    __syncthreads();
    const float* w = W1 + (size_t)i * HDIM;
    float acc = b1[i];
#pragma unroll 8
    for (int k = 0; k < HDIM; k += 4) {
        float4 wv = *reinterpret_cast<const float4*>(w + k);
        acc = fmaf(wv.x, xs[k], acc);
        acc = fmaf(wv.y, xs[k + 1], acc);
        acc = fmaf(wv.z, xs[k + 2], acc);
        acc = fmaf(wv.w, xs[k + 3], acc);
    }
    const float scale = 1.0507009873554805f;
    const float alpha = 1.6732632423543772f;
    float s = scale * (acc > 0.f ? acc : alpha * (expf(acc) - 1.f));
    float v = s * W2[i];
#pragma unroll
    for (int off = 16; off > 0; off >>= 1)
        v += __shfl_down_sync(0xffffffffu, v, off);
    if ((i & 31) == 0) red[i >> 5] = v;
    __syncthreads();
    if (i == 0) out[row] = red[0] + red[1] + red[2] + red[3] + b2[0];
}

// ---------------- host orchestration ----------------
extern "C" void kernel_launch(void* const* d_in, const int* in_sizes, int n_in,
                              void* d_out, int out_size)
{
    (void)in_sizes; (void)n_in; (void)out_size;

    const int*   idx    = (const int*)  d_in[0];
    const float* emb    = (const float*)d_in[1];
    const float* w_Wih  = (const float*)d_in[2];
    const float* w_Whh  = (const float*)d_in[3];
    const float* w_bih  = (const float*)d_in[4];
    const float* w_bhh  = (const float*)d_in[5];
    const float* s_Wih  = (const float*)d_in[6];
    const float* s_Whh  = (const float*)d_in[7];
    const float* s_bih  = (const float*)d_in[8];
    const float* s_bhh  = (const float*)d_in[9];
    const float* r_Wih  = (const float*)d_in[10];
    const float* r_Whh  = (const float*)d_in[11];
    const float* r_bih  = (const float*)d_in[12];
    const float* r_bhh  = (const float*)d_in[13];
    const float* rfc_W1 = (const float*)d_in[14];
    const float* rfc_b1 = (const float*)d_in[15];
    const float* rfc_W2 = (const float*)d_in[16];
    const float* rfc_b2 = (const float*)d_in[17];
    const float* pfc_W1 = (const float*)d_in[18];
    const float* pfc_b1 = (const float*)d_in[19];
    const float* pfc_W2 = (const float*)d_in[20];
    const float* pfc_b2 = (const float*)d_in[21];
    float* out = (float*)d_out;

    float *GXw, *GXs, *GXr, *HwA, *HwB, *HsA, *HsB, *HrA, *HrB;
    h16 *Xhi, *Xlo, *WihH, *WhhH, *WsH, *WshhH, *WrhhH;
    h16 *SHiA, *SHiB, *SLoA, *SLoB;
    cudaGetSymbolAddress((void**)&GXw, g_GXw);
    cudaGetSymbolAddress((void**)&GXs, g_GXs);
    cudaGetSymbolAddress((void**)&GXr, g_GXr);
    cudaGetSymbolAddress((void**)&HwA, g_HwA);
    cudaGetSymbolAddress((void**)&HwB, g_HwB);
    cudaGetSymbolAddress((void**)&HsA, g_HsA);
    cudaGetSymbolAddress((void**)&HsB, g_HsB);
    cudaGetSymbolAddress((void**)&HrA, g_HrA);
    cudaGetSymbolAddress((void**)&HrB, g_HrB);
    cudaGetSymbolAddress((void**)&Xhi, g_Xhi);
    cudaGetSymbolAddress((void**)&Xlo, g_Xlo);
    cudaGetSymbolAddress((void**)&WihH, g_WihH);
    cudaGetSymbolAddress((void**)&WhhH, g_WhhH);
    cudaGetSymbolAddress((void**)&WsH, g_WsH);
    cudaGetSymbolAddress((void**)&WshhH, g_WshhH);
    cudaGetSymbolAddress((void**)&WrhhH, g_WrhhH);
    cudaGetSymbolAddress((void**)&SHiA, g_SHiA);
    cudaGetSymbolAddress((void**)&SHiB, g_SHiB);
    cudaGetSymbolAddress((void**)&SLoA, g_SLoA);
    cudaGetSymbolAddress((void**)&SLoB, g_SLoB);

    const int SMEM_GEMM = 2 * GEMM_BUF;   // 73728 (>= 64KB scratch)
    const int SMEM_GRU  = 2 * GBUF2;      // 61440 (>= 48KB scratch)
    cudaFuncSetAttribute(gemm_wmma2, cudaFuncAttributeMaxDynamicSharedMemorySize, SMEM_GEMM);
    cudaFuncSetAttribute(gru_step_wmma, cudaFuncAttributeMaxDynamicSharedMemorySize, SMEM_GRU);

    // ---- prep ----
    split_w_single<<<(GDIM * KPAD + 255) / 256, 256>>>(w_Wih, WihH, GDIM, EDIM, KPAD);
    split_w_single<<<(GDIM * HDIM + 255) / 256, 256>>>(w_Whh, WhhH, GDIM, HDIM, HDIM);
    split_w_single<<<(GDIM * HDIM + 255) / 256, 256>>>(s_Wih, WsH, GDIM, HDIM, HDIM);
    split_w_single<<<(GDIM * HDIM + 255) / 256, 256>>>(s_Whh, WshhH, GDIM, HDIM, HDIM);
    split_w_single<<<(GDIM * HDIM + 255) / 256, 256>>>(r_Whh, WrhhH, GDIM, HDIM, HDIM);
    gather_split_kernel<<<(int)(((size_t)MW * KP4 + 255) / 256), 256>>>(idx, emb, Xhi, Xlo);

    // ---- word level: gx ----
    gemm_wmma2<<<dim3(GDIM / 128, MW / 128), 256, SMEM_GEMM>>>(Xhi, Xlo, WihH,
                                                               w_bih, GXw, KPAD, GDIM);

    float* hw[2] = {HwA, HwB};
    h16*   shi[2] = {SHiA, SHiB};
    h16*   slo[2] = {SLoA, SLoB};
    int cw = 0;
    gru_init_split<<<(NW * HDIM + 255) / 256, 256>>>(GXw, w_bhh, hw[0], shi[0], slo[0],
                                                     NW, TWSTEPS);
    for (int t = 1; t < TWSTEPS; t++) {
        gru_step_wmma<<<dim3(HDIM / 64, NW / 64), 256, SMEM_GRU>>>(
            hw[cw], shi[cw], slo[cw], WhhH, w_bhh, GXw, TWSTEPS, t,
            hw[1 - cw], shi[1 - cw], slo[1 - cw]);
        cw = 1 - cw;
    }

    // ---- sentence level ----
    gemm_wmma2<<<dim3(GDIM / 128, (NS * TSSTEPS) / 128), 256, SMEM_GEMM>>>(
        shi[cw], slo[cw], WsH, s_bih, GXs, HDIM, GDIM);

    gru_init_plain<<<(NS * HDIM + 255) / 256, 256>>>(GXs, s_bhh, HsA, NS, TSSTEPS);
    gru_tail_fused<4><<<NS / 4, 256>>>(HsA, WshhH, s_bhh, GXs, TSSTEPS, HsB);
    const float* p_batch = HsB;

    // r_stars -> out[16 .. 272)
    mlp_kernel<<<NS, 128>>>(p_batch, rfc_W1, rfc_b1, rfc_W2, rfc_b2, out + NR);

    // ---- review level ----
    {
        dim3 grid(GDIM / BN, (NR * TRSTEPS + BM - 1) / BM);
        sgemm_f32x2<<<grid, 256>>>(p_batch, r_Wih, r_bih, GXr, NR * TRSTEPS, HDIM, GDIM);
    }
    gru_init_plain<<<(NR * HDIM + 255) / 256, 256>>>(GXr, r_bhh, HrA, NR, TRSTEPS);
    gru_tail_fused<1><<<NR, 256>>>(HrA, WrhhH, r_bhh, GXr, TRSTEPS, HrB);

    // b_stars -> out[0 .. 16)
    mlp_kernel<<<NR, 128>>>(HrB, pfc_W1, pfc_b1, pfc_W2, pfc_b2, out);
}

// round 9
// speedup vs baseline: 3.8547x; 1.1438x over previous
#include <cuda_runtime.h>
#include <cuda_fp16.h>
#include <mma.h>
#include <math.h>
#include <stdint.h>

using namespace nvcuda;

// ---------------- problem dims ----------------
#define HDIM 256
#define GDIM 768           // 3*H
#define EDIM 200
#define NW 4096            // B*R*S word sequences
#define TWSTEPS 32
#define NS 256             // B*R
#define TSSTEPS 16
#define NR 16              // B
#define TRSTEPS 16
#define MW (NW * TWSTEPS)  // 131072 word-gx rows
#define KPAD 224           // padded K for word gx (EDIM=200 -> 224, %32)
#define KP4 (KPAD / 4)

typedef unsigned long long ull;
typedef __half h16;

// ---------------- scratch (static device globals) ----------------
__device__ float g_GXw[(size_t)MW * GDIM];             // 402 MB word input gates
__device__ float g_GXs[(size_t)NS * TSSTEPS * GDIM];
__device__ float g_GXr[(size_t)NR * TRSTEPS * GDIM];
__device__ float g_HwA[NW * HDIM], g_HwB[NW * HDIM];
__device__ float g_HsA[NS * HDIM], g_HsB[NS * HDIM];
__device__ float g_HrA[NR * HDIM], g_HrB[NR * HDIM];
// fp16 buffers (single-rounded)
__device__ __align__(16) h16 g_Xh[(size_t)MW * KPAD];
__device__ __align__(16) h16 g_WihH[GDIM * KPAD];
__device__ __align__(16) h16 g_WhhH[GDIM * HDIM];
__device__ __align__(16) h16 g_WsH [GDIM * HDIM];      // sentence Wih
__device__ __align__(16) h16 g_WshhH[GDIM * HDIM];     // sentence Whh (tail)
__device__ __align__(16) h16 g_WrhhH[GDIM * HDIM];     // review Whh (tail)
__device__ __align__(16) h16 g_SHiA[NW * HDIM], g_SHiB[NW * HDIM];

// ---------------- helpers ----------------
__device__ __forceinline__ float sigmoid_f(float x) { return 1.f / (1.f + expf(-x)); }
__device__ __forceinline__ ull pack2(float lo, float hi) {
    ull r; asm("mov.b64 %0, {%1, %2};" : "=l"(r) : "f"(lo), "f"(hi)); return r;
}
__device__ __forceinline__ ull dup2(float v) { return pack2(v, v); }
__device__ __forceinline__ void ffma2(ull& d, ull a, ull b) {
    asm("fma.rn.f32x2 %0, %1, %2, %3;" : "=l"(d) : "l"(a), "l"(b), "l"(d));
}
__device__ __forceinline__ float2 unpack2(ull v) {
    float2 f; asm("mov.b64 {%0, %1}, %2;" : "=f"(f.x), "=f"(f.y) : "l"(v)); return f;
}
__device__ __forceinline__ void cp16(uint32_t s, const void* g) {
    asm volatile("cp.async.cg.shared.global [%0], [%1], 16;" :: "r"(s), "l"(g));
}
#define CP_COMMIT() asm volatile("cp.async.commit_group;" ::: "memory")
#define CP_WAIT(n)  asm volatile("cp.async.wait_group %0;" :: "n"(n) : "memory")

// ---------------- prep kernels ----------------
__global__ void split_w_single(const float* __restrict__ src, h16* __restrict__ dst,
                               int rows, int cs, int cd)
{
    int i = blockIdx.x * blockDim.x + threadIdx.x;
    if (i >= rows * cd) return;
    int r = i / cd, c = i - r * cd;
    float v = (c < cs) ? src[(size_t)r * cs + c] : 0.f;
    dst[i] = __float2half_rn(v);
}

__global__ void gather_h16_kernel(const int* __restrict__ idx, const float* __restrict__ emb,
                                  h16* __restrict__ hi)
{
    size_t id = (size_t)blockIdx.x * blockDim.x + threadIdx.x;
    if (id >= (size_t)MW * KP4) return;
    int row = (int)(id / KP4);
    int c4 = (int)(id - (size_t)row * KP4) * 4;
    float4 v = make_float4(0.f, 0.f, 0.f, 0.f);
    if (c4 < EDIM)
        v = *reinterpret_cast<const float4*>(emb + (size_t)idx[row] * EDIM + c4);
    h16 hb[4];
    hb[0] = __float2half_rn(v.x); hb[1] = __float2half_rn(v.y);
    hb[2] = __float2half_rn(v.z); hb[3] = __float2half_rn(v.w);
    *reinterpret_cast<ull*>(hi + (size_t)row * KPAD + c4) = *reinterpret_cast<ull*>(hb);
}

// ---------------- wmma fp16 single-pass GEMM: C = A@W^T + bias --------------
// CTA 128x128, 8 warps 32x64, occupancy 2.
#define LDT2 48
#define TBY (128 * LDT2 * 2)         // 12288B per matrix tile
#define GEMM_BUF (2 * TBY)           // A, B

__global__ __launch_bounds__(256, 2)
void gemm_wmma2(const h16* __restrict__ Ahp, const h16* __restrict__ Whp,
                const float* __restrict__ bias, float* __restrict__ C,
                int K, int N)
{
    extern __shared__ __align__(128) char sm[];
    const uint32_t sbase = (uint32_t)__cvta_generic_to_shared(sm);
    float* scratch = reinterpret_cast<float*>(sm);

    const int tid = threadIdx.x;
    const int wid = tid >> 5;
    const int m0 = blockIdx.y * 128, n0 = blockIdx.x * 128;
    const int wm = wid & 3, wn = wid >> 2;

    const int lr = tid >> 1;
    const int lq = (tid & 1) * 16;

    const h16* gA = Ahp + (size_t)(m0 + lr) * K + lq;
    const h16* gB = Whp + (size_t)(n0 + lr) * K + lq;
    const uint32_t srow = lr * LDT2 * 2 + lq * 2;

    const int ntile = K / 32;

    wmma::fragment<wmma::accumulator, 16, 16, 16, float> cf[2][4];
#pragma unroll
    for (int i = 0; i < 2; i++)
#pragma unroll
        for (int j = 0; j < 4; j++) wmma::fill_fragment(cf[i][j], 0.0f);

    auto issue = [&](int it, int b) {
        const int kk = it * 32;
        uint32_t base = sbase + b * GEMM_BUF;
        cp16(base + srow,            gA + kk);
        cp16(base + srow + 16,       gA + kk + 8);
        cp16(base + TBY + srow,      gB + kk);
        cp16(base + TBY + srow + 16, gB + kk + 8);
    };

    issue(0, 0); CP_COMMIT();

    for (int it = 0; it < ntile; it++) {
        const int b = it & 1;
        if (it + 1 < ntile) { issue(it + 1, b ^ 1); CP_COMMIT(); CP_WAIT(1); }
        else                { CP_WAIT(0); }
        __syncthreads();

        const h16* tA = reinterpret_cast<const h16*>(sm + b * GEMM_BUF);
        const h16* tB = tA + 128 * LDT2;

#pragma unroll
        for (int ks = 0; ks < 32; ks += 16) {
            wmma::fragment<wmma::matrix_a, 16, 16, 16, h16, wmma::row_major> ah[2];
            wmma::fragment<wmma::matrix_b, 16, 16, 16, h16, wmma::col_major> bh[4];
#pragma unroll
            for (int i = 0; i < 2; i++)
                wmma::load_matrix_sync(ah[i], tA + (wm * 32 + i * 16) * LDT2 + ks, LDT2);
#pragma unroll
            for (int j = 0; j < 4; j++)
                wmma::load_matrix_sync(bh[j], tB + (wn * 64 + j * 16) * LDT2 + ks, LDT2);
#pragma unroll
            for (int i = 0; i < 2; i++)
#pragma unroll
                for (int j = 0; j < 4; j++)
                    wmma::mma_sync(cf[i][j], ah[i], bh[j], cf[i][j]);
        }
        __syncthreads();
    }

#pragma unroll
    for (int i = 0; i < 2; i++)
#pragma unroll
        for (int j = 0; j < 4; j++)
            wmma::store_matrix_sync(&scratch[(wm * 32 + i * 16) * 128 + wn * 64 + j * 16],
                                    cf[i][j], 128, wmma::mem_row_major);
    __syncthreads();

#pragma unroll
    for (int itx = 0; itx < 16; itx++) {
        int idx4 = tid + itx * 256;
        int r = idx4 >> 5;
        int c4 = (idx4 & 31) * 4;
        float4 v = *reinterpret_cast<const float4*>(&scratch[r * 128 + c4]);
        float4 b = *reinterpret_cast<const float4*>(&bias[n0 + c4]);
        v.x += b.x; v.y += b.y; v.z += b.z; v.w += b.w;
        *reinterpret_cast<float4*>(&C[(size_t)(m0 + r) * N + n0 + c4]) = v;
    }
}

// ---------------- fused wmma GRU step (64 rows x 64 h-cols x 3 gates) -------
// grid = (HDIM/64 = 4, NW/64 = 64) = 256 CTAs, occupancy 2, single-pass fp16.
#define GB_ROWS 192
#define A64BY (64 * LDT2 * 2)       // 6144
#define B64BY (GB_ROWS * LDT2 * 2)  // 18432
#define GBUF2 (A64BY + B64BY)       // 24576 per buffer

__global__ __launch_bounds__(256, 2)
void gru_step_wmma(const float* __restrict__ hin,
                   const h16* __restrict__ Hhi, const h16* __restrict__ Whp,
                   const float* __restrict__ bhh, const float* __restrict__ gx,
                   int T, int t, float* __restrict__ hout,
                   h16* __restrict__ HhiOut)
{
    extern __shared__ __align__(128) char sm[];
    const uint32_t sbase = (uint32_t)__cvta_generic_to_shared(sm);
    float* scratch = reinterpret_cast<float*>(sm);   // 64x192 fp32 after compute

    const int tid = threadIdx.x;
    const int wid = tid >> 5;
    const int n0 = blockIdx.x * 64;
    const int m0 = blockIdx.y * 64;
    const int wm = wid & 1;        // 2 m-tiles of 32 rows
    const int wn = wid >> 1;       // 4 n-tiles of 48 cols (of 192)

    const int lr = tid >> 2;             // 0..63
    const int lq = (tid & 3) * 8;
    const h16* gAh = Hhi + (size_t)(m0 + lr) * HDIM + lq;
    const uint32_t arow = lr * (LDT2 * 2) + lq * 2;

    auto issue = [&](int it, int b) {
        const int kk = it * 32;
        uint32_t base = sbase + b * GBUF2;
        cp16(base + arow, gAh + kk);
#pragma unroll
        for (int rep = 0; rep < 3; rep++) {
            int task = tid + rep * 256;       // 768 tasks: 192 rows x 4 chunks
            int rt = task >> 2;
            int q = (task & 3) * 8;
            int gate = rt / 64, col = rt - gate * 64;
            size_t srcoff = (size_t)(gate * HDIM + n0 + col) * HDIM + kk + q;
            cp16(base + A64BY + rt * (LDT2 * 2) + q * 2, Whp + srcoff);
        }
    };

    wmma::fragment<wmma::accumulator, 16, 16, 16, float> cf[2][3];
#pragma unroll
    for (int i = 0; i < 2; i++)
#pragma unroll
        for (int j = 0; j < 3; j++) wmma::fill_fragment(cf[i][j], 0.0f);

    issue(0, 0); CP_COMMIT();

    const int ntile = HDIM / 32;   // 8
    for (int it = 0; it < ntile; it++) {
        const int b = it & 1;
        if (it + 1 < ntile) { issue(it + 1, b ^ 1); CP_COMMIT(); CP_WAIT(1); }
        else                { CP_WAIT(0); }
        __syncthreads();

        const h16* tA = reinterpret_cast<const h16*>(sm + b * GBUF2);
        const h16* tB = tA + 64 * LDT2;

#pragma unroll
        for (int ks = 0; ks < 32; ks += 16) {
            wmma::fragment<wmma::matrix_a, 16, 16, 16, h16, wmma::row_major> ah[2];
#pragma unroll
            for (int i = 0; i < 2; i++)
                wmma::load_matrix_sync(ah[i], tA + (wm * 32 + i * 16) * LDT2 + ks, LDT2);
#pragma unroll
            for (int j = 0; j < 3; j++) {
                wmma::fragment<wmma::matrix_b, 16, 16, 16, h16, wmma::col_major> bh;
                wmma::load_matrix_sync(bh, tB + (wn * 48 + j * 16) * LDT2 + ks, LDT2);
#pragma unroll
                for (int i = 0; i < 2; i++)
                    wmma::mma_sync(cf[i][j], ah[i], bh, cf[i][j]);
            }
        }
        __syncthreads();
    }

    // stash gates to scratch [64][192]
#pragma unroll
    for (int i = 0; i < 2; i++)
#pragma unroll
        for (int j = 0; j < 3; j++)
            wmma::store_matrix_sync(&scratch[(wm * 32 + i * 16) * 192 + wn * 48 + j * 16],
                                    cf[i][j], 192, wmma::mem_row_major);
    __syncthreads();

    // fused GRU epilogue: 64 rows x 64 cols -> 1024 float4 tasks
#pragma unroll
    for (int itx = 0; itx < 4; itx++) {
        int task = tid + itx * 256;
        int r = task >> 4;
        int c4 = (task & 15) * 4;
        const int row = m0 + r;
        const int j = n0 + c4;
        const float* srow2 = &scratch[r * 192];
        float gr[4], gz[4], gn[4];
        *reinterpret_cast<float4*>(gr) = *reinterpret_cast<const float4*>(srow2 + c4);
        *reinterpret_cast<float4*>(gz) = *reinterpret_cast<const float4*>(srow2 + 64 + c4);
        *reinterpret_cast<float4*>(gn) = *reinterpret_cast<const float4*>(srow2 + 128 + c4);
        float br[4], bz[4], bn[4], xr[4], xz[4], xn[4], hh[4];
        *reinterpret_cast<float4*>(br) = *reinterpret_cast<const float4*>(bhh + j);
        *reinterpret_cast<float4*>(bz) = *reinterpret_cast<const float4*>(bhh + HDIM + j);
        *reinterpret_cast<float4*>(bn) = *reinterpret_cast<const float4*>(bhh + 2 * HDIM + j);
        const float* gxp = gx + ((size_t)row * T + t) * GDIM;
        *reinterpret_cast<float4*>(xr) = *reinterpret_cast<const float4*>(gxp + j);
        *reinterpret_cast<float4*>(xz) = *reinterpret_cast<const float4*>(gxp + HDIM + j);
        *reinterpret_cast<float4*>(xn) = *reinterpret_cast<const float4*>(gxp + 2 * HDIM + j);
        *reinterpret_cast<float4*>(hh) = *reinterpret_cast<const float4*>(hin + (size_t)row * HDIM + j);
        float o[4];
        h16 hb[4];
#pragma unroll
        for (int u = 0; u < 4; u++) {
            float rr = sigmoid_f(xr[u] + gr[u] + br[u]);
            float zz = sigmoid_f(xz[u] + gz[u] + bz[u]);
            float nv = tanhf(xn[u] + rr * (gn[u] + bn[u]));
            float h = (1.f - zz) * nv + zz * hh[u];
            o[u] = h;
            hb[u] = __float2half_rn(h);
        }
        *reinterpret_cast<float4*>(hout + (size_t)row * HDIM + j) = *reinterpret_cast<float4*>(o);
        *reinterpret_cast<ull*>(HhiOut + (size_t)row * HDIM + j) = *reinterpret_cast<ull*>(hb);
    }
}

// ---------------- t=0 GRU steps ----------------
__global__ void gru_init_split(const float* __restrict__ gx, const float* __restrict__ bhh,
                               float* __restrict__ hout, h16* __restrict__ hi,
                               int Mseq, int T)
{
    int i = blockIdx.x * blockDim.x + threadIdx.x;
    if (i >= Mseq * HDIM) return;
    int seq = i >> 8, j = i & 255;
    const float* g = gx + (size_t)seq * T * GDIM;
    float r = sigmoid_f(g[j] + bhh[j]);
    float z = sigmoid_f(g[j + HDIM] + bhh[j + HDIM]);
    float n = tanhf(g[j + 2 * HDIM] + r * bhh[j + 2 * HDIM]);
    float h = (1.f - z) * n;
    hout[i] = h;
    hi[i] = __float2half_rn(h);
}

__global__ void gru_init_plain(const float* __restrict__ gx, const float* __restrict__ bhh,
                               float* __restrict__ hout, int Mseq, int T)
{
    int i = blockIdx.x * blockDim.x + threadIdx.x;
    if (i >= Mseq * HDIM) return;
    int seq = i >> 8, j = i & 255;
    const float* g = gx + (size_t)seq * T * GDIM;
    float r = sigmoid_f(g[j] + bhh[j]);
    float z = sigmoid_f(g[j + HDIM] + bhh[j + HDIM]);
    float n = tanhf(g[j + 2 * HDIM] + r * bhh[j + 2 * HDIM]);
    hout[i] = (1.f - z) * n;
}

// ---------------- fused multi-step GRU tail ----------------------------------
template <int NSEQ>
__global__ __launch_bounds__(256)
void gru_tail_fused(const float* __restrict__ h0, const h16* __restrict__ W16,
                    const float* __restrict__ bhh, const float* __restrict__ gx,
                    int T, float* __restrict__ hfinal)
{
    __shared__ float hs[HDIM][NSEQ];
    const int tid = threadIdx.x;
    const int seq0 = blockIdx.x * NSEQ;

    for (int i = tid; i < NSEQ * HDIM; i += 256) {
        int s = i / HDIM, k = i - s * HDIM;
        hs[k][s] = h0[(size_t)(seq0 + s) * HDIM + k];
    }
    __syncthreads();

    const int j = tid;
    const h16* wr = W16 + (size_t)j * HDIM;
    const h16* wz = W16 + (size_t)(HDIM + j) * HDIM;
    const h16* wn_ = W16 + (size_t)(2 * HDIM + j) * HDIM;
    const float br = bhh[j], bz = bhh[HDIM + j], bn = bhh[2 * HDIM + j];

    for (int t = 1; t < T; t++) {
        float ar[NSEQ], az[NSEQ], an[NSEQ];
#pragma unroll
        for (int s = 0; s < NSEQ; s++) { ar[s] = 0.f; az[s] = 0.f; an[s] = 0.f; }

#pragma unroll 4
        for (int k = 0; k < HDIM; k += 8) {
            uint4 vr = *reinterpret_cast<const uint4*>(wr + k);
            uint4 vz = *reinterpret_cast<const uint4*>(wz + k);
            uint4 vn = *reinterpret_cast<const uint4*>(wn_ + k);
            const h16* pr = reinterpret_cast<const h16*>(&vr);
            const h16* pz = reinterpret_cast<const h16*>(&vz);
            const h16* pn = reinterpret_cast<const h16*>(&vn);
#pragma unroll
            for (int u = 0; u < 8; u++) {
                float fr = __half2float(pr[u]);
                float fz = __half2float(pz[u]);
                float fn = __half2float(pn[u]);
#pragma unroll
                for (int s = 0; s < NSEQ; s++) {
                    float hv = hs[k + u][s];
                    ar[s] = fmaf(fr, hv, ar[s]);
                    az[s] = fmaf(fz, hv, az[s]);
                    an[s] = fmaf(fn, hv, an[s]);
                }
            }
        }
        __syncthreads();

        float hnew[NSEQ];
#pragma unroll
        for (int s = 0; s < NSEQ; s++) {
            const float* gxp = gx + ((size_t)(seq0 + s) * T + t) * GDIM;
            float r = sigmoid_f(gxp[j] + ar[s] + br);
            float z = sigmoid_f(gxp[HDIM + j] + az[s] + bz);
            float n = tanhf(gxp[2 * HDIM + j] + r * (an[s] + bn));
            hnew[s] = (1.f - z) * n + z * hs[j][s];
        }
#pragma unroll
        for (int s = 0; s < NSEQ; s++) hs[j][s] = hnew[s];
        __syncthreads();
    }

    for (int i = tid; i < NSEQ * HDIM; i += 256) {
        int s = i / HDIM, k = i - s * HDIM;
        hfinal[(size_t)(seq0 + s) * HDIM + k] = hs[k][s];
    }
}

// ---------------- fp32 SGEMM (review gx) ----------------
#define BM 128
#define BN 128
#define BK 8
__global__ __launch_bounds__(256, 2)
void sgemm_f32x2(const float* __restrict__ A, const float* __restrict__ W,
                 const float* __restrict__ bias, float* __restrict__ C,
                 int M, int K, int N)
{
    __shared__ float As[2][BK][BM];
    __shared__ float Bs[2][BK][BN];
    const int tid = threadIdx.x;
    const int m0 = blockIdx.y * BM;
    const int n0 = blockIdx.x * BN;
    const int a_m = tid & 127, a_kq = tid >> 7;
    const int b_n = tid >> 1,  b_kq = tid & 1;
    const bool a_valid = (m0 + a_m) < M;
    const float* Arow = A + (size_t)(a_valid ? (m0 + a_m) : 0) * K;
    const float* Brow = W + (size_t)(n0 + b_n) * K;
    const int tx = tid & 15, ty = tid >> 4;

    ull acc2[8][4];
#pragma unroll
    for (int i = 0; i < 8; i++)
#pragma unroll
        for (int j = 0; j < 4; j++) acc2[i][j] = 0ull;

    float4 av = make_float4(0.f, 0.f, 0.f, 0.f);
    if (a_valid) av = *reinterpret_cast<const float4*>(Arow + a_kq * 4);
    float4 bv = *reinterpret_cast<const float4*>(Brow + b_kq * 4);
    As[0][a_kq * 4 + 0][a_m] = av.x;  As[0][a_kq * 4 + 1][a_m] = av.y;
    As[0][a_kq * 4 + 2][a_m] = av.z;  As[0][a_kq * 4 + 3][a_m] = av.w;
    Bs[0][b_kq * 4 + 0][b_n] = bv.x;  Bs[0][b_kq * 4 + 1][b_n] = bv.y;
    Bs[0][b_kq * 4 + 2][b_n] = bv.z;  Bs[0][b_kq * 4 + 3][b_n] = bv.w;
    __syncthreads();

    int buf = 0;
    for (int kk = 0; kk < K; kk += BK) {
        const bool has_next = (kk + BK) < K;
        if (has_next) {
            if (a_valid) av = *reinterpret_cast<const float4*>(Arow + kk + BK + a_kq * 4);
            bv = *reinterpret_cast<const float4*>(Brow + kk + BK + b_kq * 4);
        }
#pragma unroll
        for (int k = 0; k < BK; k++) {
            float4 a0 = *reinterpret_cast<const float4*>(&As[buf][k][ty * 8]);
            float4 a1 = *reinterpret_cast<const float4*>(&As[buf][k][ty * 8 + 4]);
            ulonglong2 bq0 = *reinterpret_cast<const ulonglong2*>(&Bs[buf][k][tx * 8]);
            ulonglong2 bq1 = *reinterpret_cast<const ulonglong2*>(&Bs[buf][k][tx * 8 + 4]);
            ull bp[4] = {bq0.x, bq0.y, bq1.x, bq1.y};
            float a[8] = {a0.x, a0.y, a0.z, a0.w, a1.x, a1.y, a1.z, a1.w};
#pragma unroll
            for (int i = 0; i < 8; i++) {
                ull ad = dup2(a[i]);
#pragma unroll
                for (int j = 0; j < 4; j++) ffma2(acc2[i][j], ad, bp[j]);
            }
        }
        if (has_next) {
            int nb = buf ^ 1;
            As[nb][a_kq * 4 + 0][a_m] = av.x;  As[nb][a_kq * 4 + 1][a_m] = av.y;
            As[nb][a_kq * 4 + 2][a_m] = av.z;  As[nb][a_kq * 4 + 3][a_m] = av.w;
            Bs[nb][b_kq * 4 + 0][b_n] = bv.x;  Bs[nb][b_kq * 4 + 1][b_n] = bv.y;
            Bs[nb][b_kq * 4 + 2][b_n] = bv.z;  Bs[nb][b_kq * 4 + 3][b_n] = bv.w;
            __syncthreads();
            buf = nb;
        }
    }
#pragma unroll
    for (int i = 0; i < 8; i++) {
        int row = m0 + ty * 8 + i;
        if (row >= M) continue;
#pragma unroll
        for (int j = 0; j < 4; j++) {
            int col = n0 + tx * 8 + j * 2;
            float2 p = unpack2(acc2[i][j]);
            float2 bb = *reinterpret_cast<const float2*>(bias + col);
            float2 o; o.x = p.x + bb.x; o.y = p.y + bb.y;
            *reinterpret_cast<float2*>(C + (size_t)row * N + col) = o;
        }
    }
}

// ---------------- MLP ----------------
__global__ __launch_bounds__(128)
void mlp_kernel(const float* __restrict__ X,
                const float* __restrict__ W1, const float* __restrict__ b1,
                const float* __restrict__ W2, const float* __restrict__ b2,
                float* __restrict__ out)
{
    const int row = blockIdx.x;
    const int i = threadIdx.x;
    __shared__ float xs[HDIM];
    __shared__ float red[4];
    xs[i]       = X[(size_t)row * HDIM + i];
    xs[i + 128] = X[(size_t)row * HDIM + i + 128];
    __syncthreads();
    const float* w = W1 + (size_t)i * HDIM;
    float acc = b1[i];
#pragma unroll 8
    for (int k = 0; k < HDIM; k += 4) {
        float4 wv = *reinterpret_cast<const float4*>(w + k);
        acc = fmaf(wv.x, xs[k], acc);
        acc = fmaf(wv.y, xs[k + 1], acc);
        acc = fmaf(wv.z, xs[k + 2], acc);
        acc = fmaf(wv.w, xs[k + 3], acc);
    }
    const float scale = 1.0507009873554805f;
    const float alpha = 1.6732632423543772f;
    float s = scale * (acc > 0.f ? acc : alpha * (expf(acc) - 1.f));
    float v = s * W2[i];
#pragma unroll
    for (int off = 16; off > 0; off >>= 1)
        v += __shfl_down_sync(0xffffffffu, v, off);
    if ((i & 31) == 0) red[i >> 5] = v;
    __syncthreads();
    if (i == 0) out[row] = red[0] + red[1] + red[2] + red[3] + b2[0];
}

// ---------------- host orchestration ----------------
extern "C" void kernel_launch(void* const* d_in, const int* in_sizes, int n_in,
                              void* d_out, int out_size)
{
    (void)in_sizes; (void)n_in; (void)out_size;

    const int*   idx    = (const int*)  d_in[0];
    const float* emb    = (const float*)d_in[1];
    const float* w_Wih  = (const float*)d_in[2];
    const float* w_Whh  = (const float*)d_in[3];
    const float* w_bih  = (const float*)d_in[4];
    const float* w_bhh  = (const float*)d_in[5];
    const float* s_Wih  = (const float*)d_in[6];
    const float* s_Whh  = (const float*)d_in[7];
    const float* s_bih  = (const float*)d_in[8];
    const float* s_bhh  = (const float*)d_in[9];
    const float* r_Wih  = (const float*)d_in[10];
    const float* r_Whh  = (const float*)d_in[11];
    const float* r_bih  = (const float*)d_in[12];
    const float* r_bhh  = (const float*)d_in[13];
    const float* rfc_W1 = (const float*)d_in[14];
    const float* rfc_b1 = (const float*)d_in[15];
    const float* rfc_W2 = (const float*)d_in[16];
    const float* rfc_b2 = (const float*)d_in[17];
    const float* pfc_W1 = (const float*)d_in[18];
    const float* pfc_b1 = (const float*)d_in[19];
    const float* pfc_W2 = (const float*)d_in[20];
    const float* pfc_b2 = (const float*)d_in[21];
    float* out = (float*)d_out;

    float *GXw, *GXs, *GXr, *HwA, *HwB, *HsA, *HsB, *HrA, *HrB;
    h16 *Xh, *WihH, *WhhH, *WsH, *WshhH, *WrhhH, *SHiA, *SHiB;
    cudaGetSymbolAddress((void**)&GXw, g_GXw);
    cudaGetSymbolAddress((void**)&GXs, g_GXs);
    cudaGetSymbolAddress((void**)&GXr, g_GXr);
    cudaGetSymbolAddress((void**)&HwA, g_HwA);
    cudaGetSymbolAddress((void**)&HwB, g_HwB);
    cudaGetSymbolAddress((void**)&HsA, g_HsA);
    cudaGetSymbolAddress((void**)&HsB, g_HsB);
    cudaGetSymbolAddress((void**)&HrA, g_HrA);
    cudaGetSymbolAddress((void**)&HrB, g_HrB);
    cudaGetSymbolAddress((void**)&Xh, g_Xh);
    cudaGetSymbolAddress((void**)&WihH, g_WihH);
    cudaGetSymbolAddress((void**)&WhhH, g_WhhH);
    cudaGetSymbolAddress((void**)&WsH, g_WsH);
    cudaGetSymbolAddress((void**)&WshhH, g_WshhH);
    cudaGetSymbolAddress((void**)&WrhhH, g_WrhhH);
    cudaGetSymbolAddress((void**)&SHiA, g_SHiA);
    cudaGetSymbolAddress((void**)&SHiB, g_SHiB);

    const int SMEM_GEMM = 65536;          // scratch 128x128 fp32 > 2*GEMM_BUF
    const int SMEM_GRU  = 2 * GBUF2;      // 49152 == scratch 64x192 fp32
    cudaFuncSetAttribute(gemm_wmma2, cudaFuncAttributeMaxDynamicSharedMemorySize, SMEM_GEMM);
    cudaFuncSetAttribute(gru_step_wmma, cudaFuncAttributeMaxDynamicSharedMemorySize, SMEM_GRU);

    // ---- prep ----
    split_w_single<<<(GDIM * KPAD + 255) / 256, 256>>>(w_Wih, WihH, GDIM, EDIM, KPAD);
    split_w_single<<<(GDIM * HDIM + 255) / 256, 256>>>(w_Whh, WhhH, GDIM, HDIM, HDIM);
    split_w_single<<<(GDIM * HDIM + 255) / 256, 256>>>(s_Wih, WsH, GDIM, HDIM, HDIM);
    split_w_single<<<(GDIM * HDIM + 255) / 256, 256>>>(s_Whh, WshhH, GDIM, HDIM, HDIM);
    split_w_single<<<(GDIM * HDIM + 255) / 256, 256>>>(r_Whh, WrhhH, GDIM, HDIM, HDIM);
    gather_h16_kernel<<<(int)(((size_t)MW * KP4 + 255) / 256), 256>>>(idx, emb, Xh);

    // ---- word level: gx ----
    gemm_wmma2<<<dim3(GDIM / 128, MW / 128), 256, SMEM_GEMM>>>(Xh, WihH,
                                                               w_bih, GXw, KPAD, GDIM);

    float* hw[2] = {HwA, HwB};
    h16*   shi[2] = {SHiA, SHiB};
    int cw = 0;
    gru_init_split<<<(NW * HDIM + 255) / 256, 256>>>(GXw, w_bhh, hw[0], shi[0],
                                                     NW, TWSTEPS);
    for (int t = 1; t < TWSTEPS; t++) {
        gru_step_wmma<<<dim3(HDIM / 64, NW / 64), 256, SMEM_GRU>>>(
            hw[cw], shi[cw], WhhH, w_bhh, GXw, TWSTEPS, t,
            hw[1 - cw], shi[1 - cw]);
        cw = 1 - cw;
    }

    // ---- sentence level ----
    gemm_wmma2<<<dim3(GDIM / 128, (NS * TSSTEPS) / 128), 256, SMEM_GEMM>>>(
        shi[cw], WsH, s_bih, GXs, HDIM, GDIM);

    gru_init_plain<<<(NS * HDIM + 255) / 256, 256>>>(GXs, s_bhh, HsA, NS, TSSTEPS);
    gru_tail_fused<4><<<NS / 4, 256>>>(HsA, WshhH, s_bhh, GXs, TSSTEPS, HsB);
    const float* p_batch = HsB;

    // r_stars -> out[16 .. 272)
    mlp_kernel<<<NS, 128>>>(p_batch, rfc_W1, rfc_b1, rfc_W2, rfc_b2, out + NR);

    // ---- review level ----
    {
        dim3 grid(GDIM / BN, (NR * TRSTEPS + BM - 1) / BM);
        sgemm_f32x2<<<grid, 256>>>(p_batch, r_Wih, r_bih, GXr, NR * TRSTEPS, HDIM, GDIM);
    }
    gru_init_plain<<<(NR * HDIM + 255) / 256, 256>>>(GXr, r_bhh, HrA, NR, TRSTEPS);
    gru_tail_fused<1><<<NR, 256>>>(HrA, WrhhH, r_bhh, GXr, TRSTEPS, HrB);

    // b_stars -> out[0 .. 16)
    mlp_kernel<<<NR, 128>>>(HrB, pfc_W1, pfc_b1, pfc_W2, pfc_b2, out);
}

// round 10
// speedup vs baseline: 3.9931x; 1.0359x over previous
#include <cuda_runtime.h>
#include <cuda_fp16.h>
#include <mma.h>
#include <cooperative_groups.h>
#include <math.h>
#include <stdint.h>

using namespace nvcuda;
namespace cg = cooperative_groups;

// ---------------- problem dims ----------------
#define HDIM 256
#define GDIM 768
#define EDIM 200
#define NW 4096
#define TWSTEPS 32
#define NS 256
#define TSSTEPS 16
#define NR 16
#define TRSTEPS 16
#define MW (NW * TWSTEPS)
#define KPAD 224
#define KP4 (KPAD / 4)

typedef unsigned long long ull;
typedef __half h16;

// ---------------- scratch ----------------
__device__ float g_GXw[(size_t)MW * GDIM];
__device__ float g_GXs[(size_t)NS * TSSTEPS * GDIM];
__device__ float g_GXr[(size_t)NR * TRSTEPS * GDIM];
__device__ float g_HwA[NW * HDIM], g_HwB[NW * HDIM];
__device__ float g_HsA[NS * HDIM], g_HsB[NS * HDIM];
__device__ float g_HrA[NR * HDIM], g_HrB[NR * HDIM];
__device__ __align__(16) h16 g_Xh[(size_t)MW * KPAD];
__device__ __align__(16) h16 g_WihH[GDIM * KPAD];
__device__ __align__(16) h16 g_WhhH[GDIM * HDIM];
__device__ __align__(16) h16 g_WsH [GDIM * HDIM];
__device__ __align__(16) h16 g_WshhH[GDIM * HDIM];
__device__ __align__(16) h16 g_WrhhH[GDIM * HDIM];
__device__ __align__(16) h16 g_SHiA[NW * HDIM], g_SHiB[NW * HDIM];

// ---------------- helpers ----------------
__device__ __forceinline__ float sigmoid_f(float x) { return 1.f / (1.f + expf(-x)); }
__device__ __forceinline__ ull pack2(float lo, float hi) {
    ull r; asm("mov.b64 %0, {%1, %2};" : "=l"(r) : "f"(lo), "f"(hi)); return r;
}
__device__ __forceinline__ ull dup2(float v) { return pack2(v, v); }
__device__ __forceinline__ void ffma2(ull& d, ull a, ull b) {
    asm("fma.rn.f32x2 %0, %1, %2, %3;" : "=l"(d) : "l"(a), "l"(b), "l"(d));
}
__device__ __forceinline__ float2 unpack2(ull v) {
    float2 f; asm("mov.b64 {%0, %1}, %2;" : "=f"(f.x), "=f"(f.y) : "l"(v)); return f;
}
__device__ __forceinline__ void cp16(uint32_t s, const void* g) {
    asm volatile("cp.async.cg.shared.global [%0], [%1], 16;" :: "r"(s), "l"(g));
}
#define CP_COMMIT() asm volatile("cp.async.commit_group;" ::: "memory")
#define CP_WAIT(n)  asm volatile("cp.async.wait_group %0;" :: "n"(n) : "memory")

// ---------------- prep kernels ----------------
__global__ void split_w_single(const float* __restrict__ src, h16* __restrict__ dst,
                               int rows, int cs, int cd)
{
    int i = blockIdx.x * blockDim.x + threadIdx.x;
    if (i >= rows * cd) return;
    int r = i / cd, c = i - r * cd;
    float v = (c < cs) ? src[(size_t)r * cs + c] : 0.f;
    dst[i] = __float2half_rn(v);
}

__global__ void gather_h16_kernel(const int* __restrict__ idx, const float* __restrict__ emb,
                                  h16* __restrict__ hi)
{
    size_t id = (size_t)blockIdx.x * blockDim.x + threadIdx.x;
    if (id >= (size_t)MW * KP4) return;
    int row = (int)(id / KP4);
    int c4 = (int)(id - (size_t)row * KP4) * 4;
    float4 v = make_float4(0.f, 0.f, 0.f, 0.f);
    if (c4 < EDIM)
        v = *reinterpret_cast<const float4*>(emb + (size_t)idx[row] * EDIM + c4);
    h16 hb[4];
    hb[0] = __float2half_rn(v.x); hb[1] = __float2half_rn(v.y);
    hb[2] = __float2half_rn(v.z); hb[3] = __float2half_rn(v.w);
    *reinterpret_cast<ull*>(hi + (size_t)row * KPAD + c4) = *reinterpret_cast<ull*>(hb);
}

// ---------------- wmma fp16 single-pass GEMM: C = A@W^T + bias --------------
#define LDT2 48
#define TBY (128 * LDT2 * 2)
#define GEMM_BUF (2 * TBY)

__global__ __launch_bounds__(256, 2)
void gemm_wmma2(const h16* __restrict__ Ahp, const h16* __restrict__ Whp,
                const float* __restrict__ bias, float* __restrict__ C,
                int K, int N)
{
    extern __shared__ __align__(128) char sm[];
    const uint32_t sbase = (uint32_t)__cvta_generic_to_shared(sm);
    float* scratch = reinterpret_cast<float*>(sm);

    const int tid = threadIdx.x;
    const int wid = tid >> 5;
    const int m0 = blockIdx.y * 128, n0 = blockIdx.x * 128;
    const int wm = wid & 3, wn = wid >> 2;

    const int lr = tid >> 1;
    const int lq = (tid & 1) * 16;

    const h16* gA = Ahp + (size_t)(m0 + lr) * K + lq;
    const h16* gB = Whp + (size_t)(n0 + lr) * K + lq;
    const uint32_t srow = lr * LDT2 * 2 + lq * 2;

    const int ntile = K / 32;

    wmma::fragment<wmma::accumulator, 16, 16, 16, float> cf[2][4];
#pragma unroll
    for (int i = 0; i < 2; i++)
#pragma unroll
        for (int j = 0; j < 4; j++) wmma::fill_fragment(cf[i][j], 0.0f);

    auto issue = [&](int it, int b) {
        const int kk = it * 32;
        uint32_t base = sbase + b * GEMM_BUF;
        cp16(base + srow,            gA + kk);
        cp16(base + srow + 16,       gA + kk + 8);
        cp16(base + TBY + srow,      gB + kk);
        cp16(base + TBY + srow + 16, gB + kk + 8);
    };

    issue(0, 0); CP_COMMIT();

    for (int it = 0; it < ntile; it++) {
        const int b = it & 1;
        if (it + 1 < ntile) { issue(it + 1, b ^ 1); CP_COMMIT(); CP_WAIT(1); }
        else                { CP_WAIT(0); }
        __syncthreads();

        const h16* tA = reinterpret_cast<const h16*>(sm + b * GEMM_BUF);
        const h16* tB = tA + 128 * LDT2;

#pragma unroll
        for (int ks = 0; ks < 32; ks += 16) {
            wmma::fragment<wmma::matrix_a, 16, 16, 16, h16, wmma::row_major> ah[2];
            wmma::fragment<wmma::matrix_b, 16, 16, 16, h16, wmma::col_major> bh[4];
#pragma unroll
            for (int i = 0; i < 2; i++)
                wmma::load_matrix_sync(ah[i], tA + (wm * 32 + i * 16) * LDT2 + ks, LDT2);
#pragma unroll
            for (int j = 0; j < 4; j++)
                wmma::load_matrix_sync(bh[j], tB + (wn * 64 + j * 16) * LDT2 + ks, LDT2);
#pragma unroll
            for (int i = 0; i < 2; i++)
#pragma unroll
                for (int j = 0; j < 4; j++)
                    wmma::mma_sync(cf[i][j], ah[i], bh[j], cf[i][j]);
        }
        __syncthreads();
    }

#pragma unroll
    for (int i = 0; i < 2; i++)
#pragma unroll
        for (int j = 0; j < 4; j++)
            wmma::store_matrix_sync(&scratch[(wm * 32 + i * 16) * 128 + wn * 64 + j * 16],
                                    cf[i][j], 128, wmma::mem_row_major);
    __syncthreads();

#pragma unroll
    for (int itx = 0; itx < 16; itx++) {
        int idx4 = tid + itx * 256;
        int r = idx4 >> 5;
        int c4 = (idx4 & 31) * 4;
        float4 v = *reinterpret_cast<const float4*>(&scratch[r * 128 + c4]);
        float4 b = *reinterpret_cast<const float4*>(&bias[n0 + c4]);
        v.x += b.x; v.y += b.y; v.z += b.z; v.w += b.w;
        *reinterpret_cast<float4*>(&C[(size_t)(m0 + r) * N + n0 + c4]) = v;
    }
}

// ---------------- persistent cooperative word-recurrent loop -----------------
// grid (4, 64) = 256 CTAs, occ 2 (capacity 296 -> co-resident). Each iteration:
// 64 rows x 64 h-cols x 3 gates wmma step, then grid-wide sync.
#define GB_ROWS 192
#define A64BY (64 * LDT2 * 2)       // 6144
#define B64BY (GB_ROWS * LDT2 * 2)  // 18432
#define GBUF2 (A64BY + B64BY)       // 24576 per buffer

__global__ __launch_bounds__(256, 2)
void gru_word_persistent(float* __restrict__ hA, float* __restrict__ hB,
                         h16* __restrict__ sA, h16* __restrict__ sB,
                         const h16* __restrict__ Whp,
                         const float* __restrict__ bhh, const float* __restrict__ gx)
{
    extern __shared__ __align__(128) char sm[];
    const uint32_t sbase = (uint32_t)__cvta_generic_to_shared(sm);
    float* scratch = reinterpret_cast<float*>(sm);   // 64x192 fp32 (48KB)

    cg::grid_group grid = cg::this_grid();

    const int tid = threadIdx.x;
    const int wid = tid >> 5;
    const int n0 = blockIdx.x * 64;
    const int m0 = blockIdx.y * 64;
    const int wm = wid & 1;
    const int wn = wid >> 1;

    const int lr = tid >> 2;
    const int lq = (tid & 3) * 8;
    const uint32_t arow = lr * (LDT2 * 2) + lq * 2;

    for (int t = 1; t < TWSTEPS; t++) {
        const int cur = (t - 1) & 1;
        const float* hin  = cur ? hB : hA;
        float*       hout = cur ? hA : hB;
        const h16*   Hhi  = cur ? sB : sA;
        h16*         Hout = cur ? sA : sB;

        const h16* gAh = Hhi + (size_t)(m0 + lr) * HDIM + lq;

        auto issue = [&](int it, int b) {
            const int kk = it * 32;
            uint32_t base = sbase + b * GBUF2;
            cp16(base + arow, gAh + kk);
#pragma unroll
            for (int rep = 0; rep < 3; rep++) {
                int task = tid + rep * 256;
                int rt = task >> 2;
                int q = (task & 3) * 8;
                int gate = rt / 64, col = rt - gate * 64;
                size_t srcoff = (size_t)(gate * HDIM + n0 + col) * HDIM + kk + q;
                cp16(base + A64BY + rt * (LDT2 * 2) + q * 2, Whp + srcoff);
            }
        };

        wmma::fragment<wmma::accumulator, 16, 16, 16, float> cf[2][3];
#pragma unroll
        for (int i = 0; i < 2; i++)
#pragma unroll
            for (int j = 0; j < 3; j++) wmma::fill_fragment(cf[i][j], 0.0f);

        issue(0, 0); CP_COMMIT();

        const int ntile = HDIM / 32;   // 8
        for (int it = 0; it < ntile; it++) {
            const int b = it & 1;
            if (it + 1 < ntile) { issue(it + 1, b ^ 1); CP_COMMIT(); CP_WAIT(1); }
            else                { CP_WAIT(0); }
            __syncthreads();

            const h16* tA = reinterpret_cast<const h16*>(sm + b * GBUF2);
            const h16* tB = tA + 64 * LDT2;

#pragma unroll
            for (int ks = 0; ks < 32; ks += 16) {
                wmma::fragment<wmma::matrix_a, 16, 16, 16, h16, wmma::row_major> ah[2];
#pragma unroll
                for (int i = 0; i < 2; i++)
                    wmma::load_matrix_sync(ah[i], tA + (wm * 32 + i * 16) * LDT2 + ks, LDT2);
#pragma unroll
                for (int j = 0; j < 3; j++) {
                    wmma::fragment<wmma::matrix_b, 16, 16, 16, h16, wmma::col_major> bh;
                    wmma::load_matrix_sync(bh, tB + (wn * 48 + j * 16) * LDT2 + ks, LDT2);
#pragma unroll
                    for (int i = 0; i < 2; i++)
                        wmma::mma_sync(cf[i][j], ah[i], bh, cf[i][j]);
                }
            }
            __syncthreads();
        }

        // stash gates to scratch [64][192]
#pragma unroll
        for (int i = 0; i < 2; i++)
#pragma unroll
            for (int j = 0; j < 3; j++)
                wmma::store_matrix_sync(&scratch[(wm * 32 + i * 16) * 192 + wn * 48 + j * 16],
                                        cf[i][j], 192, wmma::mem_row_major);
        __syncthreads();

        // fused GRU epilogue
#pragma unroll
        for (int itx = 0; itx < 4; itx++) {
            int task = tid + itx * 256;
            int r = task >> 4;
            int c4 = (task & 15) * 4;
            const int row = m0 + r;
            const int j = n0 + c4;
            const float* srow2 = &scratch[r * 192];
            float gr[4], gz[4], gn[4];
            *reinterpret_cast<float4*>(gr) = *reinterpret_cast<const float4*>(srow2 + c4);
            *reinterpret_cast<float4*>(gz) = *reinterpret_cast<const float4*>(srow2 + 64 + c4);
            *reinterpret_cast<float4*>(gn) = *reinterpret_cast<const float4*>(srow2 + 128 + c4);
            float br[4], bz[4], bn[4], xr[4], xz[4], xn[4], hh[4];
            *reinterpret_cast<float4*>(br) = *reinterpret_cast<const float4*>(bhh + j);
            *reinterpret_cast<float4*>(bz) = *reinterpret_cast<const float4*>(bhh + HDIM + j);
            *reinterpret_cast<float4*>(bn) = *reinterpret_cast<const float4*>(bhh + 2 * HDIM + j);
            const float* gxp = gx + ((size_t)row * TWSTEPS + t) * GDIM;
            *reinterpret_cast<float4*>(xr) = *reinterpret_cast<const float4*>(gxp + j);
            *reinterpret_cast<float4*>(xz) = *reinterpret_cast<const float4*>(gxp + HDIM + j);
            *reinterpret_cast<float4*>(xn) = *reinterpret_cast<const float4*>(gxp + 2 * HDIM + j);
            *reinterpret_cast<float4*>(hh) = *reinterpret_cast<const float4*>(hin + (size_t)row * HDIM + j);
            float o[4];
            h16 hb[4];
#pragma unroll
            for (int u = 0; u < 4; u++) {
                float rr = sigmoid_f(xr[u] + gr[u] + br[u]);
                float zz = sigmoid_f(xz[u] + gz[u] + bz[u]);
                float nv = tanhf(xn[u] + rr * (gn[u] + bn[u]));
                float h = (1.f - zz) * nv + zz * hh[u];
                o[u] = h;
                hb[u] = __float2half_rn(h);
            }
            *reinterpret_cast<float4*>(hout + (size_t)row * HDIM + j) = *reinterpret_cast<float4*>(o);
            *reinterpret_cast<ull*>(Hout + (size_t)row * HDIM + j) = *reinterpret_cast<ull*>(hb);
        }
        __syncthreads();   // scratch reads done before next iter's cp.async reuse
        grid.sync();       // h/Hout visible to all CTAs
    }
}

// ---------------- t=0 GRU steps ----------------
__global__ void gru_init_split(const float* __restrict__ gx, const float* __restrict__ bhh,
                               float* __restrict__ hout, h16* __restrict__ hi,
                               int Mseq, int T)
{
    int i = blockIdx.x * blockDim.x + threadIdx.x;
    if (i >= Mseq * HDIM) return;
    int seq = i >> 8, j = i & 255;
    const float* g = gx + (size_t)seq * T * GDIM;
    float r = sigmoid_f(g[j] + bhh[j]);
    float z = sigmoid_f(g[j + HDIM] + bhh[j + HDIM]);
    float n = tanhf(g[j + 2 * HDIM] + r * bhh[j + 2 * HDIM]);
    float h = (1.f - z) * n;
    hout[i] = h;
    hi[i] = __float2half_rn(h);
}

__global__ void gru_init_plain(const float* __restrict__ gx, const float* __restrict__ bhh,
                               float* __restrict__ hout, int Mseq, int T)
{
    int i = blockIdx.x * blockDim.x + threadIdx.x;
    if (i >= Mseq * HDIM) return;
    int seq = i >> 8, j = i & 255;
    const float* g = gx + (size_t)seq * T * GDIM;
    float r = sigmoid_f(g[j] + bhh[j]);
    float z = sigmoid_f(g[j + HDIM] + bhh[j + HDIM]);
    float n = tanhf(g[j + 2 * HDIM] + r * bhh[j + 2 * HDIM]);
    hout[i] = (1.f - z) * n;
}

// ---------------- fused multi-step GRU tail ----------------------------------
template <int NSEQ>
__global__ __launch_bounds__(256)
void gru_tail_fused(const float* __restrict__ h0, const h16* __restrict__ W16,
                    const float* __restrict__ bhh, const float* __restrict__ gx,
                    int T, float* __restrict__ hfinal)
{
    __shared__ float hs[HDIM][NSEQ];
    const int tid = threadIdx.x;
    const int seq0 = blockIdx.x * NSEQ;

    for (int i = tid; i < NSEQ * HDIM; i += 256) {
        int s = i / HDIM, k = i - s * HDIM;
        hs[k][s] = h0[(size_t)(seq0 + s) * HDIM + k];
    }
    __syncthreads();

    const int j = tid;
    const h16* wr = W16 + (size_t)j * HDIM;
    const h16* wz = W16 + (size_t)(HDIM + j) * HDIM;
    const h16* wn_ = W16 + (size_t)(2 * HDIM + j) * HDIM;
    const float br = bhh[j], bz = bhh[HDIM + j], bn = bhh[2 * HDIM + j];

    for (int t = 1; t < T; t++) {
        float ar[NSEQ], az[NSEQ], an[NSEQ];
#pragma unroll
        for (int s = 0; s < NSEQ; s++) { ar[s] = 0.f; az[s] = 0.f; an[s] = 0.f; }

#pragma unroll 4
        for (int k = 0; k < HDIM; k += 8) {
            uint4 vr = *reinterpret_cast<const uint4*>(wr + k);
            uint4 vz = *reinterpret_cast<const uint4*>(wz + k);
            uint4 vn = *reinterpret_cast<const uint4*>(wn_ + k);
            const h16* pr = reinterpret_cast<const h16*>(&vr);
            const h16* pz = reinterpret_cast<const h16*>(&vz);
            const h16* pn = reinterpret_cast<const h16*>(&vn);
#pragma unroll
            for (int u = 0; u < 8; u++) {
                float fr = __half2float(pr[u]);
                float fz = __half2float(pz[u]);
                float fn = __half2float(pn[u]);
#pragma unroll
                for (int s = 0; s < NSEQ; s++) {
                    float hv = hs[k + u][s];
                    ar[s] = fmaf(fr, hv, ar[s]);
                    az[s] = fmaf(fz, hv, az[s]);
                    an[s] = fmaf(fn, hv, an[s]);
                }
            }
        }
        __syncthreads();

        float hnew[NSEQ];
#pragma unroll
        for (int s = 0; s < NSEQ; s++) {
            const float* gxp = gx + ((size_t)(seq0 + s) * T + t) * GDIM;
            float r = sigmoid_f(gxp[j] + ar[s] + br);
            float z = sigmoid_f(gxp[HDIM + j] + az[s] + bz);
            float n = tanhf(gxp[2 * HDIM + j] + r * (an[s] + bn));
            hnew[s] = (1.f - z) * n + z * hs[j][s];
        }
#pragma unroll
        for (int s = 0; s < NSEQ; s++) hs[j][s] = hnew[s];
        __syncthreads();
    }

    for (int i = tid; i < NSEQ * HDIM; i += 256) {
        int s = i / HDIM, k = i - s * HDIM;
        hfinal[(size_t)(seq0 + s) * HDIM + k] = hs[k][s];
    }
}

// ---------------- fp32 SGEMM (review gx) ----------------
#define BM 128
#define BN 128
#define BK 8
__global__ __launch_bounds__(256, 2)
void sgemm_f32x2(const float* __restrict__ A, const float* __restrict__ W,
                 const float* __restrict__ bias, float* __restrict__ C,
                 int M, int K, int N)
{
    __shared__ float As[2][BK][BM];
    __shared__ float Bs[2][BK][BN];
    const int tid = threadIdx.x;
    const int m0 = blockIdx.y * BM;
    const int n0 = blockIdx.x * BN;
    const int a_m = tid & 127, a_kq = tid >> 7;
    const int b_n = tid >> 1,  b_kq = tid & 1;
    const bool a_valid = (m0 + a_m) < M;
    const float* Arow = A + (size_t)(a_valid ? (m0 + a_m) : 0) * K;
    const float* Brow = W + (size_t)(n0 + b_n) * K;
    const int tx = tid & 15, ty = tid >> 4;

    ull acc2[8][4];
#pragma unroll
    for (int i = 0; i < 8; i++)
#pragma unroll
        for (int j = 0; j < 4; j++) acc2[i][j] = 0ull;

    float4 av = make_float4(0.f, 0.f, 0.f, 0.f);
    if (a_valid) av = *reinterpret_cast<const float4*>(Arow + a_kq * 4);
    float4 bv = *reinterpret_cast<const float4*>(Brow + b_kq * 4);
    As[0][a_kq * 4 + 0][a_m] = av.x;  As[0][a_kq * 4 + 1][a_m] = av.y;
    As[0][a_kq * 4 + 2][a_m] = av.z;  As[0][a_kq * 4 + 3][a_m] = av.w;
    Bs[0][b_kq * 4 + 0][b_n] = bv.x;  Bs[0][b_kq * 4 + 1][b_n] = bv.y;
    Bs[0][b_kq * 4 + 2][b_n] = bv.z;  Bs[0][b_kq * 4 + 3][b_n] = bv.w;
    __syncthreads();

    int buf = 0;
    for (int kk = 0; kk < K; kk += BK) {
        const bool has_next = (kk + BK) < K;
        if (has_next) {
            if (a_valid) av = *reinterpret_cast<const float4*>(Arow + kk + BK + a_kq * 4);
            bv = *reinterpret_cast<const float4*>(Brow + kk + BK + b_kq * 4);
        }
#pragma unroll
        for (int k = 0; k < BK; k++) {
            float4 a0 = *reinterpret_cast<const float4*>(&As[buf][k][ty * 8]);
            float4 a1 = *reinterpret_cast<const float4*>(&As[buf][k][ty * 8 + 4]);
            ulonglong2 bq0 = *reinterpret_cast<const ulonglong2*>(&Bs[buf][k][tx * 8]);
            ulonglong2 bq1 = *reinterpret_cast<const ulonglong2*>(&Bs[buf][k][tx * 8 + 4]);
            ull bp[4] = {bq0.x, bq0.y, bq1.x, bq1.y};
            float a[8] = {a0.x, a0.y, a0.z, a0.w, a1.x, a1.y, a1.z, a1.w};
#pragma unroll
            for (int i = 0; i < 8; i++) {
                ull ad = dup2(a[i]);
#pragma unroll
                for (int j = 0; j < 4; j++) ffma2(acc2[i][j], ad, bp[j]);
            }
        }
        if (has_next) {
            int nb = buf ^ 1;
            As[nb][a_kq * 4 + 0][a_m] = av.x;  As[nb][a_kq * 4 + 1][a_m] = av.y;
            As[nb][a_kq * 4 + 2][a_m] = av.z;  As[nb][a_kq * 4 + 3][a_m] = av.w;
            Bs[nb][b_kq * 4 + 0][b_n] = bv.x;  Bs[nb][b_kq * 4 + 1][b_n] = bv.y;
            Bs[nb][b_kq * 4 + 2][b_n] = bv.z;  Bs[nb][b_kq * 4 + 3][b_n] = bv.w;
            __syncthreads();
            buf = nb;
        }
    }
#pragma unroll
    for (int i = 0; i < 8; i++) {
        int row = m0 + ty * 8 + i;
        if (row >= M) continue;
#pragma unroll
        for (int j = 0; j < 4; j++) {
            int col = n0 + tx * 8 + j * 2;
            float2 p = unpack2(acc2[i][j]);
            float2 bb = *reinterpret_cast<const float2*>(bias + col);
            float2 o; o.x = p.x + bb.x; o.y = p.y + bb.y;
            *reinterpret_cast<float2*>(C + (size_t)row * N + col) = o;
        }
    }
}

// ---------------- MLP ----------------
__global__ __launch_bounds__(128)
void mlp_kernel(const float* __restrict__ X,
                const float* __restrict__ W1, const float* __restrict__ b1,
                const float* __restrict__ W2, const float* __restrict__ b2,
                float* __restrict__ out)
{
    const int row = blockIdx.x;
    const int i = threadIdx.x;
    __shared__ float xs[HDIM];
    __shared__ float red[4];
    xs[i]       = X[(size_t)row * HDIM + i];
    xs[i + 128] = X[(size_t)row * HDIM + i + 128];
    __syncthreads();
    const float* w = W1 + (size_t)i * HDIM;
    float acc = b1[i];
#pragma unroll 8
    for (int k = 0; k < HDIM; k += 4) {
        float4 wv = *reinterpret_cast<const float4*>(w + k);
        acc = fmaf(wv.x, xs[k], acc);
        acc = fmaf(wv.y, xs[k + 1], acc);
        acc = fmaf(wv.z, xs[k + 2], acc);
        acc = fmaf(wv.w, xs[k + 3], acc);
    }
    const float scale = 1.0507009873554805f;
    const float alpha = 1.6732632423543772f;
    float s = scale * (acc > 0.f ? acc : alpha * (expf(acc) - 1.f));
    float v = s * W2[i];
#pragma unroll
    for (int off = 16; off > 0; off >>= 1)
        v += __shfl_down_sync(0xffffffffu, v, off);
    if ((i & 31) == 0) red[i >> 5] = v;
    __syncthreads();
    if (i == 0) out[row] = red[0] + red[1] + red[2] + red[3] + b2[0];
}

// ---------------- host orchestration ----------------
extern "C" void kernel_launch(void* const* d_in, const int* in_sizes, int n_in,
                              void* d_out, int out_size)
{
    (void)in_sizes; (void)n_in; (void)out_size;

    const int*   idx    = (const int*)  d_in[0];
    const float* emb    = (const float*)d_in[1];
    const float* w_Wih  = (const float*)d_in[2];
    const float* w_Whh  = (const float*)d_in[3];
    const float* w_bih  = (const float*)d_in[4];
    const float* w_bhh  = (const float*)d_in[5];
    const float* s_Wih  = (const float*)d_in[6];
    const float* s_Whh  = (const float*)d_in[7];
    const float* s_bih  = (const float*)d_in[8];
    const float* s_bhh  = (const float*)d_in[9];
    const float* r_Wih  = (const float*)d_in[10];
    const float* r_Whh  = (const float*)d_in[11];
    const float* r_bih  = (const float*)d_in[12];
    const float* r_bhh  = (const float*)d_in[13];
    const float* rfc_W1 = (const float*)d_in[14];
    const float* rfc_b1 = (const float*)d_in[15];
    const float* rfc_W2 = (const float*)d_in[16];
    const float* rfc_b2 = (const float*)d_in[17];
    const float* pfc_W1 = (const float*)d_in[18];
    const float* pfc_b1 = (const float*)d_in[19];
    const float* pfc_W2 = (const float*)d_in[20];
    const float* pfc_b2 = (const float*)d_in[21];
    float* out = (float*)d_out;

    float *GXw, *GXs, *GXr, *HwA, *HwB, *HsA, *HsB, *HrA, *HrB;
    h16 *Xh, *WihH, *WhhH, *WsH, *WshhH, *WrhhH, *SHiA, *SHiB;
    cudaGetSymbolAddress((void**)&GXw, g_GXw);
    cudaGetSymbolAddress((void**)&GXs, g_GXs);
    cudaGetSymbolAddress((void**)&GXr, g_GXr);
    cudaGetSymbolAddress((void**)&HwA, g_HwA);
    cudaGetSymbolAddress((void**)&HwB, g_HwB);
    cudaGetSymbolAddress((void**)&HsA, g_HsA);
    cudaGetSymbolAddress((void**)&HsB, g_HsB);
    cudaGetSymbolAddress((void**)&HrA, g_HrA);
    cudaGetSymbolAddress((void**)&HrB, g_HrB);
    cudaGetSymbolAddress((void**)&Xh, g_Xh);
    cudaGetSymbolAddress((void**)&WihH, g_WihH);
    cudaGetSymbolAddress((void**)&WhhH, g_WhhH);
    cudaGetSymbolAddress((void**)&WsH, g_WsH);
    cudaGetSymbolAddress((void**)&WshhH, g_WshhH);
    cudaGetSymbolAddress((void**)&WrhhH, g_WrhhH);
    cudaGetSymbolAddress((void**)&SHiA, g_SHiA);
    cudaGetSymbolAddress((void**)&SHiB, g_SHiB);

    const int SMEM_GEMM = 65536;
    const int SMEM_GRU  = 2 * GBUF2;   // 49152
    cudaFuncSetAttribute(gemm_wmma2, cudaFuncAttributeMaxDynamicSharedMemorySize, SMEM_GEMM);
    cudaFuncSetAttribute(gru_word_persistent, cudaFuncAttributeMaxDynamicSharedMemorySize, SMEM_GRU);

    // ---- prep ----
    split_w_single<<<(GDIM * KPAD + 255) / 256, 256>>>(w_Wih, WihH, GDIM, EDIM, KPAD);
    split_w_single<<<(GDIM * HDIM + 255) / 256, 256>>>(w_Whh, WhhH, GDIM, HDIM, HDIM);
    split_w_single<<<(GDIM * HDIM + 255) / 256, 256>>>(s_Wih, WsH, GDIM, HDIM, HDIM);
    split_w_single<<<(GDIM * HDIM + 255) / 256, 256>>>(s_Whh, WshhH, GDIM, HDIM, HDIM);
    split_w_single<<<(GDIM * HDIM + 255) / 256, 256>>>(r_Whh, WrhhH, GDIM, HDIM, HDIM);
    gather_h16_kernel<<<(int)(((size_t)MW * KP4 + 255) / 256), 256>>>(idx, emb, Xh);

    // ---- word level: gx ----
    gemm_wmma2<<<dim3(GDIM / 128, MW / 128), 256, SMEM_GEMM>>>(Xh, WihH,
                                                               w_bih, GXw, KPAD, GDIM);

    // t=0 into buffer A, then persistent cooperative loop t=1..31
    gru_init_split<<<(NW * HDIM + 255) / 256, 256>>>(GXw, w_bhh, HwA, SHiA,
                                                     NW, TWSTEPS);
    {
        void* args[] = {&HwA, &HwB, &SHiA, &SHiB, &WhhH, (void*)&w_bhh, (void*)&GXw};
        cudaLaunchConfig_t cfg = {};
        cfg.gridDim = dim3(HDIM / 64, NW / 64);     // (4, 64) = 256 CTAs
        cfg.blockDim = dim3(256, 1, 1);
        cfg.dynamicSmemBytes = SMEM_GRU;
        cudaLaunchAttribute attr;
        attr.id = cudaLaunchAttributeCooperative;
        attr.val.cooperative = 1;
        cfg.attrs = &attr;
        cfg.numAttrs = 1;
        cudaLaunchKernelEx(&cfg, gru_word_persistent,
                           HwA, HwB, SHiA, SHiB, (const h16*)WhhH,
                           (const float*)w_bhh, (const float*)GXw);
        (void)args;
    }
    // 31 iterations: final h in buffer index (31 & 1) = 1 -> B buffers
    h16*   sent_hi = SHiB;

    // ---- sentence level ----
    gemm_wmma2<<<dim3(GDIM / 128, (NS * TSSTEPS) / 128), 256, SMEM_GEMM>>>(
        sent_hi, WsH, s_bih, GXs, HDIM, GDIM);

    gru_init_plain<<<(NS * HDIM + 255) / 256, 256>>>(GXs, s_bhh, HsA, NS, TSSTEPS);
    gru_tail_fused<4><<<NS / 4, 256>>>(HsA, WshhH, s_bhh, GXs, TSSTEPS, HsB);
    const float* p_batch = HsB;

    // r_stars -> out[16 .. 272)
    mlp_kernel<<<NS, 128>>>(p_batch, rfc_W1, rfc_b1, rfc_W2, rfc_b2, out + NR);

    // ---- review level ----
    {
        dim3 grid(GDIM / BN, (NR * TRSTEPS + BM - 1) / BM);
        sgemm_f32x2<<<grid, 256>>>(p_batch, r_Wih, r_bih, GXr, NR * TRSTEPS, HDIM, GDIM);
    }
    gru_init_plain<<<(NR * HDIM + 255) / 256, 256>>>(GXr, r_bhh, HrA, NR, TRSTEPS);
    gru_tail_fused<1><<<NR, 256>>>(HrA, WrhhH, r_bhh, GXr, TRSTEPS, HrB);

    // b_stars -> out[0 .. 16)
    mlp_kernel<<<NR, 128>>>(HrB, pfc_W1, pfc_b1, pfc_W2, pfc_b2, out);
}

// round 11
// speedup vs baseline: 4.0151x; 1.0055x over previous
#include <cuda_runtime.h>
#include <cuda_fp16.h>
#include <mma.h>
#include <cooperative_groups.h>
#include <math.h>
#include <stdint.h>

using namespace nvcuda;
namespace cg = cooperative_groups;

// ---------------- problem dims ----------------
#define HDIM 256
#define GDIM 768
#define EDIM 200
#define NW 4096
#define TWSTEPS 32
#define NS 256
#define TSSTEPS 16
#define NR 16
#define TRSTEPS 16
#define MW (NW * TWSTEPS)
#define KPAD 224
#define KP4 (KPAD / 4)

typedef unsigned long long ull;
typedef __half h16;

// ---------------- scratch ----------------
__device__ __align__(16) h16 g_GXw[(size_t)MW * GDIM];   // fp16 word input gates (201MB)
__device__ float g_GXs[(size_t)NS * TSSTEPS * GDIM];
__device__ float g_GXr[(size_t)NR * TRSTEPS * GDIM];
__device__ float g_HsA[NS * HDIM], g_HsB[NS * HDIM];
__device__ float g_HrA[NR * HDIM], g_HrB[NR * HDIM];
__device__ __align__(16) h16 g_Xh[(size_t)MW * KPAD];
__device__ __align__(16) h16 g_WihH[GDIM * KPAD];
__device__ __align__(16) h16 g_WhhH[GDIM * HDIM];
__device__ __align__(16) h16 g_WsH [GDIM * HDIM];
__device__ __align__(16) h16 g_WshhH[GDIM * HDIM];
__device__ __align__(16) h16 g_WrhhH[GDIM * HDIM];
__device__ __align__(16) h16 g_SHiA[NW * HDIM], g_SHiB[NW * HDIM];

// ---------------- helpers ----------------
__device__ __forceinline__ float sigmoid_f(float x) { return 1.f / (1.f + expf(-x)); }
__device__ __forceinline__ ull pack2(float lo, float hi) {
    ull r; asm("mov.b64 %0, {%1, %2};" : "=l"(r) : "f"(lo), "f"(hi)); return r;
}
__device__ __forceinline__ ull dup2(float v) { return pack2(v, v); }
__device__ __forceinline__ void ffma2(ull& d, ull a, ull b) {
    asm("fma.rn.f32x2 %0, %1, %2, %3;" : "=l"(d) : "l"(a), "l"(b), "l"(d));
}
__device__ __forceinline__ float2 unpack2(ull v) {
    float2 f; asm("mov.b64 {%0, %1}, %2;" : "=f"(f.x), "=f"(f.y) : "l"(v)); return f;
}
__device__ __forceinline__ void cp16(uint32_t s, const void* g) {
    asm volatile("cp.async.cg.shared.global [%0], [%1], 16;" :: "r"(s), "l"(g));
}
#define CP_COMMIT() asm volatile("cp.async.commit_group;" ::: "memory")
#define CP_WAIT(n)  asm volatile("cp.async.wait_group %0;" :: "n"(n) : "memory")

__device__ __forceinline__ void ld_h4(float* o, const h16* p) {
    ull v = *reinterpret_cast<const ull*>(p);
    const h16* q = reinterpret_cast<const h16*>(&v);
    o[0] = __half2float(q[0]); o[1] = __half2float(q[1]);
    o[2] = __half2float(q[2]); o[3] = __half2float(q[3]);
}

// ---------------- prep kernels ----------------
__global__ void split_w_single(const float* __restrict__ src, h16* __restrict__ dst,
                               int rows, int cs, int cd)
{
    int i = blockIdx.x * blockDim.x + threadIdx.x;
    if (i >= rows * cd) return;
    int r = i / cd, c = i - r * cd;
    float v = (c < cs) ? src[(size_t)r * cs + c] : 0.f;
    dst[i] = __float2half_rn(v);
}

// 4 same-size square weight conversions in one launch (vectorized 4-wide)
__global__ void split_w_quad(const float* s0, h16* d0, const float* s1, h16* d1,
                             const float* s2, h16* d2, const float* s3, h16* d3,
                             int n4)   // n4 = elems/4 per matrix
{
    int i = blockIdx.x * blockDim.x + threadIdx.x;
    int mat = i / n4;
    int off = (i - mat * n4) * 4;
    if (mat >= 4) return;
    const float* s = (mat == 0) ? s0 : (mat == 1) ? s1 : (mat == 2) ? s2 : s3;
    h16* d = (mat == 0) ? d0 : (mat == 1) ? d1 : (mat == 2) ? d2 : d3;
    float4 v = *reinterpret_cast<const float4*>(s + off);
    h16 hb[4];
    hb[0] = __float2half_rn(v.x); hb[1] = __float2half_rn(v.y);
    hb[2] = __float2half_rn(v.z); hb[3] = __float2half_rn(v.w);
    *reinterpret_cast<ull*>(d + off) = *reinterpret_cast<ull*>(hb);
}

__global__ void gather_h16_kernel(const int* __restrict__ idx, const float* __restrict__ emb,
                                  h16* __restrict__ hi)
{
    size_t id = (size_t)blockIdx.x * blockDim.x + threadIdx.x;
    if (id >= (size_t)MW * KP4) return;
    int row = (int)(id / KP4);
    int c4 = (int)(id - (size_t)row * KP4) * 4;
    float4 v = make_float4(0.f, 0.f, 0.f, 0.f);
    if (c4 < EDIM)
        v = *reinterpret_cast<const float4*>(emb + (size_t)idx[row] * EDIM + c4);
    h16 hb[4];
    hb[0] = __float2half_rn(v.x); hb[1] = __float2half_rn(v.y);
    hb[2] = __float2half_rn(v.z); hb[3] = __float2half_rn(v.w);
    *reinterpret_cast<ull*>(hi + (size_t)row * KPAD + c4) = *reinterpret_cast<ull*>(hb);
}

// ---------------- wmma fp16 GEMM: C = A@W^T + bias (OutT = float or h16) ----
#define LDT2 48
#define TBY (128 * LDT2 * 2)
#define GEMM_BUF (2 * TBY)

template <typename OutT>
__global__ __launch_bounds__(256, 2)
void gemm_wmma2(const h16* __restrict__ Ahp, const h16* __restrict__ Whp,
                const float* __restrict__ bias, OutT* __restrict__ C,
                int K, int N)
{
    extern __shared__ __align__(128) char sm[];
    const uint32_t sbase = (uint32_t)__cvta_generic_to_shared(sm);
    float* scratch = reinterpret_cast<float*>(sm);

    const int tid = threadIdx.x;
    const int wid = tid >> 5;
    const int m0 = blockIdx.y * 128, n0 = blockIdx.x * 128;
    const int wm = wid & 3, wn = wid >> 2;

    const int lr = tid >> 1;
    const int lq = (tid & 1) * 16;

    const h16* gA = Ahp + (size_t)(m0 + lr) * K + lq;
    const h16* gB = Whp + (size_t)(n0 + lr) * K + lq;
    const uint32_t srow = lr * LDT2 * 2 + lq * 2;

    const int ntile = K / 32;

    wmma::fragment<wmma::accumulator, 16, 16, 16, float> cf[2][4];
#pragma unroll
    for (int i = 0; i < 2; i++)
#pragma unroll
        for (int j = 0; j < 4; j++) wmma::fill_fragment(cf[i][j], 0.0f);

    auto issue = [&](int it, int b) {
        const int kk = it * 32;
        uint32_t base = sbase + b * GEMM_BUF;
        cp16(base + srow,            gA + kk);
        cp16(base + srow + 16,       gA + kk + 8);
        cp16(base + TBY + srow,      gB + kk);
        cp16(base + TBY + srow + 16, gB + kk + 8);
    };

    issue(0, 0); CP_COMMIT();

    for (int it = 0; it < ntile; it++) {
        const int b = it & 1;
        if (it + 1 < ntile) { issue(it + 1, b ^ 1); CP_COMMIT(); CP_WAIT(1); }
        else                { CP_WAIT(0); }
        __syncthreads();

        const h16* tA = reinterpret_cast<const h16*>(sm + b * GEMM_BUF);
        const h16* tB = tA + 128 * LDT2;

#pragma unroll
        for (int ks = 0; ks < 32; ks += 16) {
            wmma::fragment<wmma::matrix_a, 16, 16, 16, h16, wmma::row_major> ah[2];
            wmma::fragment<wmma::matrix_b, 16, 16, 16, h16, wmma::col_major> bh[4];
#pragma unroll
            for (int i = 0; i < 2; i++)
                wmma::load_matrix_sync(ah[i], tA + (wm * 32 + i * 16) * LDT2 + ks, LDT2);
#pragma unroll
            for (int j = 0; j < 4; j++)
                wmma::load_matrix_sync(bh[j], tB + (wn * 64 + j * 16) * LDT2 + ks, LDT2);
#pragma unroll
            for (int i = 0; i < 2; i++)
#pragma unroll
                for (int j = 0; j < 4; j++)
                    wmma::mma_sync(cf[i][j], ah[i], bh[j], cf[i][j]);
        }
        __syncthreads();
    }

#pragma unroll
    for (int i = 0; i < 2; i++)
#pragma unroll
        for (int j = 0; j < 4; j++)
            wmma::store_matrix_sync(&scratch[(wm * 32 + i * 16) * 128 + wn * 64 + j * 16],
                                    cf[i][j], 128, wmma::mem_row_major);
    __syncthreads();

#pragma unroll
    for (int itx = 0; itx < 16; itx++) {
        int idx4 = tid + itx * 256;
        int r = idx4 >> 5;
        int c4 = (idx4 & 31) * 4;
        float4 v = *reinterpret_cast<const float4*>(&scratch[r * 128 + c4]);
        float4 b = *reinterpret_cast<const float4*>(&bias[n0 + c4]);
        v.x += b.x; v.y += b.y; v.z += b.z; v.w += b.w;
        if constexpr (sizeof(OutT) == 4) {
            *reinterpret_cast<float4*>(&C[(size_t)(m0 + r) * N + n0 + c4]) = v;
        } else {
            h16 hb[4];
            hb[0] = __float2half_rn(v.x); hb[1] = __float2half_rn(v.y);
            hb[2] = __float2half_rn(v.z); hb[3] = __float2half_rn(v.w);
            *reinterpret_cast<ull*>(&C[(size_t)(m0 + r) * N + n0 + c4]) =
                *reinterpret_cast<ull*>(hb);
        }
    }
}

// ---------------- persistent cooperative word-recurrent loop -----------------
// grid (4, 64) = 256 CTAs, occ 2. h carried fp16 only; gx fp16.
#define GB_ROWS 192
#define A64BY (64 * LDT2 * 2)       // 6144
#define B64BY (GB_ROWS * LDT2 * 2)  // 18432
#define GBUF2 (A64BY + B64BY)       // 24576 per buffer

__global__ __launch_bounds__(256, 2)
void gru_word_persistent(h16* __restrict__ sA, h16* __restrict__ sB,
                         const h16* __restrict__ Whp,
                         const float* __restrict__ bhh, const h16* __restrict__ gx)
{
    extern __shared__ __align__(128) char sm[];
    const uint32_t sbase = (uint32_t)__cvta_generic_to_shared(sm);
    float* scratch = reinterpret_cast<float*>(sm);   // 64x192 fp32 (48KB)

    cg::grid_group grid = cg::this_grid();

    const int tid = threadIdx.x;
    const int wid = tid >> 5;
    const int n0 = blockIdx.x * 64;
    const int m0 = blockIdx.y * 64;
    const int wm = wid & 1;
    const int wn = wid >> 1;

    const int lr = tid >> 2;
    const int lq = (tid & 3) * 8;
    const uint32_t arow = lr * (LDT2 * 2) + lq * 2;

    for (int t = 1; t < TWSTEPS; t++) {
        const int cur = (t - 1) & 1;
        const h16* Hhi  = cur ? sB : sA;
        h16*       Hout = cur ? sA : sB;

        const h16* gAh = Hhi + (size_t)(m0 + lr) * HDIM + lq;

        auto issue = [&](int it, int b) {
            const int kk = it * 32;
            uint32_t base = sbase + b * GBUF2;
            cp16(base + arow, gAh + kk);
#pragma unroll
            for (int rep = 0; rep < 3; rep++) {
                int task = tid + rep * 256;
                int rt = task >> 2;
                int q = (task & 3) * 8;
                int gate = rt / 64, col = rt - gate * 64;
                size_t srcoff = (size_t)(gate * HDIM + n0 + col) * HDIM + kk + q;
                cp16(base + A64BY + rt * (LDT2 * 2) + q * 2, Whp + srcoff);
            }
        };

        wmma::fragment<wmma::accumulator, 16, 16, 16, float> cf[2][3];
#pragma unroll
        for (int i = 0; i < 2; i++)
#pragma unroll
            for (int j = 0; j < 3; j++) wmma::fill_fragment(cf[i][j], 0.0f);

        issue(0, 0); CP_COMMIT();

        const int ntile = HDIM / 32;   // 8
        for (int it = 0; it < ntile; it++) {
            const int b = it & 1;
            if (it + 1 < ntile) { issue(it + 1, b ^ 1); CP_COMMIT(); CP_WAIT(1); }
            else                { CP_WAIT(0); }
            __syncthreads();

            const h16* tA = reinterpret_cast<const h16*>(sm + b * GBUF2);
            const h16* tB = tA + 64 * LDT2;

#pragma unroll
            for (int ks = 0; ks < 32; ks += 16) {
                wmma::fragment<wmma::matrix_a, 16, 16, 16, h16, wmma::row_major> ah[2];
#pragma unroll
                for (int i = 0; i < 2; i++)
                    wmma::load_matrix_sync(ah[i], tA + (wm * 32 + i * 16) * LDT2 + ks, LDT2);
#pragma unroll
                for (int j = 0; j < 3; j++) {
                    wmma::fragment<wmma::matrix_b, 16, 16, 16, h16, wmma::col_major> bh;
                    wmma::load_matrix_sync(bh, tB + (wn * 48 + j * 16) * LDT2 + ks, LDT2);
#pragma unroll
                    for (int i = 0; i < 2; i++)
                        wmma::mma_sync(cf[i][j], ah[i], bh, cf[i][j]);
                }
            }
            __syncthreads();
        }

        // stash gates to scratch [64][192]
#pragma unroll
        for (int i = 0; i < 2; i++)
#pragma unroll
            for (int j = 0; j < 3; j++)
                wmma::store_matrix_sync(&scratch[(wm * 32 + i * 16) * 192 + wn * 48 + j * 16],
                                        cf[i][j], 192, wmma::mem_row_major);
        __syncthreads();

        // fused GRU epilogue (fp16 gx, fp16 h)
#pragma unroll
        for (int itx = 0; itx < 4; itx++) {
            int task = tid + itx * 256;
            int r = task >> 4;
            int c4 = (task & 15) * 4;
            const int row = m0 + r;
            const int j = n0 + c4;
            const float* srow2 = &scratch[r * 192];
            float gr[4], gz[4], gn[4];
            *reinterpret_cast<float4*>(gr) = *reinterpret_cast<const float4*>(srow2 + c4);
            *reinterpret_cast<float4*>(gz) = *reinterpret_cast<const float4*>(srow2 + 64 + c4);
            *reinterpret_cast<float4*>(gn) = *reinterpret_cast<const float4*>(srow2 + 128 + c4);
            float br[4], bz[4], bn[4], xr[4], xz[4], xn[4], hh[4];
            *reinterpret_cast<float4*>(br) = *reinterpret_cast<const float4*>(bhh + j);
            *reinterpret_cast<float4*>(bz) = *reinterpret_cast<const float4*>(bhh + HDIM + j);
            *reinterpret_cast<float4*>(bn) = *reinterpret_cast<const float4*>(bhh + 2 * HDIM + j);
            const h16* gxp = gx + ((size_t)row * TWSTEPS + t) * GDIM;
            ld_h4(xr, gxp + j);
            ld_h4(xz, gxp + HDIM + j);
            ld_h4(xn, gxp + 2 * HDIM + j);
            ld_h4(hh, Hhi + (size_t)row * HDIM + j);
            h16 hb[4];
#pragma unroll
            for (int u = 0; u < 4; u++) {
                float rr = sigmoid_f(xr[u] + gr[u] + br[u]);
                float zz = sigmoid_f(xz[u] + gz[u] + bz[u]);
                float nv = tanhf(xn[u] + rr * (gn[u] + bn[u]));
                float h = (1.f - zz) * nv + zz * hh[u];
                hb[u] = __float2half_rn(h);
            }
            *reinterpret_cast<ull*>(Hout + (size_t)row * HDIM + j) = *reinterpret_cast<ull*>(hb);
        }
        __syncthreads();
        grid.sync();
    }
}

// ---------------- t=0 GRU steps ----------------
__global__ void gru_init_h16(const h16* __restrict__ gx, const float* __restrict__ bhh,
                             h16* __restrict__ hi, int Mseq, int T)
{
    int i = blockIdx.x * blockDim.x + threadIdx.x;
    if (i >= Mseq * HDIM) return;
    int seq = i >> 8, j = i & 255;
    const h16* g = gx + (size_t)seq * T * GDIM;
    float xr = __half2float(g[j]);
    float xz = __half2float(g[j + HDIM]);
    float xn = __half2float(g[j + 2 * HDIM]);
    float r = sigmoid_f(xr + bhh[j]);
    float z = sigmoid_f(xz + bhh[j + HDIM]);
    float n = tanhf(xn + r * bhh[j + 2 * HDIM]);
    hi[i] = __float2half_rn((1.f - z) * n);
}

__global__ void gru_init_plain(const float* __restrict__ gx, const float* __restrict__ bhh,
                               float* __restrict__ hout, int Mseq, int T)
{
    int i = blockIdx.x * blockDim.x + threadIdx.x;
    if (i >= Mseq * HDIM) return;
    int seq = i >> 8, j = i & 255;
    const float* g = gx + (size_t)seq * T * GDIM;
    float r = sigmoid_f(g[j] + bhh[j]);
    float z = sigmoid_f(g[j + HDIM] + bhh[j + HDIM]);
    float n = tanhf(g[j + 2 * HDIM] + r * bhh[j + 2 * HDIM]);
    hout[i] = (1.f - z) * n;
}

// ---------------- fused multi-step GRU tail ----------------------------------
template <int NSEQ>
__global__ __launch_bounds__(256)
void gru_tail_fused(const float* __restrict__ h0, const h16* __restrict__ W16,
                    const float* __restrict__ bhh, const float* __restrict__ gx,
                    int T, float* __restrict__ hfinal)
{
    __shared__ float hs[HDIM][NSEQ];
    const int tid = threadIdx.x;
    const int seq0 = blockIdx.x * NSEQ;

    for (int i = tid; i < NSEQ * HDIM; i += 256) {
        int s = i / HDIM, k = i - s * HDIM;
        hs[k][s] = h0[(size_t)(seq0 + s) * HDIM + k];
    }
    __syncthreads();

    const int j = tid;
    const h16* wr = W16 + (size_t)j * HDIM;
    const h16* wz = W16 + (size_t)(HDIM + j) * HDIM;
    const h16* wn_ = W16 + (size_t)(2 * HDIM + j) * HDIM;
    const float br = bhh[j], bz = bhh[HDIM + j], bn = bhh[2 * HDIM + j];

    for (int t = 1; t < T; t++) {
        float ar[NSEQ], az[NSEQ], an[NSEQ];
#pragma unroll
        for (int s = 0; s < NSEQ; s++) { ar[s] = 0.f; az[s] = 0.f; an[s] = 0.f; }

#pragma unroll 4
        for (int k = 0; k < HDIM; k += 8) {
            uint4 vr = *reinterpret_cast<const uint4*>(wr + k);
            uint4 vz = *reinterpret_cast<const uint4*>(wz + k);
            uint4 vn = *reinterpret_cast<const uint4*>(wn_ + k);
            const h16* pr = reinterpret_cast<const h16*>(&vr);
            const h16* pz = reinterpret_cast<const h16*>(&vz);
            const h16* pn = reinterpret_cast<const h16*>(&vn);
#pragma unroll
            for (int u = 0; u < 8; u++) {
                float fr = __half2float(pr[u]);
                float fz = __half2float(pz[u]);
                float fn = __half2float(pn[u]);
#pragma unroll
                for (int s = 0; s < NSEQ; s++) {
                    float hv = hs[k + u][s];
                    ar[s] = fmaf(fr, hv, ar[s]);
                    az[s] = fmaf(fz, hv, az[s]);
                    an[s] = fmaf(fn, hv, an[s]);
                }
            }
        }
        __syncthreads();

        float hnew[NSEQ];
#pragma unroll
        for (int s = 0; s < NSEQ; s++) {
            const float* gxp = gx + ((size_t)(seq0 + s) * T + t) * GDIM;
            float r = sigmoid_f(gxp[j] + ar[s] + br);
            float z = sigmoid_f(gxp[HDIM + j] + az[s] + bz);
            float n = tanhf(gxp[2 * HDIM + j] + r * (an[s] + bn));
            hnew[s] = (1.f - z) * n + z * hs[j][s];
        }
#pragma unroll
        for (int s = 0; s < NSEQ; s++) hs[j][s] = hnew[s];
        __syncthreads();
    }

    for (int i = tid; i < NSEQ * HDIM; i += 256) {
        int s = i / HDIM, k = i - s * HDIM;
        hfinal[(size_t)(seq0 + s) * HDIM + k] = hs[k][s];
    }
}

// ---------------- fp32 SGEMM (review gx) ----------------
#define BM 128
#define BN 128
#define BK 8
__global__ __launch_bounds__(256, 2)
void sgemm_f32x2(const float* __restrict__ A, const float* __restrict__ W,
                 const float* __restrict__ bias, float* __restrict__ C,
                 int M, int K, int N)
{
    __shared__ float As[2][BK][BM];
    __shared__ float Bs[2][BK][BN];
    const int tid = threadIdx.x;
    const int m0 = blockIdx.y * BM;
    const int n0 = blockIdx.x * BN;
    const int a_m = tid & 127, a_kq = tid >> 7;
    const int b_n = tid >> 1,  b_kq = tid & 1;
    const bool a_valid = (m0 + a_m) < M;
    const float* Arow = A + (size_t)(a_valid ? (m0 + a_m) : 0) * K;
    const float* Brow = W + (size_t)(n0 + b_n) * K;
    const int tx = tid & 15, ty = tid >> 4;

    ull acc2[8][4];
#pragma unroll
    for (int i = 0; i < 8; i++)
#pragma unroll
        for (int j = 0; j < 4; j++) acc2[i][j] = 0ull;

    float4 av = make_float4(0.f, 0.f, 0.f, 0.f);
    if (a_valid) av = *reinterpret_cast<const float4*>(Arow + a_kq * 4);
    float4 bv = *reinterpret_cast<const float4*>(Brow + b_kq * 4);
    As[0][a_kq * 4 + 0][a_m] = av.x;  As[0][a_kq * 4 + 1][a_m] = av.y;
    As[0][a_kq * 4 + 2][a_m] = av.z;  As[0][a_kq * 4 + 3][a_m] = av.w;
    Bs[0][b_kq * 4 + 0][b_n] = bv.x;  Bs[0][b_kq * 4 + 1][b_n] = bv.y;
    Bs[0][b_kq * 4 + 2][b_n] = bv.z;  Bs[0][b_kq * 4 + 3][b_n] = bv.w;
    __syncthreads();

    int buf = 0;
    for (int kk = 0; kk < K; kk += BK) {
        const bool has_next = (kk + BK) < K;
        if (has_next) {
            if (a_valid) av = *reinterpret_cast<const float4*>(Arow + kk + BK + a_kq * 4);
            bv = *reinterpret_cast<const float4*>(Brow + kk + BK + b_kq * 4);
        }
#pragma unroll
        for (int k = 0; k < BK; k++) {
            float4 a0 = *reinterpret_cast<const float4*>(&As[buf][k][ty * 8]);
            float4 a1 = *reinterpret_cast<const float4*>(&As[buf][k][ty * 8 + 4]);
            ulonglong2 bq0 = *reinterpret_cast<const ulonglong2*>(&Bs[buf][k][tx * 8]);
            ulonglong2 bq1 = *reinterpret_cast<const ulonglong2*>(&Bs[buf][k][tx * 8 + 4]);
            ull bp[4] = {bq0.x, bq0.y, bq1.x, bq1.y};
            float a[8] = {a0.x, a0.y, a0.z, a0.w, a1.x, a1.y, a1.z, a1.w};
#pragma unroll
            for (int i = 0; i < 8; i++) {
                ull ad = dup2(a[i]);
#pragma unroll
                for (int j = 0; j < 4; j++) ffma2(acc2[i][j], ad, bp[j]);
            }
        }
        if (has_next) {
            int nb = buf ^ 1;
            As[nb][a_kq * 4 + 0][a_m] = av.x;  As[nb][a_kq * 4 + 1][a_m] = av.y;
            As[nb][a_kq * 4 + 2][a_m] = av.z;  As[nb][a_kq * 4 + 3][a_m] = av.w;
            Bs[nb][b_kq * 4 + 0][b_n] = bv.x;  Bs[nb][b_kq * 4 + 1][b_n] = bv.y;
            Bs[nb][b_kq * 4 + 2][b_n] = bv.z;  Bs[nb][b_kq * 4 + 3][b_n] = bv.w;
            __syncthreads();
            buf = nb;
        }
    }
#pragma unroll
    for (int i = 0; i < 8; i++) {
        int row = m0 + ty * 8 + i;
        if (row >= M) continue;
#pragma unroll
        for (int j = 0; j < 4; j++) {
            int col = n0 + tx * 8 + j * 2;
            float2 p = unpack2(acc2[i][j]);
            float2 bb = *reinterpret_cast<const float2*>(bias + col);
            float2 o; o.x = p.x + bb.x; o.y = p.y + bb.y;
            *reinterpret_cast<float2*>(C + (size_t)row * N + col) = o;
        }
    }
}

// ---------------- MLP ----------------
__global__ __launch_bounds__(128)
void mlp_kernel(const float* __restrict__ X,
                const float* __restrict__ W1, const float* __restrict__ b1,
                const float* __restrict__ W2, const float* __restrict__ b2,
                float* __restrict__ out)
{
    const int row = blockIdx.x;
    const int i = threadIdx.x;
    __shared__ float xs[HDIM];
    __shared__ float red[4];
    xs[i]       = X[(size_t)row * HDIM + i];
    xs[i + 128] = X[(size_t)row * HDIM + i + 128];
    __syncthreads();
    const float* w = W1 + (size_t)i * HDIM;
    float acc = b1[i];
#pragma unroll 8
    for (int k = 0; k < HDIM; k += 4) {
        float4 wv = *reinterpret_cast<const float4*>(w + k);
        acc = fmaf(wv.x, xs[k], acc);
        acc = fmaf(wv.y, xs[k + 1], acc);
        acc = fmaf(wv.z, xs[k + 2], acc);
        acc = fmaf(wv.w, xs[k + 3], acc);
    }
    const float scale = 1.0507009873554805f;
    const float alpha = 1.6732632423543772f;
    float s = scale * (acc > 0.f ? acc : alpha * (expf(acc) - 1.f));
    float v = s * W2[i];
#pragma unroll
    for (int off = 16; off > 0; off >>= 1)
        v += __shfl_down_sync(0xffffffffu, v, off);
    if ((i & 31) == 0) red[i >> 5] = v;
    __syncthreads();
    if (i == 0) out[row] = red[0] + red[1] + red[2] + red[3] + b2[0];
}

// ---------------- host orchestration ----------------
extern "C" void kernel_launch(void* const* d_in, const int* in_sizes, int n_in,
                              void* d_out, int out_size)
{
    (void)in_sizes; (void)n_in; (void)out_size;

    const int*   idx    = (const int*)  d_in[0];
    const float* emb    = (const float*)d_in[1];
    const float* w_Wih  = (const float*)d_in[2];
    const float* w_Whh  = (const float*)d_in[3];
    const float* w_bih  = (const float*)d_in[4];
    const float* w_bhh  = (const float*)d_in[5];
    const float* s_Wih  = (const float*)d_in[6];
    const float* s_Whh  = (const float*)d_in[7];
    const float* s_bih  = (const float*)d_in[8];
    const float* s_bhh  = (const float*)d_in[9];
    const float* r_Wih  = (const float*)d_in[10];
    const float* r_Whh  = (const float*)d_in[11];
    const float* r_bih  = (const float*)d_in[12];
    const float* r_bhh  = (const float*)d_in[13];
    const float* rfc_W1 = (const float*)d_in[14];
    const float* rfc_b1 = (const float*)d_in[15];
    const float* rfc_W2 = (const float*)d_in[16];
    const float* rfc_b2 = (const float*)d_in[17];
    const float* pfc_W1 = (const float*)d_in[18];
    const float* pfc_b1 = (const float*)d_in[19];
    const float* pfc_W2 = (const float*)d_in[20];
    const float* pfc_b2 = (const float*)d_in[21];
    float* out = (float*)d_out;

    float *GXs, *GXr, *HsA, *HsB, *HrA, *HrB;
    h16 *GXw, *Xh, *WihH, *WhhH, *WsH, *WshhH, *WrhhH, *SHiA, *SHiB;
    cudaGetSymbolAddress((void**)&GXw, g_GXw);
    cudaGetSymbolAddress((void**)&GXs, g_GXs);
    cudaGetSymbolAddress((void**)&GXr, g_GXr);
    cudaGetSymbolAddress((void**)&HsA, g_HsA);
    cudaGetSymbolAddress((void**)&HsB, g_HsB);
    cudaGetSymbolAddress((void**)&HrA, g_HrA);
    cudaGetSymbolAddress((void**)&HrB, g_HrB);
    cudaGetSymbolAddress((void**)&Xh, g_Xh);
    cudaGetSymbolAddress((void**)&WihH, g_WihH);
    cudaGetSymbolAddress((void**)&WhhH, g_WhhH);
    cudaGetSymbolAddress((void**)&WsH, g_WsH);
    cudaGetSymbolAddress((void**)&WshhH, g_WshhH);
    cudaGetSymbolAddress((void**)&WrhhH, g_WrhhH);
    cudaGetSymbolAddress((void**)&SHiA, g_SHiA);
    cudaGetSymbolAddress((void**)&SHiB, g_SHiB);

    const int SMEM_GEMM = 65536;
    const int SMEM_GRU  = 2 * GBUF2;   // 49152
    cudaFuncSetAttribute(gemm_wmma2<h16>, cudaFuncAttributeMaxDynamicSharedMemorySize, SMEM_GEMM);
    cudaFuncSetAttribute(gemm_wmma2<float>, cudaFuncAttributeMaxDynamicSharedMemorySize, SMEM_GEMM);
    cudaFuncSetAttribute(gru_word_persistent, cudaFuncAttributeMaxDynamicSharedMemorySize, SMEM_GRU);

    // ---- prep ----
    split_w_single<<<(GDIM * KPAD + 255) / 256, 256>>>(w_Wih, WihH, GDIM, EDIM, KPAD);
    {
        int n4 = GDIM * HDIM / 4;   // per-matrix float4 count
        split_w_quad<<<(4 * n4 + 255) / 256, 256>>>(w_Whh, WhhH, s_Wih, WsH,
                                                    s_Whh, WshhH, r_Whh, WrhhH, n4);
    }
    gather_h16_kernel<<<(int)(((size_t)MW * KP4 + 255) / 256), 256>>>(idx, emb, Xh);

    // ---- word level: gx (fp16 out) ----
    gemm_wmma2<h16><<<dim3(GDIM / 128, MW / 128), 256, SMEM_GEMM>>>(Xh, WihH,
                                                                    w_bih, GXw, KPAD, GDIM);

    // t=0, then persistent cooperative loop t=1..31 (fp16 h)
    gru_init_h16<<<(NW * HDIM + 255) / 256, 256>>>(GXw, w_bhh, SHiA, NW, TWSTEPS);
    {
        cudaLaunchConfig_t cfg = {};
        cfg.gridDim = dim3(HDIM / 64, NW / 64);     // (4, 64) = 256 CTAs
        cfg.blockDim = dim3(256, 1, 1);
        cfg.dynamicSmemBytes = SMEM_GRU;
        cudaLaunchAttribute attr;
        attr.id = cudaLaunchAttributeCooperative;
        attr.val.cooperative = 1;
        cfg.attrs = &attr;
        cfg.numAttrs = 1;
        cudaLaunchKernelEx(&cfg, gru_word_persistent,
                           SHiA, SHiB, (const h16*)WhhH,
                           (const float*)w_bhh, (const h16*)GXw);
    }
    // 31 iterations: final h in B buffers
    h16* sent_hi = SHiB;

    // ---- sentence level (fp32 gx out for tail) ----
    gemm_wmma2<float><<<dim3(GDIM / 128, (NS * TSSTEPS) / 128), 256, SMEM_GEMM>>>(
        sent_hi, WsH, s_bih, GXs, HDIM, GDIM);

    gru_init_plain<<<(NS * HDIM + 255) / 256, 256>>>(GXs, s_bhh, HsA, NS, TSSTEPS);
    gru_tail_fused<4><<<NS / 4, 256>>>(HsA, WshhH, s_bhh, GXs, TSSTEPS, HsB);
    const float* p_batch = HsB;

    // r_stars -> out[16 .. 272)
    mlp_kernel<<<NS, 128>>>(p_batch, rfc_W1, rfc_b1, rfc_W2, rfc_b2, out + NR);

    // ---- review level ----
    {
        dim3 grid(GDIM / BN, (NR * TRSTEPS + BM - 1) / BM);
        sgemm_f32x2<<<grid, 256>>>(p_batch, r_Wih, r_bih, GXr, NR * TRSTEPS, HDIM, GDIM);
    }
    gru_init_plain<<<(NR * HDIM + 255) / 256, 256>>>(GXr, r_bhh, HrA, NR, TRSTEPS);
    gru_tail_fused<1><<<NR, 256>>>(HrA, WrhhH, r_bhh, GXr, TRSTEPS, HrB);

    // b_stars -> out[0 .. 16)
    mlp_kernel<<<NR, 128>>>(HrB, pfc_W1, pfc_b1, pfc_W2, pfc_b2, out);
}

// round 12
// speedup vs baseline: 4.1638x; 1.0370x over previous
#include <cuda_runtime.h>
#include <cuda_fp16.h>
#include <mma.h>
#include <cooperative_groups.h>
#include <math.h>
#include <stdint.h>

using namespace nvcuda;
namespace cg = cooperative_groups;

// ---------------- problem dims ----------------
#define HDIM 256
#define GDIM 768
#define EDIM 200
#define NW 4096
#define TWSTEPS 32
#define NS 256
#define TSSTEPS 16
#define NR 16
#define TRSTEPS 16
#define MW (NW * TWSTEPS)
#define KPAD 224
#define KP4 (KPAD / 4)

typedef unsigned long long ull;
typedef __half h16;

// ---------------- scratch ----------------
__device__ __align__(16) h16 g_GXw[(size_t)MW * GDIM];   // fp16 word input gates
__device__ float g_GXs[(size_t)NS * TSSTEPS * GDIM];
__device__ float g_GXr[(size_t)NR * TRSTEPS * GDIM];
__device__ float g_HsA[NS * HDIM], g_HsB[NS * HDIM];
__device__ float g_HrA[NR * HDIM], g_HrB[NR * HDIM];
__device__ __align__(16) h16 g_Xh[(size_t)MW * KPAD];
__device__ __align__(16) h16 g_WihH[GDIM * KPAD];
__device__ __align__(16) h16 g_WhhH[GDIM * HDIM];
__device__ __align__(16) h16 g_WsH [GDIM * HDIM];
__device__ __align__(16) h16 g_WshhH[GDIM * HDIM];
__device__ __align__(16) h16 g_WrhhH[GDIM * HDIM];
__device__ __align__(16) h16 g_SHiA[NW * HDIM], g_SHiB[NW * HDIM];

// ---------------- helpers ----------------
__device__ __forceinline__ float sigmoid_f(float x) { return 1.f / (1.f + expf(-x)); }
__device__ __forceinline__ ull pack2(float lo, float hi) {
    ull r; asm("mov.b64 %0, {%1, %2};" : "=l"(r) : "f"(lo), "f"(hi)); return r;
}
__device__ __forceinline__ ull dup2(float v) { return pack2(v, v); }
__device__ __forceinline__ void ffma2(ull& d, ull a, ull b) {
    asm("fma.rn.f32x2 %0, %1, %2, %3;" : "=l"(d) : "l"(a), "l"(b), "l"(d));
}
__device__ __forceinline__ float2 unpack2(ull v) {
    float2 f; asm("mov.b64 {%0, %1}, %2;" : "=f"(f.x), "=f"(f.y) : "l"(v)); return f;
}
__device__ __forceinline__ void cp16(uint32_t s, const void* g) {
    asm volatile("cp.async.cg.shared.global [%0], [%1], 16;" :: "r"(s), "l"(g));
}
#define CP_COMMIT() asm volatile("cp.async.commit_group;" ::: "memory")
#define CP_WAIT(n)  asm volatile("cp.async.wait_group %0;" :: "n"(n) : "memory")

__device__ __forceinline__ void ld_h4(float* o, const h16* p) {
    ull v = *reinterpret_cast<const ull*>(p);
    const h16* q = reinterpret_cast<const h16*>(&v);
    o[0] = __half2float(q[0]); o[1] = __half2float(q[1]);
    o[2] = __half2float(q[2]); o[3] = __half2float(q[3]);
}

// ---------------- prep kernels ----------------
__global__ void split_w_single(const float* __restrict__ src, h16* __restrict__ dst,
                               int rows, int cs, int cd)
{
    int i = blockIdx.x * blockDim.x + threadIdx.x;
    if (i >= rows * cd) return;
    int r = i / cd, c = i - r * cd;
    float v = (c < cs) ? src[(size_t)r * cs + c] : 0.f;
    dst[i] = __float2half_rn(v);
}

__global__ void split_w_quad(const float* s0, h16* d0, const float* s1, h16* d1,
                             const float* s2, h16* d2, const float* s3, h16* d3,
                             int n4)
{
    int i = blockIdx.x * blockDim.x + threadIdx.x;
    int mat = i / n4;
    int off = (i - mat * n4) * 4;
    if (mat >= 4) return;
    const float* s = (mat == 0) ? s0 : (mat == 1) ? s1 : (mat == 2) ? s2 : s3;
    h16* d = (mat == 0) ? d0 : (mat == 1) ? d1 : (mat == 2) ? d2 : d3;
    float4 v = *reinterpret_cast<const float4*>(s + off);
    h16 hb[4];
    hb[0] = __float2half_rn(v.x); hb[1] = __float2half_rn(v.y);
    hb[2] = __float2half_rn(v.z); hb[3] = __float2half_rn(v.w);
    *reinterpret_cast<ull*>(d + off) = *reinterpret_cast<ull*>(hb);
}

__global__ void gather_h16_kernel(const int* __restrict__ idx, const float* __restrict__ emb,
                                  h16* __restrict__ hi)
{
    size_t id = (size_t)blockIdx.x * blockDim.x + threadIdx.x;
    if (id >= (size_t)MW * KP4) return;
    int row = (int)(id / KP4);
    int c4 = (int)(id - (size_t)row * KP4) * 4;
    float4 v = make_float4(0.f, 0.f, 0.f, 0.f);
    if (c4 < EDIM)
        v = *reinterpret_cast<const float4*>(emb + (size_t)idx[row] * EDIM + c4);
    h16 hb[4];
    hb[0] = __float2half_rn(v.x); hb[1] = __float2half_rn(v.y);
    hb[2] = __float2half_rn(v.z); hb[3] = __float2half_rn(v.w);
    *reinterpret_cast<ull*>(hi + (size_t)row * KPAD + c4) = *reinterpret_cast<ull*>(hb);
}

// ---------------- wmma fp16 GEMM: C = A@W^T + bias (OutT = float or h16) ----
// LDT2 = 40 halfs = 80B row stride: 80/16 = 5 (coprime with 8) -> conflict-free LDSM.
#define LDT2 40
#define TBY (128 * LDT2 * 2)         // 10240B per matrix tile
#define GEMM_BUF (2 * TBY)

template <typename OutT>
__global__ __launch_bounds__(256, 2)
void gemm_wmma2(const h16* __restrict__ Ahp, const h16* __restrict__ Whp,
                const float* __restrict__ bias, OutT* __restrict__ C,
                int K, int N)
{
    extern __shared__ __align__(128) char sm[];
    const uint32_t sbase = (uint32_t)__cvta_generic_to_shared(sm);
    float* scratch = reinterpret_cast<float*>(sm);

    const int tid = threadIdx.x;
    const int wid = tid >> 5;
    const int m0 = blockIdx.y * 128, n0 = blockIdx.x * 128;
    const int wm = wid & 3, wn = wid >> 2;

    const int lr = tid >> 1;
    const int lq = (tid & 1) * 16;

    const h16* gA = Ahp + (size_t)(m0 + lr) * K + lq;
    const h16* gB = Whp + (size_t)(n0 + lr) * K + lq;
    const uint32_t srow = lr * LDT2 * 2 + lq * 2;

    const int ntile = K / 32;

    wmma::fragment<wmma::accumulator, 16, 16, 16, float> cf[2][4];
#pragma unroll
    for (int i = 0; i < 2; i++)
#pragma unroll
        for (int j = 0; j < 4; j++) wmma::fill_fragment(cf[i][j], 0.0f);

    auto issue = [&](int it, int b) {
        const int kk = it * 32;
        uint32_t base = sbase + b * GEMM_BUF;
        cp16(base + srow,            gA + kk);
        cp16(base + srow + 16,       gA + kk + 8);
        cp16(base + TBY + srow,      gB + kk);
        cp16(base + TBY + srow + 16, gB + kk + 8);
    };

    issue(0, 0); CP_COMMIT();

    for (int it = 0; it < ntile; it++) {
        const int b = it & 1;
        if (it + 1 < ntile) { issue(it + 1, b ^ 1); CP_COMMIT(); CP_WAIT(1); }
        else                { CP_WAIT(0); }
        __syncthreads();

        const h16* tA = reinterpret_cast<const h16*>(sm + b * GEMM_BUF);
        const h16* tB = tA + 128 * LDT2;

#pragma unroll
        for (int ks = 0; ks < 32; ks += 16) {
            wmma::fragment<wmma::matrix_a, 16, 16, 16, h16, wmma::row_major> ah[2];
            wmma::fragment<wmma::matrix_b, 16, 16, 16, h16, wmma::col_major> bh[4];
#pragma unroll
            for (int i = 0; i < 2; i++)
                wmma::load_matrix_sync(ah[i], tA + (wm * 32 + i * 16) * LDT2 + ks, LDT2);
#pragma unroll
            for (int j = 0; j < 4; j++)
                wmma::load_matrix_sync(bh[j], tB + (wn * 64 + j * 16) * LDT2 + ks, LDT2);
#pragma unroll
            for (int i = 0; i < 2; i++)
#pragma unroll
                for (int j = 0; j < 4; j++)
                    wmma::mma_sync(cf[i][j], ah[i], bh[j], cf[i][j]);
        }
        __syncthreads();
    }

#pragma unroll
    for (int i = 0; i < 2; i++)
#pragma unroll
        for (int j = 0; j < 4; j++)
            wmma::store_matrix_sync(&scratch[(wm * 32 + i * 16) * 128 + wn * 64 + j * 16],
                                    cf[i][j], 128, wmma::mem_row_major);
    __syncthreads();

#pragma unroll
    for (int itx = 0; itx < 16; itx++) {
        int idx4 = tid + itx * 256;
        int r = idx4 >> 5;
        int c4 = (idx4 & 31) * 4;
        float4 v = *reinterpret_cast<const float4*>(&scratch[r * 128 + c4]);
        float4 b = *reinterpret_cast<const float4*>(&bias[n0 + c4]);
        v.x += b.x; v.y += b.y; v.z += b.z; v.w += b.w;
        if constexpr (sizeof(OutT) == 4) {
            *reinterpret_cast<float4*>(&C[(size_t)(m0 + r) * N + n0 + c4]) = v;
        } else {
            h16 hb[4];
            hb[0] = __float2half_rn(v.x); hb[1] = __float2half_rn(v.y);
            hb[2] = __float2half_rn(v.z); hb[3] = __float2half_rn(v.w);
            *reinterpret_cast<ull*>(&C[(size_t)(m0 + r) * N + n0 + c4]) =
                *reinterpret_cast<ull*>(hb);
        }
    }
}

// ---------------- persistent cooperative word-recurrent loop -----------------
#define GB_ROWS 192
#define A64BY (64 * LDT2 * 2)       // 5120
#define B64BY (GB_ROWS * LDT2 * 2)  // 15360
#define GBUF2 (A64BY + B64BY)       // 20480 per buffer

__global__ __launch_bounds__(256, 2)
void gru_word_persistent(h16* __restrict__ sA, h16* __restrict__ sB,
                         const h16* __restrict__ Whp,
                         const float* __restrict__ bhh, const h16* __restrict__ gx)
{
    extern __shared__ __align__(128) char sm[];
    const uint32_t sbase = (uint32_t)__cvta_generic_to_shared(sm);
    float* scratch = reinterpret_cast<float*>(sm);   // 64x192 fp32 (48KB)

    cg::grid_group grid = cg::this_grid();

    const int tid = threadIdx.x;
    const int wid = tid >> 5;
    const int n0 = blockIdx.x * 64;
    const int m0 = blockIdx.y * 64;
    const int wm = wid & 1;
    const int wn = wid >> 1;

    const int lr = tid >> 2;
    const int lq = (tid & 3) * 8;
    const uint32_t arow = lr * (LDT2 * 2) + lq * 2;

    for (int t = 1; t < TWSTEPS; t++) {
        const int cur = (t - 1) & 1;
        const h16* Hhi  = cur ? sB : sA;
        h16*       Hout = cur ? sA : sB;

        const h16* gAh = Hhi + (size_t)(m0 + lr) * HDIM + lq;

        auto issue = [&](int it, int b) {
            const int kk = it * 32;
            uint32_t base = sbase + b * GBUF2;
            cp16(base + arow, gAh + kk);
#pragma unroll
            for (int rep = 0; rep < 3; rep++) {
                int task = tid + rep * 256;
                int rt = task >> 2;
                int q = (task & 3) * 8;
                int gate = rt / 64, col = rt - gate * 64;
                size_t srcoff = (size_t)(gate * HDIM + n0 + col) * HDIM + kk + q;
                cp16(base + A64BY + rt * (LDT2 * 2) + q * 2, Whp + srcoff);
            }
        };

        wmma::fragment<wmma::accumulator, 16, 16, 16, float> cf[2][3];
#pragma unroll
        for (int i = 0; i < 2; i++)
#pragma unroll
            for (int j = 0; j < 3; j++) wmma::fill_fragment(cf[i][j], 0.0f);

        issue(0, 0); CP_COMMIT();

        const int ntile = HDIM / 32;   // 8
        for (int it = 0; it < ntile; it++) {
            const int b = it & 1;
            if (it + 1 < ntile) { issue(it + 1, b ^ 1); CP_COMMIT(); CP_WAIT(1); }
            else                { CP_WAIT(0); }
            __syncthreads();

            const h16* tA = reinterpret_cast<const h16*>(sm + b * GBUF2);
            const h16* tB = tA + 64 * LDT2;

#pragma unroll
            for (int ks = 0; ks < 32; ks += 16) {
                wmma::fragment<wmma::matrix_a, 16, 16, 16, h16, wmma::row_major> ah[2];
#pragma unroll
                for (int i = 0; i < 2; i++)
                    wmma::load_matrix_sync(ah[i], tA + (wm * 32 + i * 16) * LDT2 + ks, LDT2);
#pragma unroll
                for (int j = 0; j < 3; j++) {
                    wmma::fragment<wmma::matrix_b, 16, 16, 16, h16, wmma::col_major> bh;
                    wmma::load_matrix_sync(bh, tB + (wn * 48 + j * 16) * LDT2 + ks, LDT2);
#pragma unroll
                    for (int i = 0; i < 2; i++)
                        wmma::mma_sync(cf[i][j], ah[i], bh, cf[i][j]);
                }
            }
            __syncthreads();
        }

        // stash gates to scratch [64][192]
#pragma unroll
        for (int i = 0; i < 2; i++)
#pragma unroll
            for (int j = 0; j < 3; j++)
                wmma::store_matrix_sync(&scratch[(wm * 32 + i * 16) * 192 + wn * 48 + j * 16],
                                        cf[i][j], 192, wmma::mem_row_major);
        __syncthreads();

        // fused GRU epilogue (fp16 gx, fp16 h)
#pragma unroll
        for (int itx = 0; itx < 4; itx++) {
            int task = tid + itx * 256;
            int r = task >> 4;
            int c4 = (task & 15) * 4;
            const int row = m0 + r;
            const int j = n0 + c4;
            const float* srow2 = &scratch[r * 192];
            float gr[4], gz[4], gn[4];
            *reinterpret_cast<float4*>(gr) = *reinterpret_cast<const float4*>(srow2 + c4);
            *reinterpret_cast<float4*>(gz) = *reinterpret_cast<const float4*>(srow2 + 64 + c4);
            *reinterpret_cast<float4*>(gn) = *reinterpret_cast<const float4*>(srow2 + 128 + c4);
            float br[4], bz[4], bn[4], xr[4], xz[4], xn[4], hh[4];
            *reinterpret_cast<float4*>(br) = *reinterpret_cast<const float4*>(bhh + j);
            *reinterpret_cast<float4*>(bz) = *reinterpret_cast<const float4*>(bhh + HDIM + j);
            *reinterpret_cast<float4*>(bn) = *reinterpret_cast<const float4*>(bhh + 2 * HDIM + j);
            const h16* gxp = gx + ((size_t)row * TWSTEPS + t) * GDIM;
            ld_h4(xr, gxp + j);
            ld_h4(xz, gxp + HDIM + j);
            ld_h4(xn, gxp + 2 * HDIM + j);
            ld_h4(hh, Hhi + (size_t)row * HDIM + j);
            h16 hb[4];
#pragma unroll
            for (int u = 0; u < 4; u++) {
                float rr = sigmoid_f(xr[u] + gr[u] + br[u]);
                float zz = sigmoid_f(xz[u] + gz[u] + bz[u]);
                float nv = tanhf(xn[u] + rr * (gn[u] + bn[u]));
                float h = (1.f - zz) * nv + zz * hh[u];
                hb[u] = __float2half_rn(h);
            }
            *reinterpret_cast<ull*>(Hout + (size_t)row * HDIM + j) = *reinterpret_cast<ull*>(hb);
        }
        __syncthreads();
        grid.sync();
    }
}

// ---------------- t=0 GRU steps ----------------
__global__ void gru_init_h16(const h16* __restrict__ gx, const float* __restrict__ bhh,
                             h16* __restrict__ hi, int Mseq, int T)
{
    int i = blockIdx.x * blockDim.x + threadIdx.x;
    if (i >= Mseq * HDIM) return;
    int seq = i >> 8, j = i & 255;
    const h16* g = gx + (size_t)seq * T * GDIM;
    float xr = __half2float(g[j]);
    float xz = __half2float(g[j + HDIM]);
    float xn = __half2float(g[j + 2 * HDIM]);
    float r = sigmoid_f(xr + bhh[j]);
    float z = sigmoid_f(xz + bhh[j + HDIM]);
    float n = tanhf(xn + r * bhh[j + 2 * HDIM]);
    hi[i] = __float2half_rn((1.f - z) * n);
}

__global__ void gru_init_plain(const float* __restrict__ gx, const float* __restrict__ bhh,
                               float* __restrict__ hout, int Mseq, int T)
{
    int i = blockIdx.x * blockDim.x + threadIdx.x;
    if (i >= Mseq * HDIM) return;
    int seq = i >> 8, j = i & 255;
    const float* g = gx + (size_t)seq * T * GDIM;
    float r = sigmoid_f(g[j] + bhh[j]);
    float z = sigmoid_f(g[j + HDIM] + bhh[j + HDIM]);
    float n = tanhf(g[j + 2 * HDIM] + r * bhh[j + 2 * HDIM]);
    hout[i] = (1.f - z) * n;
}

// ---------------- fused multi-step GRU tail ----------------------------------
template <int NSEQ>
__global__ __launch_bounds__(256)
void gru_tail_fused(const float* __restrict__ h0, const h16* __restrict__ W16,
                    const float* __restrict__ bhh, const float* __restrict__ gx,
                    int T, float* __restrict__ hfinal)
{
    __shared__ float hs[HDIM][NSEQ];
    const int tid = threadIdx.x;
    const int seq0 = blockIdx.x * NSEQ;

    for (int i = tid; i < NSEQ * HDIM; i += 256) {
        int s = i / HDIM, k = i - s * HDIM;
        hs[k][s] = h0[(size_t)(seq0 + s) * HDIM + k];
    }
    __syncthreads();

    const int j = tid;
    const h16* wr = W16 + (size_t)j * HDIM;
    const h16* wz = W16 + (size_t)(HDIM + j) * HDIM;
    const h16* wn_ = W16 + (size_t)(2 * HDIM + j) * HDIM;
    const float br = bhh[j], bz = bhh[HDIM + j], bn = bhh[2 * HDIM + j];

    for (int t = 1; t < T; t++) {
        float ar[NSEQ], az[NSEQ], an[NSEQ];
#pragma unroll
        for (int s = 0; s < NSEQ; s++) { ar[s] = 0.f; az[s] = 0.f; an[s] = 0.f; }

#pragma unroll 4
        for (int k = 0; k < HDIM; k += 8) {
            uint4 vr = *reinterpret_cast<const uint4*>(wr + k);
            uint4 vz = *reinterpret_cast<const uint4*>(wz + k);
            uint4 vn = *reinterpret_cast<const uint4*>(wn_ + k);
            const h16* pr = reinterpret_cast<const h16*>(&vr);
            const h16* pz = reinterpret_cast<const h16*>(&vz);
            const h16* pn = reinterpret_cast<const h16*>(&vn);
#pragma unroll
            for (int u = 0; u < 8; u++) {
                float fr = __half2float(pr[u]);
                float fz = __half2float(pz[u]);
                float fn = __half2float(pn[u]);
#pragma unroll
                for (int s = 0; s < NSEQ; s++) {
                    float hv = hs[k + u][s];
                    ar[s] = fmaf(fr, hv, ar[s]);
                    az[s] = fmaf(fz, hv, az[s]);
                    an[s] = fmaf(fn, hv, an[s]);
                }
            }
        }
        __syncthreads();

        float hnew[NSEQ];
#pragma unroll
        for (int s = 0; s < NSEQ; s++) {
            const float* gxp = gx + ((size_t)(seq0 + s) * T + t) * GDIM;
            float r = sigmoid_f(gxp[j] + ar[s] + br);
            float z = sigmoid_f(gxp[HDIM + j] + az[s] + bz);
            float n = tanhf(gxp[2 * HDIM + j] + r * (an[s] + bn));
            hnew[s] = (1.f - z) * n + z * hs[j][s];
        }
#pragma unroll
        for (int s = 0; s < NSEQ; s++) hs[j][s] = hnew[s];
        __syncthreads();
    }

    for (int i = tid; i < NSEQ * HDIM; i += 256) {
        int s = i / HDIM, k = i - s * HDIM;
        hfinal[(size_t)(seq0 + s) * HDIM + k] = hs[k][s];
    }
}

// ---------------- fp32 SGEMM (review gx) ----------------
#define BM 128
#define BN 128
#define BK 8
__global__ __launch_bounds__(256, 2)
void sgemm_f32x2(const float* __restrict__ A, const float* __restrict__ W,
                 const float* __restrict__ bias, float* __restrict__ C,
                 int M, int K, int N)
{
    __shared__ float As[2][BK][BM];
    __shared__ float Bs[2][BK][BN];
    const int tid = threadIdx.x;
    const int m0 = blockIdx.y * BM;
    const int n0 = blockIdx.x * BN;
    const int a_m = tid & 127, a_kq = tid >> 7;
    const int b_n = tid >> 1,  b_kq = tid & 1;
    const bool a_valid = (m0 + a_m) < M;
    const float* Arow = A + (size_t)(a_valid ? (m0 + a_m) : 0) * K;
    const float* Brow = W + (size_t)(n0 + b_n) * K;
    const int tx = tid & 15, ty = tid >> 4;

    ull acc2[8][4];
#pragma unroll
    for (int i = 0; i < 8; i++)
#pragma unroll
        for (int j = 0; j < 4; j++) acc2[i][j] = 0ull;

    float4 av = make_float4(0.f, 0.f, 0.f, 0.f);
    if (a_valid) av = *reinterpret_cast<const float4*>(Arow + a_kq * 4);
    float4 bv = *reinterpret_cast<const float4*>(Brow + b_kq * 4);
    As[0][a_kq * 4 + 0][a_m] = av.x;  As[0][a_kq * 4 + 1][a_m] = av.y;
    As[0][a_kq * 4 + 2][a_m] = av.z;  As[0][a_kq * 4 + 3][a_m] = av.w;
    Bs[0][b_kq * 4 + 0][b_n] = bv.x;  Bs[0][b_kq * 4 + 1][b_n] = bv.y;
    Bs[0][b_kq * 4 + 2][b_n] = bv.z;  Bs[0][b_kq * 4 + 3][b_n] = bv.w;
    __syncthreads();

    int buf = 0;
    for (int kk = 0; kk < K; kk += BK) {
        const bool has_next = (kk + BK) < K;
        if (has_next) {
            if (a_valid) av = *reinterpret_cast<const float4*>(Arow + kk + BK + a_kq * 4);
            bv = *reinterpret_cast<const float4*>(Brow + kk + BK + b_kq * 4);
        }
#pragma unroll
        for (int k = 0; k < BK; k++) {
            float4 a0 = *reinterpret_cast<const float4*>(&As[buf][k][ty * 8]);
            float4 a1 = *reinterpret_cast<const float4*>(&As[buf][k][ty * 8 + 4]);
            ulonglong2 bq0 = *reinterpret_cast<const ulonglong2*>(&Bs[buf][k][tx * 8]);
            ulonglong2 bq1 = *reinterpret_cast<const ulonglong2*>(&Bs[buf][k][tx * 8 + 4]);
            ull bp[4] = {bq0.x, bq0.y, bq1.x, bq1.y};
            float a[8] = {a0.x, a0.y, a0.z, a0.w, a1.x, a1.y, a1.z, a1.w};
#pragma unroll
            for (int i = 0; i < 8; i++) {
                ull ad = dup2(a[i]);
#pragma unroll
                for (int j = 0; j < 4; j++) ffma2(acc2[i][j], ad, bp[j]);
            }
        }
        if (has_next) {
            int nb = buf ^ 1;
            As[nb][a_kq * 4 + 0][a_m] = av.x;  As[nb][a_kq * 4 + 1][a_m] = av.y;
            As[nb][a_kq * 4 + 2][a_m] = av.z;  As[nb][a_kq * 4 + 3][a_m] = av.w;
            Bs[nb][b_kq * 4 + 0][b_n] = bv.x;  Bs[nb][b_kq * 4 + 1][b_n] = bv.y;
            Bs[nb][b_kq * 4 + 2][b_n] = bv.z;  Bs[nb][b_kq * 4 + 3][b_n] = bv.w;
            __syncthreads();
            buf = nb;
        }
    }
#pragma unroll
    for (int i = 0; i < 8; i++) {
        int row = m0 + ty * 8 + i;
        if (row >= M) continue;
#pragma unroll
        for (int j = 0; j < 4; j++) {
            int col = n0 + tx * 8 + j * 2;
            float2 p = unpack2(acc2[i][j]);
            float2 bb = *reinterpret_cast<const float2*>(bias + col);
            float2 o; o.x = p.x + bb.x; o.y = p.y + bb.y;
            *reinterpret_cast<float2*>(C + (size_t)row * N + col) = o;
        }
    }
}

// ---------------- MLP ----------------
__global__ __launch_bounds__(128)
void mlp_kernel(const float* __restrict__ X,
                const float* __restrict__ W1, const float* __restrict__ b1,
                const float* __restrict__ W2, const float* __restrict__ b2,
                float* __restrict__ out)
{
    const int row = blockIdx.x;
    const int i = threadIdx.x;
    __shared__ float xs[HDIM];
    __shared__ float red[4];
    xs[i]       = X[(size_t)row * HDIM + i];
    xs[i + 128] = X[(size_t)row * HDIM + i + 128];
    __syncthreads();
    const float* w = W1 + (size_t)i * HDIM;
    float acc = b1[i];
#pragma unroll 8
    for (int k = 0; k < HDIM; k += 4) {
        float4 wv = *reinterpret_cast<const float4*>(w + k);
        acc = fmaf(wv.x, xs[k], acc);
        acc = fmaf(wv.y, xs[k + 1], acc);
        acc = fmaf(wv.z, xs[k + 2], acc);
        acc = fmaf(wv.w, xs[k + 3], acc);
    }
    const float scale = 1.0507009873554805f;
    const float alpha = 1.6732632423543772f;
    float s = scale * (acc > 0.f ? acc : alpha * (expf(acc) - 1.f));
    float v = s * W2[i];
#pragma unroll
    for (int off = 16; off > 0; off >>= 1)
        v += __shfl_down_sync(0xffffffffu, v, off);
    if ((i & 31) == 0) red[i >> 5] = v;
    __syncthreads();
    if (i == 0) out[row] = red[0] + red[1] + red[2] + red[3] + b2[0];
}

// ---------------- host orchestration ----------------
extern "C" void kernel_launch(void* const* d_in, const int* in_sizes, int n_in,
                              void* d_out, int out_size)
{
    (void)in_sizes; (void)n_in; (void)out_size;

    const int*   idx    = (const int*)  d_in[0];
    const float* emb    = (const float*)d_in[1];
    const float* w_Wih  = (const float*)d_in[2];
    const float* w_Whh  = (const float*)d_in[3];
    const float* w_bih  = (const float*)d_in[4];
    const float* w_bhh  = (const float*)d_in[5];
    const float* s_Wih  = (const float*)d_in[6];
    const float* s_Whh  = (const float*)d_in[7];
    const float* s_bih  = (const float*)d_in[8];
    const float* s_bhh  = (const float*)d_in[9];
    const float* r_Wih  = (const float*)d_in[10];
    const float* r_Whh  = (const float*)d_in[11];
    const float* r_bih  = (const float*)d_in[12];
    const float* r_bhh  = (const float*)d_in[13];
    const float* rfc_W1 = (const float*)d_in[14];
    const float* rfc_b1 = (const float*)d_in[15];
    const float* rfc_W2 = (const float*)d_in[16];
    const float* rfc_b2 = (const float*)d_in[17];
    const float* pfc_W1 = (const float*)d_in[18];
    const float* pfc_b1 = (const float*)d_in[19];
    const float* pfc_W2 = (const float*)d_in[20];
    const float* pfc_b2 = (const float*)d_in[21];
    float* out = (float*)d_out;

    float *GXs, *GXr, *HsA, *HsB, *HrA, *HrB;
    h16 *GXw, *Xh, *WihH, *WhhH, *WsH, *WshhH, *WrhhH, *SHiA, *SHiB;
    cudaGetSymbolAddress((void**)&GXw, g_GXw);
    cudaGetSymbolAddress((void**)&GXs, g_GXs);
    cudaGetSymbolAddress((void**)&GXr, g_GXr);
    cudaGetSymbolAddress((void**)&HsA, g_HsA);
    cudaGetSymbolAddress((void**)&HsB, g_HsB);
    cudaGetSymbolAddress((void**)&HrA, g_HrA);
    cudaGetSymbolAddress((void**)&HrB, g_HrB);
    cudaGetSymbolAddress((void**)&Xh, g_Xh);
    cudaGetSymbolAddress((void**)&WihH, g_WihH);
    cudaGetSymbolAddress((void**)&WhhH, g_WhhH);
    cudaGetSymbolAddress((void**)&WsH, g_WsH);
    cudaGetSymbolAddress((void**)&WshhH, g_WshhH);
    cudaGetSymbolAddress((void**)&WrhhH, g_WrhhH);
    cudaGetSymbolAddress((void**)&SHiA, g_SHiA);
    cudaGetSymbolAddress((void**)&SHiB, g_SHiB);

    const int SMEM_GEMM = 65536;       // fp32 scratch dominates (128x128x4)
    const int SMEM_GRU  = 49152;       // max(2*GBUF2=40960, 64x192x4=49152)
    cudaFuncSetAttribute(gemm_wmma2<h16>, cudaFuncAttributeMaxDynamicSharedMemorySize, SMEM_GEMM);
    cudaFuncSetAttribute(gemm_wmma2<float>, cudaFuncAttributeMaxDynamicSharedMemorySize, SMEM_GEMM);
    cudaFuncSetAttribute(gru_word_persistent, cudaFuncAttributeMaxDynamicSharedMemorySize, SMEM_GRU);

    // ---- prep ----
    split_w_single<<<(GDIM * KPAD + 255) / 256, 256>>>(w_Wih, WihH, GDIM, EDIM, KPAD);
    {
        int n4 = GDIM * HDIM / 4;
        split_w_quad<<<(4 * n4 + 255) / 256, 256>>>(w_Whh, WhhH, s_Wih, WsH,
                                                    s_Whh, WshhH, r_Whh, WrhhH, n4);
    }
    gather_h16_kernel<<<(int)(((size_t)MW * KP4 + 255) / 256), 256>>>(idx, emb, Xh);

    // ---- word level: gx (fp16 out) ----
    gemm_wmma2<h16><<<dim3(GDIM / 128, MW / 128), 256, SMEM_GEMM>>>(Xh, WihH,
                                                                    w_bih, GXw, KPAD, GDIM);

    // t=0, then persistent cooperative loop t=1..31 (fp16 h)
    gru_init_h16<<<(NW * HDIM + 255) / 256, 256>>>(GXw, w_bhh, SHiA, NW, TWSTEPS);
    {
        cudaLaunchConfig_t cfg = {};
        cfg.gridDim = dim3(HDIM / 64, NW / 64);     // (4, 64) = 256 CTAs
        cfg.blockDim = dim3(256, 1, 1);
        cfg.dynamicSmemBytes = SMEM_GRU;
        cudaLaunchAttribute attr;
        attr.id = cudaLaunchAttributeCooperative;
        attr.val.cooperative = 1;
        cfg.attrs = &attr;
        cfg.numAttrs = 1;
        cudaLaunchKernelEx(&cfg, gru_word_persistent,
                           SHiA, SHiB, (const h16*)WhhH,
                           (const float*)w_bhh, (const h16*)GXw);
    }
    h16* sent_hi = SHiB;   // 31 iterations -> B buffers

    // ---- sentence level ----
    gemm_wmma2<float><<<dim3(GDIM / 128, (NS * TSSTEPS) / 128), 256, SMEM_GEMM>>>(
        sent_hi, WsH, s_bih, GXs, HDIM, GDIM);

    gru_init_plain<<<(NS * HDIM + 255) / 256, 256>>>(GXs, s_bhh, HsA, NS, TSSTEPS);
    gru_tail_fused<4><<<NS / 4, 256>>>(HsA, WshhH, s_bhh, GXs, TSSTEPS, HsB);
    const float* p_batch = HsB;

    // r_stars -> out[16 .. 272)
    mlp_kernel<<<NS, 128>>>(p_batch, rfc_W1, rfc_b1, rfc_W2, rfc_b2, out + NR);

    // ---- review level ----
    {
        dim3 grid(GDIM / BN, (NR * TRSTEPS + BM - 1) / BM);
        sgemm_f32x2<<<grid, 256>>>(p_batch, r_Wih, r_bih, GXr, NR * TRSTEPS, HDIM, GDIM);
    }
    gru_init_plain<<<(NR * HDIM + 255) / 256, 256>>>(GXr, r_bhh, HrA, NR, TRSTEPS);
    gru_tail_fused<1><<<NR, 256>>>(HrA, WrhhH, r_bhh, GXr, TRSTEPS, HrB);

    // b_stars -> out[0 .. 16)
    mlp_kernel<<<NR, 128>>>(HrB, pfc_W1, pfc_b1, pfc_W2, pfc_b2, out);
}

// round 13
// speedup vs baseline: 4.2407x; 1.0185x over previous
#include <cuda_runtime.h>
#include <cuda_fp16.h>
#include <mma.h>
#include <cooperative_groups.h>
#include <math.h>
#include <stdint.h>

using namespace nvcuda;
namespace cg = cooperative_groups;

// ---------------- problem dims ----------------
#define HDIM 256
#define GDIM 768
#define EDIM 200
#define NW 4096
#define TWSTEPS 32
#define NS 256
#define TSSTEPS 16
#define NR 16
#define TRSTEPS 16
#define MW (NW * TWSTEPS)
#define KPAD 224
#define KP4 (KPAD / 4)

typedef unsigned long long ull;
typedef __half h16;

// ---------------- scratch ----------------
__device__ __align__(16) h16 g_GXw[(size_t)MW * GDIM];   // fp16 word input gates
__device__ float g_GXs[(size_t)NS * TSSTEPS * GDIM];
__device__ float g_GXr[(size_t)NR * TRSTEPS * GDIM];
__device__ float g_HsA[NS * HDIM], g_HsB[NS * HDIM];
__device__ float g_HrA[NR * HDIM], g_HrB[NR * HDIM];
__device__ __align__(16) h16 g_Xh[(size_t)MW * KPAD];
__device__ __align__(16) h16 g_WihH[GDIM * KPAD];
__device__ __align__(16) h16 g_WhhH[GDIM * HDIM];
__device__ __align__(16) h16 g_WsH [GDIM * HDIM];
__device__ __align__(16) h16 g_WshhH[GDIM * HDIM];
__device__ __align__(16) h16 g_WrhhH[GDIM * HDIM];
__device__ __align__(16) h16 g_SHiA[NW * HDIM], g_SHiB[NW * HDIM];

// ---------------- helpers ----------------
__device__ __forceinline__ float sigmoid_f(float x) { return 1.f / (1.f + expf(-x)); }
__device__ __forceinline__ ull pack2(float lo, float hi) {
    ull r; asm("mov.b64 %0, {%1, %2};" : "=l"(r) : "f"(lo), "f"(hi)); return r;
}
__device__ __forceinline__ ull dup2(float v) { return pack2(v, v); }
__device__ __forceinline__ void ffma2(ull& d, ull a, ull b) {
    asm("fma.rn.f32x2 %0, %1, %2, %3;" : "=l"(d) : "l"(a), "l"(b), "l"(d));
}
__device__ __forceinline__ float2 unpack2(ull v) {
    float2 f; asm("mov.b64 {%0, %1}, %2;" : "=f"(f.x), "=f"(f.y) : "l"(v)); return f;
}
__device__ __forceinline__ void cp16(uint32_t s, const void* g) {
    asm volatile("cp.async.cg.shared.global [%0], [%1], 16;" :: "r"(s), "l"(g));
}
#define CP_COMMIT() asm volatile("cp.async.commit_group;" ::: "memory")
#define CP_WAIT(n)  asm volatile("cp.async.wait_group %0;" :: "n"(n) : "memory")

__device__ __forceinline__ void ld_h4(float* o, const h16* p) {
    ull v = *reinterpret_cast<const ull*>(p);
    const h16* q = reinterpret_cast<const h16*>(&v);
    o[0] = __half2float(q[0]); o[1] = __half2float(q[1]);
    o[2] = __half2float(q[2]); o[3] = __half2float(q[3]);
}

// ---------------- prep kernels ----------------
__global__ void split_w_single(const float* __restrict__ src, h16* __restrict__ dst,
                               int rows, int cs, int cd)
{
    int i = blockIdx.x * blockDim.x + threadIdx.x;
    if (i >= rows * cd) return;
    int r = i / cd, c = i - r * cd;
    float v = (c < cs) ? src[(size_t)r * cs + c] : 0.f;
    dst[i] = __float2half_rn(v);
}

__global__ void split_w_quad(const float* s0, h16* d0, const float* s1, h16* d1,
                             const float* s2, h16* d2, const float* s3, h16* d3,
                             int n4)
{
    int i = blockIdx.x * blockDim.x + threadIdx.x;
    int mat = i / n4;
    int off = (i - mat * n4) * 4;
    if (mat >= 4) return;
    const float* s = (mat == 0) ? s0 : (mat == 1) ? s1 : (mat == 2) ? s2 : s3;
    h16* d = (mat == 0) ? d0 : (mat == 1) ? d1 : (mat == 2) ? d2 : d3;
    float4 v = *reinterpret_cast<const float4*>(s + off);
    h16 hb[4];
    hb[0] = __float2half_rn(v.x); hb[1] = __float2half_rn(v.y);
    hb[2] = __float2half_rn(v.z); hb[3] = __float2half_rn(v.w);
    *reinterpret_cast<ull*>(d + off) = *reinterpret_cast<ull*>(hb);
}

__global__ void gather_h16_kernel(const int* __restrict__ idx, const float* __restrict__ emb,
                                  h16* __restrict__ hi)
{
    size_t id = (size_t)blockIdx.x * blockDim.x + threadIdx.x;
    if (id >= (size_t)MW * KP4) return;
    int row = (int)(id / KP4);
    int c4 = (int)(id - (size_t)row * KP4) * 4;
    float4 v = make_float4(0.f, 0.f, 0.f, 0.f);
    if (c4 < EDIM)
        v = *reinterpret_cast<const float4*>(emb + (size_t)idx[row] * EDIM + c4);
    h16 hb[4];
    hb[0] = __float2half_rn(v.x); hb[1] = __float2half_rn(v.y);
    hb[2] = __float2half_rn(v.z); hb[3] = __float2half_rn(v.w);
    *reinterpret_cast<ull*>(hi + (size_t)row * KPAD + c4) = *reinterpret_cast<ull*>(hb);
}

// ---------------- wmma fp16 GEMM: C = A@W^T + bias (OutT = float or h16) ----
#define LDT2 40
#define TBY (128 * LDT2 * 2)         // 10240B per matrix tile
#define GEMM_BUF (2 * TBY)

template <typename OutT>
__global__ __launch_bounds__(256, 2)
void gemm_wmma2(const h16* __restrict__ Ahp, const h16* __restrict__ Whp,
                const float* __restrict__ bias, OutT* __restrict__ C,
                int K, int N)
{
    extern __shared__ __align__(128) char sm[];
    const uint32_t sbase = (uint32_t)__cvta_generic_to_shared(sm);
    float* scratch = reinterpret_cast<float*>(sm);

    const int tid = threadIdx.x;
    const int wid = tid >> 5;
    const int m0 = blockIdx.y * 128, n0 = blockIdx.x * 128;
    const int wm = wid & 3, wn = wid >> 2;

    const int lr = tid >> 1;
    const int lq = (tid & 1) * 16;

    const h16* gA = Ahp + (size_t)(m0 + lr) * K + lq;
    const h16* gB = Whp + (size_t)(n0 + lr) * K + lq;
    const uint32_t srow = lr * LDT2 * 2 + lq * 2;

    const int ntile = K / 32;

    wmma::fragment<wmma::accumulator, 16, 16, 16, float> cf[2][4];
#pragma unroll
    for (int i = 0; i < 2; i++)
#pragma unroll
        for (int j = 0; j < 4; j++) wmma::fill_fragment(cf[i][j], 0.0f);

    auto issue = [&](int it, int b) {
        const int kk = it * 32;
        uint32_t base = sbase + b * GEMM_BUF;
        cp16(base + srow,            gA + kk);
        cp16(base + srow + 16,       gA + kk + 8);
        cp16(base + TBY + srow,      gB + kk);
        cp16(base + TBY + srow + 16, gB + kk + 8);
    };

    issue(0, 0); CP_COMMIT();

    for (int it = 0; it < ntile; it++) {
        const int b = it & 1;
        if (it + 1 < ntile) { issue(it + 1, b ^ 1); CP_COMMIT(); CP_WAIT(1); }
        else                { CP_WAIT(0); }
        __syncthreads();

        const h16* tA = reinterpret_cast<const h16*>(sm + b * GEMM_BUF);
        const h16* tB = tA + 128 * LDT2;

#pragma unroll
        for (int ks = 0; ks < 32; ks += 16) {
            wmma::fragment<wmma::matrix_a, 16, 16, 16, h16, wmma::row_major> ah[2];
            wmma::fragment<wmma::matrix_b, 16, 16, 16, h16, wmma::col_major> bh[4];
#pragma unroll
            for (int i = 0; i < 2; i++)
                wmma::load_matrix_sync(ah[i], tA + (wm * 32 + i * 16) * LDT2 + ks, LDT2);
#pragma unroll
            for (int j = 0; j < 4; j++)
                wmma::load_matrix_sync(bh[j], tB + (wn * 64 + j * 16) * LDT2 + ks, LDT2);
#pragma unroll
            for (int i = 0; i < 2; i++)
#pragma unroll
                for (int j = 0; j < 4; j++)
                    wmma::mma_sync(cf[i][j], ah[i], bh[j], cf[i][j]);
        }
        __syncthreads();
    }

#pragma unroll
    for (int i = 0; i < 2; i++)
#pragma unroll
        for (int j = 0; j < 4; j++)
            wmma::store_matrix_sync(&scratch[(wm * 32 + i * 16) * 128 + wn * 64 + j * 16],
                                    cf[i][j], 128, wmma::mem_row_major);
    __syncthreads();

#pragma unroll
    for (int itx = 0; itx < 16; itx++) {
        int idx4 = tid + itx * 256;
        int r = idx4 >> 5;
        int c4 = (idx4 & 31) * 4;
        float4 v = *reinterpret_cast<const float4*>(&scratch[r * 128 + c4]);
        float4 b = *reinterpret_cast<const float4*>(&bias[n0 + c4]);
        v.x += b.x; v.y += b.y; v.z += b.z; v.w += b.w;
        if constexpr (sizeof(OutT) == 4) {
            *reinterpret_cast<float4*>(&C[(size_t)(m0 + r) * N + n0 + c4]) = v;
        } else {
            h16 hb[4];
            hb[0] = __float2half_rn(v.x); hb[1] = __float2half_rn(v.y);
            hb[2] = __float2half_rn(v.z); hb[3] = __float2half_rn(v.w);
            *reinterpret_cast<ull*>(&C[(size_t)(m0 + r) * N + n0 + c4]) =
                *reinterpret_cast<ull*>(hb);
        }
    }
}

// ---------------- persistent cooperative word-recurrent loop -----------------
// CTA = 128 rows x 32 h-cols (96 gate rows). W tile smem-resident (loaded once).
// grid (8, 32) = 256 CTAs, occ 2.
#define WROWS 96
#define WLD 264                        // halfs; 528B stride, 33 mod 8 = 1 -> conflict-free
#define WBYTES (WROWS * WLD * 2)       // 50688
#define ABUF (128 * LDT2 * 2)          // 10240 per A buffer
#define PSMEM (WBYTES + 24576)         // + max(2*ABUF, 64x96 fp32 scratch) = 75264

__global__ __launch_bounds__(256, 2)
void gru_word_persistent(h16* __restrict__ sA, h16* __restrict__ sB,
                         const h16* __restrict__ Whp,
                         const float* __restrict__ bhh, const h16* __restrict__ gx)
{
    extern __shared__ __align__(128) char sm[];
    const uint32_t sbase = (uint32_t)__cvta_generic_to_shared(sm);
    const h16* Wsm = reinterpret_cast<const h16*>(sm);
    float* scratch = reinterpret_cast<float*>(sm + WBYTES);   // 64x96 fp32 (24KB)

    cg::grid_group grid = cg::this_grid();

    const int tid = threadIdx.x;
    const int wid = tid >> 5;
    const int n0 = blockIdx.x * 32;      // 32 h-cols
    const int m0 = blockIdx.y * 128;     // 128 rows
    const int wm = wid & 3;              // 32-row tile
    const int wn = wid >> 2;             // 48-col tile (of 96 gate cols)

    // ---- prologue: load W tile (96 gate-rows x 256 K) once ----
    for (int task = tid; task < WROWS * 32; task += 256) {
        int rt = task >> 5;              // gate-row 0..95
        int q = task & 31;               // 16B chunk (8 halfs)
        int gate = rt >> 5, col = rt & 31;
        size_t srcoff = (size_t)(gate * HDIM + n0 + col) * HDIM + q * 8;
        cp16(sbase + rt * (WLD * 2) + q * 16, Whp + srcoff);
    }
    CP_COMMIT(); CP_WAIT(0);
    __syncthreads();

    const int lr = tid >> 1;             // 0..127
    const int lq = (tid & 1) * 16;       // half offset 0/16
    const uint32_t arow = lr * (LDT2 * 2) + lq * 2;

    for (int t = 1; t < TWSTEPS; t++) {
        const int cur = (t - 1) & 1;
        const h16* Hhi  = cur ? sB : sA;
        h16*       Hout = cur ? sA : sB;

        const h16* gAh = Hhi + (size_t)(m0 + lr) * HDIM + lq;

        auto issue = [&](int it, int b) {
            const int kk = it * 32;
            uint32_t base = sbase + WBYTES + b * ABUF;
            cp16(base + arow,      gAh + kk);
            cp16(base + arow + 16, gAh + kk + 8);
        };

        wmma::fragment<wmma::accumulator, 16, 16, 16, float> cf[2][3];
#pragma unroll
        for (int i = 0; i < 2; i++)
#pragma unroll
            for (int j = 0; j < 3; j++) wmma::fill_fragment(cf[i][j], 0.0f);

        issue(0, 0); CP_COMMIT();

        const int ntile = HDIM / 32;     // 8
        for (int it = 0; it < ntile; it++) {
            const int b = it & 1;
            if (it + 1 < ntile) { issue(it + 1, b ^ 1); CP_COMMIT(); CP_WAIT(1); }
            else                { CP_WAIT(0); }
            __syncthreads();

            const h16* tA = reinterpret_cast<const h16*>(sm + WBYTES + b * ABUF);
            const int kk = it * 32;

#pragma unroll
            for (int ks = 0; ks < 32; ks += 16) {
                wmma::fragment<wmma::matrix_a, 16, 16, 16, h16, wmma::row_major> ah0, ah1;
                wmma::load_matrix_sync(ah0, tA + (wm * 32) * LDT2 + ks, LDT2);
                wmma::load_matrix_sync(ah1, tA + (wm * 32 + 16) * LDT2 + ks, LDT2);
#pragma unroll
                for (int j = 0; j < 3; j++) {
                    wmma::fragment<wmma::matrix_b, 16, 16, 16, h16, wmma::col_major> bh;
                    wmma::load_matrix_sync(bh, Wsm + (wn * 48 + j * 16) * WLD + kk + ks, WLD);
                    wmma::mma_sync(cf[0][j], ah0, bh, cf[0][j]);
                    wmma::mma_sync(cf[1][j], ah1, bh, cf[1][j]);
                }
            }
            __syncthreads();
        }

        // ---- epilogue in 2 row-passes (scratch 64x96 aliases A buffers) ----
#pragma unroll
        for (int p = 0; p < 2; p++) {
            __syncthreads();
            if ((wm >> 1) == p) {
#pragma unroll
                for (int i = 0; i < 2; i++)
#pragma unroll
                    for (int j = 0; j < 3; j++)
                        wmma::store_matrix_sync(
                            &scratch[((wm & 1) * 32 + i * 16) * 96 + wn * 48 + j * 16],
                            cf[i][j], 96, wmma::mem_row_major);
            }
            __syncthreads();
#pragma unroll
            for (int itx = 0; itx < 2; itx++) {
                int task = tid + itx * 256;
                int r = task >> 3;              // 0..63
                int c4 = (task & 7) * 4;        // 0..28
                const int row = m0 + p * 64 + r;
                const int j = n0 + c4;
                const float* srow2 = &scratch[r * 96];
                float gr[4], gz[4], gn[4];
                *reinterpret_cast<float4*>(gr) = *reinterpret_cast<const float4*>(srow2 + c4);
                *reinterpret_cast<float4*>(gz) = *reinterpret_cast<const float4*>(srow2 + 32 + c4);
                *reinterpret_cast<float4*>(gn) = *reinterpret_cast<const float4*>(srow2 + 64 + c4);
                float br[4], bz[4], bn[4], xr[4], xz[4], xn[4], hh[4];
                *reinterpret_cast<float4*>(br) = *reinterpret_cast<const float4*>(bhh + j);
                *reinterpret_cast<float4*>(bz) = *reinterpret_cast<const float4*>(bhh + HDIM + j);
                *reinterpret_cast<float4*>(bn) = *reinterpret_cast<const float4*>(bhh + 2 * HDIM + j);
                const h16* gxp = gx + ((size_t)row * TWSTEPS + t) * GDIM;
                ld_h4(xr, gxp + j);
                ld_h4(xz, gxp + HDIM + j);
                ld_h4(xn, gxp + 2 * HDIM + j);
                ld_h4(hh, Hhi + (size_t)row * HDIM + j);
                h16 hb[4];
#pragma unroll
                for (int u = 0; u < 4; u++) {
                    float rr = sigmoid_f(xr[u] + gr[u] + br[u]);
                    float zz = sigmoid_f(xz[u] + gz[u] + bz[u]);
                    float nv = tanhf(xn[u] + rr * (gn[u] + bn[u]));
                    float h = (1.f - zz) * nv + zz * hh[u];
                    hb[u] = __float2half_rn(h);
                }
                *reinterpret_cast<ull*>(Hout + (size_t)row * HDIM + j) =
                    *reinterpret_cast<ull*>(hb);
            }
        }
        __syncthreads();
        grid.sync();
    }
}

// ---------------- t=0 GRU steps ----------------
__global__ void gru_init_h16(const h16* __restrict__ gx, const float* __restrict__ bhh,
                             h16* __restrict__ hi, int Mseq, int T)
{
    int i = blockIdx.x * blockDim.x + threadIdx.x;
    if (i >= Mseq * HDIM) return;
    int seq = i >> 8, j = i & 255;
    const h16* g = gx + (size_t)seq * T * GDIM;
    float xr = __half2float(g[j]);
    float xz = __half2float(g[j + HDIM]);
    float xn = __half2float(g[j + 2 * HDIM]);
    float r = sigmoid_f(xr + bhh[j]);
    float z = sigmoid_f(xz + bhh[j + HDIM]);
    float n = tanhf(xn + r * bhh[j + 2 * HDIM]);
    hi[i] = __float2half_rn((1.f - z) * n);
}

__global__ void gru_init_plain(const float* __restrict__ gx, const float* __restrict__ bhh,
                               float* __restrict__ hout, int Mseq, int T)
{
    int i = blockIdx.x * blockDim.x + threadIdx.x;
    if (i >= Mseq * HDIM) return;
    int seq = i >> 8, j = i & 255;
    const float* g = gx + (size_t)seq * T * GDIM;
    float r = sigmoid_f(g[j] + bhh[j]);
    float z = sigmoid_f(g[j + HDIM] + bhh[j + HDIM]);
    float n = tanhf(g[j + 2 * HDIM] + r * bhh[j + 2 * HDIM]);
    hout[i] = (1.f - z) * n;
}

// ---------------- fused multi-step GRU tail ----------------------------------
template <int NSEQ>
__global__ __launch_bounds__(256)
void gru_tail_fused(const float* __restrict__ h0, const h16* __restrict__ W16,
                    const float* __restrict__ bhh, const float* __restrict__ gx,
                    int T, float* __restrict__ hfinal)
{
    __shared__ float hs[HDIM][NSEQ];
    const int tid = threadIdx.x;
    const int seq0 = blockIdx.x * NSEQ;

    for (int i = tid; i < NSEQ * HDIM; i += 256) {
        int s = i / HDIM, k = i - s * HDIM;
        hs[k][s] = h0[(size_t)(seq0 + s) * HDIM + k];
    }
    __syncthreads();

    const int j = tid;
    const h16* wr = W16 + (size_t)j * HDIM;
    const h16* wz = W16 + (size_t)(HDIM + j) * HDIM;
    const h16* wn_ = W16 + (size_t)(2 * HDIM + j) * HDIM;
    const float br = bhh[j], bz = bhh[HDIM + j], bn = bhh[2 * HDIM + j];

    for (int t = 1; t < T; t++) {
        float ar[NSEQ], az[NSEQ], an[NSEQ];
#pragma unroll
        for (int s = 0; s < NSEQ; s++) { ar[s] = 0.f; az[s] = 0.f; an[s] = 0.f; }

#pragma unroll 4
        for (int k = 0; k < HDIM; k += 8) {
            uint4 vr = *reinterpret_cast<const uint4*>(wr + k);
            uint4 vz = *reinterpret_cast<const uint4*>(wz + k);
            uint4 vn = *reinterpret_cast<const uint4*>(wn_ + k);
            const h16* pr = reinterpret_cast<const h16*>(&vr);
            const h16* pz = reinterpret_cast<const h16*>(&vz);
            const h16* pn = reinterpret_cast<const h16*>(&vn);
#pragma unroll
            for (int u = 0; u < 8; u++) {
                float fr = __half2float(pr[u]);
                float fz = __half2float(pz[u]);
                float fn = __half2float(pn[u]);
#pragma unroll
                for (int s = 0; s < NSEQ; s++) {
                    float hv = hs[k + u][s];
                    ar[s] = fmaf(fr, hv, ar[s]);
                    az[s] = fmaf(fz, hv, az[s]);
                    an[s] = fmaf(fn, hv, an[s]);
                }
            }
        }
        __syncthreads();

        float hnew[NSEQ];
#pragma unroll
        for (int s = 0; s < NSEQ; s++) {
            const float* gxp = gx + ((size_t)(seq0 + s) * T + t) * GDIM;
            float r = sigmoid_f(gxp[j] + ar[s] + br);
            float z = sigmoid_f(gxp[HDIM + j] + az[s] + bz);
            float n = tanhf(gxp[2 * HDIM + j] + r * (an[s] + bn));
            hnew[s] = (1.f - z) * n + z * hs[j][s];
        }
#pragma unroll
        for (int s = 0; s < NSEQ; s++) hs[j][s] = hnew[s];
        __syncthreads();
    }

    for (int i = tid; i < NSEQ * HDIM; i += 256) {
        int s = i / HDIM, k = i - s * HDIM;
        hfinal[(size_t)(seq0 + s) * HDIM + k] = hs[k][s];
    }
}

// ---------------- fp32 SGEMM (review gx) ----------------
#define BM 128
#define BN 128
#define BK 8
__global__ __launch_bounds__(256, 2)
void sgemm_f32x2(const float* __restrict__ A, const float* __restrict__ W,
                 const float* __restrict__ bias, float* __restrict__ C,
                 int M, int K, int N)
{
    __shared__ float As[2][BK][BM];
    __shared__ float Bs[2][BK][BN];
    const int tid = threadIdx.x;
    const int m0 = blockIdx.y * BM;
    const int n0 = blockIdx.x * BN;
    const int a_m = tid & 127, a_kq = tid >> 7;
    const int b_n = tid >> 1,  b_kq = tid & 1;
    const bool a_valid = (m0 + a_m) < M;
    const float* Arow = A + (size_t)(a_valid ? (m0 + a_m) : 0) * K;
    const float* Brow = W + (size_t)(n0 + b_n) * K;
    const int tx = tid & 15, ty = tid >> 4;

    ull acc2[8][4];
#pragma unroll
    for (int i = 0; i < 8; i++)
#pragma unroll
        for (int j = 0; j < 4; j++) acc2[i][j] = 0ull;

    float4 av = make_float4(0.f, 0.f, 0.f, 0.f);
    if (a_valid) av = *reinterpret_cast<const float4*>(Arow + a_kq * 4);
    float4 bv = *reinterpret_cast<const float4*>(Brow + b_kq * 4);
    As[0][a_kq * 4 + 0][a_m] = av.x;  As[0][a_kq * 4 + 1][a_m] = av.y;
    As[0][a_kq * 4 + 2][a_m] = av.z;  As[0][a_kq * 4 + 3][a_m] = av.w;
    Bs[0][b_kq * 4 + 0][b_n] = bv.x;  Bs[0][b_kq * 4 + 1][b_n] = bv.y;
    Bs[0][b_kq * 4 + 2][b_n] = bv.z;  Bs[0][b_kq * 4 + 3][b_n] = bv.w;
    __syncthreads();

    int buf = 0;
    for (int kk = 0; kk < K; kk += BK) {
        const bool has_next = (kk + BK) < K;
        if (has_next) {
            if (a_valid) av = *reinterpret_cast<const float4*>(Arow + kk + BK + a_kq * 4);
            bv = *reinterpret_cast<const float4*>(Brow + kk + BK + b_kq * 4);
        }
#pragma unroll
        for (int k = 0; k < BK; k++) {
            float4 a0 = *reinterpret_cast<const float4*>(&As[buf][k][ty * 8]);
            float4 a1 = *reinterpret_cast<const float4*>(&As[buf][k][ty * 8 + 4]);
            ulonglong2 bq0 = *reinterpret_cast<const ulonglong2*>(&Bs[buf][k][tx * 8]);
            ulonglong2 bq1 = *reinterpret_cast<const ulonglong2*>(&Bs[buf][k][tx * 8 + 4]);
            ull bp[4] = {bq0.x, bq0.y, bq1.x, bq1.y};
            float a[8] = {a0.x, a0.y, a0.z, a0.w, a1.x, a1.y, a1.z, a1.w};
#pragma unroll
            for (int i = 0; i < 8; i++) {
                ull ad = dup2(a[i]);
#pragma unroll
                for (int j = 0; j < 4; j++) ffma2(acc2[i][j], ad, bp[j]);
            }
        }
        if (has_next) {
            int nb = buf ^ 1;
            As[nb][a_kq * 4 + 0][a_m] = av.x;  As[nb][a_kq * 4 + 1][a_m] = av.y;
            As[nb][a_kq * 4 + 2][a_m] = av.z;  As[nb][a_kq * 4 + 3][a_m] = av.w;
            Bs[nb][b_kq * 4 + 0][b_n] = bv.x;  Bs[nb][b_kq * 4 + 1][b_n] = bv.y;
            Bs[nb][b_kq * 4 + 2][b_n] = bv.z;  Bs[nb][b_kq * 4 + 3][b_n] = bv.w;
            __syncthreads();
            buf = nb;
        }
    }
#pragma unroll
    for (int i = 0; i < 8; i++) {
        int row = m0 + ty * 8 + i;
        if (row >= M) continue;
#pragma unroll
        for (int j = 0; j < 4; j++) {
            int col = n0 + tx * 8 + j * 2;
            float2 p = unpack2(acc2[i][j]);
            float2 bb = *reinterpret_cast<const float2*>(bias + col);
            float2 o; o.x = p.x + bb.x; o.y = p.y + bb.y;
            *reinterpret_cast<float2*>(C + (size_t)row * N + col) = o;
        }
    }
}

// ---------------- MLP ----------------
__global__ __launch_bounds__(128)
void mlp_kernel(const float* __restrict__ X,
                const float* __restrict__ W1, const float* __restrict__ b1,
                const float* __restrict__ W2, const float* __restrict__ b2,
                float* __restrict__ out)
{
    const int row = blockIdx.x;
    const int i = threadIdx.x;
    __shared__ float xs[HDIM];
    __shared__ float red[4];
    xs[i]       = X[(size_t)row * HDIM + i];
    xs[i + 128] = X[(size_t)row * HDIM + i + 128];
    __syncthreads();
    const float* w = W1 + (size_t)i * HDIM;
    float acc = b1[i];
#pragma unroll 8
    for (int k = 0; k < HDIM; k += 4) {
        float4 wv = *reinterpret_cast<const float4*>(w + k);
        acc = fmaf(wv.x, xs[k], acc);
        acc = fmaf(wv.y, xs[k + 1], acc);
        acc = fmaf(wv.z, xs[k + 2], acc);
        acc = fmaf(wv.w, xs[k + 3], acc);
    }
    const float scale = 1.0507009873554805f;
    const float alpha = 1.6732632423543772f;
    float s = scale * (acc > 0.f ? acc : alpha * (expf(acc) - 1.f));
    float v = s * W2[i];
#pragma unroll
    for (int off = 16; off > 0; off >>= 1)
        v += __shfl_down_sync(0xffffffffu, v, off);
    if ((i & 31) == 0) red[i >> 5] = v;
    __syncthreads();
    if (i == 0) out[row] = red[0] + red[1] + red[2] + red[3] + b2[0];
}

// ---------------- host orchestration ----------------
extern "C" void kernel_launch(void* const* d_in, const int* in_sizes, int n_in,
                              void* d_out, int out_size)
{
    (void)in_sizes; (void)n_in; (void)out_size;

    const int*   idx    = (const int*)  d_in[0];
    const float* emb    = (const float*)d_in[1];
    const float* w_Wih  = (const float*)d_in[2];
    const float* w_Whh  = (const float*)d_in[3];
    const float* w_bih  = (const float*)d_in[4];
    const float* w_bhh  = (const float*)d_in[5];
    const float* s_Wih  = (const float*)d_in[6];
    const float* s_Whh  = (const float*)d_in[7];
    const float* s_bih  = (const float*)d_in[8];
    const float* s_bhh  = (const float*)d_in[9];
    const float* r_Wih  = (const float*)d_in[10];
    const float* r_Whh  = (const float*)d_in[11];
    const float* r_bih  = (const float*)d_in[12];
    const float* r_bhh  = (const float*)d_in[13];
    const float* rfc_W1 = (const float*)d_in[14];
    const float* rfc_b1 = (const float*)d_in[15];
    const float* rfc_W2 = (const float*)d_in[16];
    const float* rfc_b2 = (const float*)d_in[17];
    const float* pfc_W1 = (const float*)d_in[18];
    const float* pfc_b1 = (const float*)d_in[19];
    const float* pfc_W2 = (const float*)d_in[20];
    const float* pfc_b2 = (const float*)d_in[21];
    float* out = (float*)d_out;

    float *GXs, *GXr, *HsA, *HsB, *HrA, *HrB;
    h16 *GXw, *Xh, *WihH, *WhhH, *WsH, *WshhH, *WrhhH, *SHiA, *SHiB;
    cudaGetSymbolAddress((void**)&GXw, g_GXw);
    cudaGetSymbolAddress((void**)&GXs, g_GXs);
    cudaGetSymbolAddress((void**)&GXr, g_GXr);
    cudaGetSymbolAddress((void**)&HsA, g_HsA);
    cudaGetSymbolAddress((void**)&HsB, g_HsB);
    cudaGetSymbolAddress((void**)&HrA, g_HrA);
    cudaGetSymbolAddress((void**)&HrB, g_HrB);
    cudaGetSymbolAddress((void**)&Xh, g_Xh);
    cudaGetSymbolAddress((void**)&WihH, g_WihH);
    cudaGetSymbolAddress((void**)&WhhH, g_WhhH);
    cudaGetSymbolAddress((void**)&WsH, g_WsH);
    cudaGetSymbolAddress((void**)&WshhH, g_WshhH);
    cudaGetSymbolAddress((void**)&WrhhH, g_WrhhH);
    cudaGetSymbolAddress((void**)&SHiA, g_SHiA);
    cudaGetSymbolAddress((void**)&SHiB, g_SHiB);

    const int SMEM_GEMM = 65536;
    cudaFuncSetAttribute(gemm_wmma2<h16>, cudaFuncAttributeMaxDynamicSharedMemorySize, SMEM_GEMM);
    cudaFuncSetAttribute(gemm_wmma2<float>, cudaFuncAttributeMaxDynamicSharedMemorySize, SMEM_GEMM);
    cudaFuncSetAttribute(gru_word_persistent, cudaFuncAttributeMaxDynamicSharedMemorySize, PSMEM);

    // ---- prep ----
    split_w_single<<<(GDIM * KPAD + 255) / 256, 256>>>(w_Wih, WihH, GDIM, EDIM, KPAD);
    {
        int n4 = GDIM * HDIM / 4;
        split_w_quad<<<(4 * n4 + 255) / 256, 256>>>(w_Whh, WhhH, s_Wih, WsH,
                                                    s_Whh, WshhH, r_Whh, WrhhH, n4);
    }
    gather_h16_kernel<<<(int)(((size_t)MW * KP4 + 255) / 256), 256>>>(idx, emb, Xh);

    // ---- word level: gx (fp16 out) ----
    gemm_wmma2<h16><<<dim3(GDIM / 128, MW / 128), 256, SMEM_GEMM>>>(Xh, WihH,
                                                                    w_bih, GXw, KPAD, GDIM);

    // t=0, then persistent cooperative loop t=1..31 (fp16 h, W smem-resident)
    gru_init_h16<<<(NW * HDIM + 255) / 256, 256>>>(GXw, w_bhh, SHiA, NW, TWSTEPS);
    {
        cudaLaunchConfig_t cfg = {};
        cfg.gridDim = dim3(HDIM / 32, NW / 128);    // (8, 32) = 256 CTAs
        cfg.blockDim = dim3(256, 1, 1);
        cfg.dynamicSmemBytes = PSMEM;
        cudaLaunchAttribute attr;
        attr.id = cudaLaunchAttributeCooperative;
        attr.val.cooperative = 1;
        cfg.attrs = &attr;
        cfg.numAttrs = 1;
        cudaLaunchKernelEx(&cfg, gru_word_persistent,
                           SHiA, SHiB, (const h16*)WhhH,
                           (const float*)w_bhh, (const h16*)GXw);
    }
    h16* sent_hi = SHiB;   // 31 iterations -> B buffers

    // ---- sentence level ----
    gemm_wmma2<float><<<dim3(GDIM / 128, (NS * TSSTEPS) / 128), 256, SMEM_GEMM>>>(
        sent_hi, WsH, s_bih, GXs, HDIM, GDIM);

    gru_init_plain<<<(NS * HDIM + 255) / 256, 256>>>(GXs, s_bhh, HsA, NS, TSSTEPS);
    gru_tail_fused<4><<<NS / 4, 256>>>(HsA, WshhH, s_bhh, GXs, TSSTEPS, HsB);
    const float* p_batch = HsB;

    // r_stars -> out[16 .. 272)
    mlp_kernel<<<NS, 128>>>(p_batch, rfc_W1, rfc_b1, rfc_W2, rfc_b2, out + NR);

    // ---- review level ----
    {
        dim3 grid(GDIM / BN, (NR * TRSTEPS + BM - 1) / BM);
        sgemm_f32x2<<<grid, 256>>>(p_batch, r_Wih, r_bih, GXr, NR * TRSTEPS, HDIM, GDIM);
    }
    gru_init_plain<<<(NR * HDIM + 255) / 256, 256>>>(GXr, r_bhh, HrA, NR, TRSTEPS);
    gru_tail_fused<1><<<NR, 256>>>(HrA, WrhhH, r_bhh, GXr, TRSTEPS, HrB);

    // b_stars -> out[0 .. 16)
    mlp_kernel<<<NR, 128>>>(HrB, pfc_W1, pfc_b1, pfc_W2, pfc_b2, out);
}